// round 9
// baseline (speedup 1.0000x reference)
#include <cuda_runtime.h>
#include <cuda_fp16.h>
#include <math.h>
#include <stdint.h>

// ================= problem constants =================
namespace {
constexpr int B_ = 8, L_ = 4800, D_ = 256, H_ = 8, DIM_ = 32;
constexpr int M_ = B_ * L_;            // 38400 rows
constexpr float EPS_ATTN = 1e-6f, EPS_LN = 1e-5f;
constexpr int KV_ELEMS = B_ * H_ * DIM_ * DIM_;   // 65536
constexpr int KS_ELEMS = B_ * H_ * DIM_;          // 2048

constexpr int BM = 64;                 // CTA rows; 8 warps; warp tile 64x32
constexpr int SMEM_K8  = (8  * 1024 + 768) * 4;   // 35840 B
constexpr int SMEM_K16 = (16 * 1024 + 768) * 4;   // 68608 B
}

// ================= scratch (static device globals) =================
__device__ float g_x0[M_ * D_];
__device__ float g_x1[M_ * D_];
__device__ float g_Q  [M_ * D_];
__device__ float g_KVc[M_ * 2 * D_];          // combined K (cols 0-255) | V (cols 256-511)
__device__ float g_A  [M_ * D_];
__device__ float g_Msg[M_ * D_];
__device__ float g_Hid[M_ * 2 * D_];
__device__ float g_KV[KV_ELEMS];
__device__ float g_Ks[KS_ELEMS];
__device__ __half g_WTh [4 * D_ * D_];        // frag-major fp16: Wq,Wk,Wv,Wm
__device__ __half g_w1Th[8 * 2 * D_ * D_];
__device__ __half g_w2Th[8 * D_ * 2 * D_];

// ================= mma helper =================
__device__ __forceinline__ void mma_f16(float d[4], const uint32_t a[4],
                                        uint32_t b0, uint32_t b1) {
    asm volatile(
        "mma.sync.aligned.m16n8k16.row.col.f32.f16.f16.f32 "
        "{%0,%1,%2,%3}, {%4,%5,%6,%7}, {%8,%9}, {%0,%1,%2,%3};\n"
        : "+f"(d[0]), "+f"(d[1]), "+f"(d[2]), "+f"(d[3])
        : "r"(a[0]), "r"(a[1]), "r"(a[2]), "r"(a[3]), "r"(b0), "r"(b1));
}

// ================= weight pack: [K,N] f32 -> frag-major fp16 =================
__device__ __forceinline__ void pack_one(const float* __restrict__ in,
                                         __half* __restrict__ out,
                                         int t, int K, int N)
{
    int k = t / N, n = t % N;
    int nblk = n >> 8, nloc = n & 255;
    int wn = nloc >> 5, j = (nloc >> 3) & 3, gid = nloc & 7;
    int p = j >> 1, jh = j & 1;
    int kch = k >> 5, kin = k & 31, kstep = kin >> 4, c16 = kin & 15;
    int qid = (c16 >> 1) & 3, kh = (c16 >> 3) & 1, h = c16 & 1;
    int lane = gid * 4 + qid;
    int NKCH = K >> 5;
    size_t idx = ((((((size_t)nblk * NKCH + kch) * 2 + kstep) * 8 + wn) * 2 + p) * 32
                  + lane) * 8 + jh * 4 + kh * 2 + h;
    out[idx] = __float2half_rn(in[t]);
}

__global__ void pack_all(const float* __restrict__ Wq, const float* __restrict__ Wk,
                         const float* __restrict__ Wv, const float* __restrict__ Wm,
                         const float* __restrict__ w1, const float* __restrict__ w2,
                         __half* __restrict__ WTh, __half* __restrict__ w1Th,
                         __half* __restrict__ w2Th)
{
    long idx = (long)blockIdx.x * 256 + threadIdx.x;
    const long S0 = 4L * 65536, S1 = 8L * 131072;
    if (idx < S0) {
        int which = (int)(idx >> 16), t = (int)(idx & 65535);
        const float* src = which == 0 ? Wq : which == 1 ? Wk : which == 2 ? Wv : Wm;
        pack_one(src, WTh + (long)which * 65536, t, 256, 256);
    } else if (idx < S0 + S1) {
        long i2 = idx - S0;
        int layer = (int)(i2 >> 17), t = (int)(i2 & 131071);
        pack_one(w1 + (long)layer * 131072, w1Th + (long)layer * 131072, t, 256, 512);
    } else {
        long i2 = idx - S0 - S1;
        int layer = (int)(i2 >> 17), t = (int)(i2 & 131071);
        pack_one(w2 + (long)layer * 131072, w2Th + (long)layer * 131072, t, 512, 256);
    }
}

// ================= fp16 tensor-core GEMM, dual-prefetch barrier-free mainloop =====
enum { EPI_QK = 1, EPI_V = 2, EPI_RELU = 3, EPI_BIAS_LN = 5, EPI_LN_RES = 6,
       EPI_KV = 7 };   // combined K|V: block 0 = elu+1 w/ bias, block 1 = plain w/ bias2

template<int EPI, int KCH>
__global__ __launch_bounds__(256, 2)
void gemm_f16(const float* __restrict__ A, const __half* __restrict__ Bp,
              const float* __restrict__ bias, const float* __restrict__ mask,
              const float* __restrict__ lng, const float* __restrict__ lnb,
              float* __restrict__ C, int N)
{
    constexpr int K = KCH * 32;
    extern __shared__ float sm[];
    uint32_t* As = (uint32_t*)sm;                  // KCH slots x 1024 u32 (A frags)
    float* sbias = sm + KCH * 1024;
    float* sg    = sbias + 256;
    float* sb    = sg + 256;
    float* red1 = sm;                 // epilogue scratch (reuses A region)
    float* red2 = sm + 512;
    float* smu  = sm + 1024;
    float* srs  = sm + 1088;

    const int tid = threadIdx.x;
    const int wn = tid >> 5, lane = tid & 31;
    const int gid = lane >> 2, qid = lane & 3;
    const int rowBase = blockIdx.y * BM;
    const int colBase = blockIdx.x * 256;

    if (EPI == EPI_QK || EPI == EPI_V || EPI == EPI_BIAS_LN)
        sbias[tid] = bias[colBase + tid];
    if (EPI == EPI_KV)
        sbias[tid] = (blockIdx.x == 0 ? bias : lng)[tid];   // bk | bv
    if (EPI == EPI_BIAS_LN || EPI == EPI_LN_RES) { sg[tid] = lng[tid]; sb[tid] = lnb[tid]; }

    // ---- stage FULL A tile (64 x K) as fp16 fragments, once ----
    {
        const int arow = tid >> 2, aq = tid & 3;
        const float* Aptr = A + (size_t)(rowBase + arow) * K + aq * 8;
        const int a_base = ((aq >> 1) * 4 + (arow >> 4)) * 128 + (arow & 7) * 16
                         + (aq & 1) * 2 + ((arow >> 3) & 1);
        #pragma unroll
        for (int c = 0; c < KCH; c++) {
            float4 v0 = *(const float4*)(Aptr + (size_t)c * 32);
            float4 v1 = *(const float4*)(Aptr + (size_t)c * 32 + 4);
            uint32_t* d = As + c * 1024 + a_base;
            const float* f0 = (const float*)&v0;
            const float* f1 = (const float*)&v1;
            #pragma unroll
            for (int q = 0; q < 2; q++) {
                __half2 h = __float22half2_rn(make_float2(f0[2*q], f0[2*q+1]));
                d[q * 4] = *(const uint32_t*)&h;
            }
            #pragma unroll
            for (int q = 0; q < 2; q++) {
                __half2 h = __float22half2_rn(make_float2(f1[2*q], f1[2*q+1]));
                d[(q + 2) * 4] = *(const uint32_t*)&h;
            }
        }
    }
    __syncthreads();

    // ---- mainloop: barrier-free, A+B double-buffered one kk ahead ----
    float acc[4][4][4];
    #pragma unroll
    for (int mi = 0; mi < 4; mi++)
        #pragma unroll
        for (int j = 0; j < 4; j++)
            #pragma unroll
            for (int q = 0; q < 4; q++) acc[mi][j][q] = 0.f;

    // linear streams: A frags advance 512 u32 / kk; B frags advance 4096 halves / kk
    const uint32_t* Asl = As + lane * 4;
    const __half* Bch = Bp + (size_t)blockIdx.x * KCH * 8192
                        + (size_t)wn * 512 + lane * 8;

    uint4 af[2][4], bf[2][2];
    #pragma unroll
    for (int mi = 0; mi < 4; mi++)
        af[0][mi] = *(const uint4*)(Asl + mi * 128);
    bf[0][0] = *(const uint4*)(Bch);
    bf[0][1] = *(const uint4*)(Bch + 256);

    #pragma unroll
    for (int kk = 0; kk < 2 * KCH; kk++) {
        const int cur = kk & 1, nxt = cur ^ 1;
        if (kk + 1 < 2 * KCH) {
            const uint32_t* asn = Asl + (kk + 1) * 512;
            #pragma unroll
            for (int mi = 0; mi < 4; mi++)
                af[nxt][mi] = *(const uint4*)(asn + mi * 128);
            const __half* s = Bch + (size_t)(kk + 1) * 4096;
            bf[nxt][0] = *(const uint4*)(s);
            bf[nxt][1] = *(const uint4*)(s + 256);
        }
        #pragma unroll
        for (int mi = 0; mi < 4; mi++) {
            const uint32_t a4[4] = {af[cur][mi].x, af[cur][mi].y,
                                    af[cur][mi].z, af[cur][mi].w};
            mma_f16(acc[mi][0], a4, bf[cur][0].x, bf[cur][0].y);
            mma_f16(acc[mi][1], a4, bf[cur][0].z, bf[cur][0].w);
            mma_f16(acc[mi][2], a4, bf[cur][1].x, bf[cur][1].y);
            mma_f16(acc[mi][3], a4, bf[cur][1].z, bf[cur][1].w);
        }
    }
    __syncthreads();   // A region free for epilogue scratch

    // ================= epilogue =================
    // element (mi,j,q): row = rowBase + mi*16 + (q>>1)*8 + gid
    //                   col = colBase + wn*32 + j*8 + qid*2 + (q&1)
    if (EPI == EPI_QK || EPI == EPI_V || EPI == EPI_BIAS_LN || EPI == EPI_KV) {
        #pragma unroll
        for (int mi = 0; mi < 4; mi++)
            #pragma unroll
            for (int j = 0; j < 4; j++) {
                const int c = wn * 32 + j * 8 + qid * 2;
                acc[mi][j][0] += sbias[c];   acc[mi][j][1] += sbias[c + 1];
                acc[mi][j][2] += sbias[c];   acc[mi][j][3] += sbias[c + 1];
            }
    }
    if (EPI == EPI_QK || EPI == EPI_V || EPI == EPI_KV) {
        const bool do_elu = (EPI == EPI_QK) || (EPI == EPI_KV && blockIdx.x == 0);
        float mk[4][2];
        #pragma unroll
        for (int mi = 0; mi < 4; mi++)
            #pragma unroll
            for (int r = 0; r < 2; r++)
                mk[mi][r] = mask[rowBase + mi * 16 + r * 8 + gid];
        #pragma unroll
        for (int mi = 0; mi < 4; mi++)
            #pragma unroll
            for (int j = 0; j < 4; j++)
                #pragma unroll
                for (int q = 0; q < 4; q++) {
                    float t = acc[mi][j][q];
                    if (do_elu) t = (t > 0.f) ? (t + 1.f) : expf(t);
                    acc[mi][j][q] = t * mk[mi][q >> 1];
                }
    }
    if (EPI == EPI_RELU) {
        #pragma unroll
        for (int mi = 0; mi < 4; mi++)
            #pragma unroll
            for (int j = 0; j < 4; j++)
                #pragma unroll
                for (int q = 0; q < 4; q++)
                    acc[mi][j][q] = acc[mi][j][q] > 0.f ? acc[mi][j][q] : 0.f;
    }

    if (EPI == EPI_BIAS_LN || EPI == EPI_LN_RES) {
        float s1[4][2], s2[4][2];
        #pragma unroll
        for (int mi = 0; mi < 4; mi++)
            #pragma unroll
            for (int r = 0; r < 2; r++) { s1[mi][r] = 0.f; s2[mi][r] = 0.f; }
        #pragma unroll
        for (int mi = 0; mi < 4; mi++)
            #pragma unroll
            for (int j = 0; j < 4; j++)
                #pragma unroll
                for (int q = 0; q < 4; q++) {
                    float v = acc[mi][j][q];
                    s1[mi][q >> 1] += v;
                    s2[mi][q >> 1] = fmaf(v, v, s2[mi][q >> 1]);
                }
        #pragma unroll
        for (int o = 1; o <= 2; o <<= 1)
            #pragma unroll
            for (int mi = 0; mi < 4; mi++)
                #pragma unroll
                for (int r = 0; r < 2; r++) {
                    s1[mi][r] += __shfl_xor_sync(0xffffffffu, s1[mi][r], o);
                    s2[mi][r] += __shfl_xor_sync(0xffffffffu, s2[mi][r], o);
                }
        if (qid == 0) {
            #pragma unroll
            for (int mi = 0; mi < 4; mi++)
                #pragma unroll
                for (int r = 0; r < 2; r++) {
                    int rl = mi * 16 + r * 8 + gid;
                    red1[rl * 8 + wn] = s1[mi][r];
                    red2[rl * 8 + wn] = s2[mi][r];
                }
        }
        __syncthreads();
        if (tid < 64) {
            float a = 0.f, b2 = 0.f;
            #pragma unroll
            for (int w = 0; w < 8; w++) { a += red1[tid * 8 + w]; b2 += red2[tid * 8 + w]; }
            float mu = a * (1.f / 256.f);
            float var = b2 * (1.f / 256.f) - mu * mu;
            smu[tid] = mu;
            srs[tid] = rsqrtf(var + EPS_LN);
        }
        __syncthreads();
        #pragma unroll
        for (int mi = 0; mi < 4; mi++)
            #pragma unroll
            for (int j = 0; j < 4; j++)
                #pragma unroll
                for (int q = 0; q < 4; q++) {
                    int rl = mi * 16 + (q >> 1) * 8 + gid;
                    int c  = wn * 32 + j * 8 + qid * 2 + (q & 1);
                    acc[mi][j][q] = (acc[mi][j][q] - smu[rl]) * srs[rl] * sg[c] + sb[c];
                }
    }

    // store
    #pragma unroll
    for (int mi = 0; mi < 4; mi++) {
        #pragma unroll
        for (int j = 0; j < 4; j++) {
            const int c  = colBase + wn * 32 + j * 8 + qid * 2;
            const int r0 = rowBase + mi * 16 + gid;
            const int r1 = r0 + 8;
            float2 v0 = make_float2(acc[mi][j][0], acc[mi][j][1]);
            float2 v1 = make_float2(acc[mi][j][2], acc[mi][j][3]);
            if (EPI == EPI_LN_RES) {
                float2 x0 = *(const float2*)&C[(size_t)r0 * N + c];
                float2 x1 = *(const float2*)&C[(size_t)r1 * N + c];
                v0.x += x0.x; v0.y += x0.y;
                v1.x += x1.x; v1.y += x1.y;
            }
            *(float2*)&C[(size_t)r0 * N + c] = v0;
            *(float2*)&C[(size_t)r1 * N + c] = v1;
        }
    }
}

// ================= zero KV / Ksum =================
__global__ void zero_kv(float* __restrict__ kv, float* __restrict__ ks)
{
    int i = blockIdx.x * 256 + threadIdx.x;
    if (i < KV_ELEMS) kv[i] = 0.f;
    if (i < KS_ELEMS) ks[i] = 0.f;
}

// ================= KV reduction (reads combined K|V buffer, stride 512) =========
__global__ __launch_bounds__(256)
void kv_kernel(const float* __restrict__ KVc,
               float* __restrict__ KV, float* __restrict__ Ks, int rowsPerSplit)
{
    const int bh = blockIdx.x;
    const int b = bh >> 3, h = bh & 7;
    const int l0 = blockIdx.y * rowsPerSplit;
    const int tid = threadIdx.x;
    const int lr = tid >> 5;
    const int ld = tid & 31;

    __shared__ float Kt[8][32];
    __shared__ float Vt[8][32];

    float a0 = 0.f, a1 = 0.f, a2 = 0.f, a3 = 0.f, ks = 0.f;

    for (int c = 0; c < rowsPerSplit; c += 8) {
        int l = l0 + c + lr;
        size_t base = ((size_t)b * L_ + l) * (2 * D_) + h * DIM_ + ld;
        Kt[lr][ld] = KVc[base];
        Vt[lr][ld] = KVc[base + D_];
        __syncthreads();
        #pragma unroll
        for (int r = 0; r < 8; r++) {
            float kv = Kt[r][ld];
            a0 = fmaf(kv, Vt[r][lr +  0], a0);
            a1 = fmaf(kv, Vt[r][lr +  8], a1);
            a2 = fmaf(kv, Vt[r][lr + 16], a2);
            a3 = fmaf(kv, Vt[r][lr + 24], a3);
        }
        if (tid < 32) {
            #pragma unroll
            for (int r = 0; r < 8; r++) ks += Kt[r][tid];
        }
        __syncthreads();
    }

    float* kvb = KV + (size_t)bh * DIM_ * DIM_;
    atomicAdd(&kvb[(lr +  0) * DIM_ + ld], a0);
    atomicAdd(&kvb[(lr +  8) * DIM_ + ld], a1);
    atomicAdd(&kvb[(lr + 16) * DIM_ + ld], a2);
    atomicAdd(&kvb[(lr + 24) * DIM_ + ld], a3);
    if (tid < 32) atomicAdd(&Ks[bh * DIM_ + tid], ks);
}

// ================= attention apply =================
__global__ __launch_bounds__(256)
void attn_apply(const float* __restrict__ Q, const float* __restrict__ KV,
                const float* __restrict__ Ks, float* __restrict__ Out)
{
    __shared__ float sKV[H_ * DIM_ * DIM_];
    __shared__ float sKs[H_ * DIM_];
    const int b = blockIdx.y;
    const int tid = threadIdx.x;

    for (int i = tid; i < H_ * DIM_ * DIM_; i += 256)
        sKV[i] = KV[(size_t)b * H_ * DIM_ * DIM_ + i];
    if (tid < H_ * DIM_) sKs[tid] = Ks[b * H_ * DIM_ + tid];
    __syncthreads();

    const int token = blockIdx.x * 256 + tid;
    if (token >= L_) return;
    const size_t row = (size_t)b * L_ + token;
    const float* q = Q + row * D_;
    float* o = Out + row * D_;

    for (int h = 0; h < H_; h++) {
        float qr[DIM_];
        #pragma unroll
        for (int d = 0; d < DIM_; d++) qr[d] = q[h * DIM_ + d];
        float s = 0.f;
        #pragma unroll
        for (int d = 0; d < DIM_; d++) s = fmaf(qr[d], sKs[h * DIM_ + d], s);
        float z = 1.f / (s + EPS_ATTN);
        const float* kvh = &sKV[h * DIM_ * DIM_];
        #pragma unroll 4
        for (int m = 0; m < DIM_; m++) {
            float acc = 0.f;
            #pragma unroll
            for (int d = 0; d < DIM_; d++) acc = fmaf(kvh[m * DIM_ + d], qr[d], acc);
            o[h * DIM_ + m] = acc * z;
        }
    }
}

// ================= host orchestration =================
namespace {

struct Ptrs {
    float *x0, *x1, *Q, *KVc, *A, *Msg, *Hid, *KV, *Ks;
    __half *WTh, *w1Th, *w2Th;
};

void run_layer(float* x, const float* src, const float* xm, const float* sm,
               const __half* WqP, const float* bq, const __half* WkvP,
               const float* bk, const float* bv,
               const __half* WmP, const float* bm,
               const __half* w1P, const __half* w2P, const float* g1, const float* b1,
               const float* g2, const float* b2, const Ptrs& p)
{
    dim3 g1d(1, M_ / BM);   // (1, 600)
    dim3 g2d(2, M_ / BM);   // (2, 600)

    zero_kv<<<(KV_ELEMS + 255) / 256, 256>>>(p.KV, p.Ks);
    gemm_f16<EPI_QK, 8><<<g1d, 256, SMEM_K8>>>(x,   WqP,  bq, xm, nullptr, nullptr, p.Q,   256);
    gemm_f16<EPI_KV, 8><<<g2d, 256, SMEM_K8>>>(src, WkvP, bk, sm, bv,      nullptr, p.KVc, 512);
    kv_kernel<<<dim3(B_ * H_, 20), 256>>>(p.KVc, p.KV, p.Ks, L_ / 20);
    attn_apply<<<dim3((L_ + 255) / 256, B_), 256>>>(p.Q, p.KV, p.Ks, p.A);

    gemm_f16<EPI_BIAS_LN, 8><<<g1d, 256, SMEM_K8>>>(p.A,   WmP, bm, nullptr, g1, b1, p.Msg, 256);
    gemm_f16<EPI_RELU  , 8><<<g2d, 256, SMEM_K8>>>(p.Msg, w1P, nullptr, nullptr, nullptr, nullptr, p.Hid, 512);
    gemm_f16<EPI_LN_RES, 16><<<g1d, 256, SMEM_K16>>>(p.Hid, w2P, nullptr, nullptr, g2, b2, x, 256);
}

} // namespace

extern "C" void kernel_launch(void* const* d_in, const int* in_sizes, int n_in,
                              void* d_out, int out_size)
{
    const float* desc0 = (const float*)d_in[0];
    const float* desc1 = (const float*)d_in[1];
    const float* mask0 = (const float*)d_in[2];
    const float* mask1 = (const float*)d_in[3];
    const float* Wq = (const float*)d_in[4];
    const float* bq = (const float*)d_in[5];
    const float* Wk = (const float*)d_in[6];
    const float* bk = (const float*)d_in[7];
    const float* Wv = (const float*)d_in[8];
    const float* bv = (const float*)d_in[9];
    const float* Wm = (const float*)d_in[10];
    const float* bm = (const float*)d_in[11];
    const float* w1 = (const float*)d_in[12];
    const float* w2 = (const float*)d_in[13];
    const float* g1 = (const float*)d_in[14];
    const float* b1 = (const float*)d_in[15];
    const float* g2 = (const float*)d_in[16];
    const float* b2 = (const float*)d_in[17];

    Ptrs p;
    cudaGetSymbolAddress((void**)&p.x0,  g_x0);
    cudaGetSymbolAddress((void**)&p.x1,  g_x1);
    cudaGetSymbolAddress((void**)&p.Q,   g_Q);
    cudaGetSymbolAddress((void**)&p.KVc, g_KVc);
    cudaGetSymbolAddress((void**)&p.A,   g_A);
    cudaGetSymbolAddress((void**)&p.Msg, g_Msg);
    cudaGetSymbolAddress((void**)&p.Hid, g_Hid);
    cudaGetSymbolAddress((void**)&p.KV,  g_KV);
    cudaGetSymbolAddress((void**)&p.Ks,  g_Ks);
    cudaGetSymbolAddress((void**)&p.WTh,  g_WTh);
    cudaGetSymbolAddress((void**)&p.w1Th, g_w1Th);
    cudaGetSymbolAddress((void**)&p.w2Th, g_w2Th);

    cudaFuncSetAttribute((const void*)gemm_f16<EPI_QK, 8>,      cudaFuncAttributeMaxDynamicSharedMemorySize, SMEM_K8);
    cudaFuncSetAttribute((const void*)gemm_f16<EPI_KV, 8>,      cudaFuncAttributeMaxDynamicSharedMemorySize, SMEM_K8);
    cudaFuncSetAttribute((const void*)gemm_f16<EPI_RELU, 8>,    cudaFuncAttributeMaxDynamicSharedMemorySize, SMEM_K8);
    cudaFuncSetAttribute((const void*)gemm_f16<EPI_BIAS_LN, 8>, cudaFuncAttributeMaxDynamicSharedMemorySize, SMEM_K8);
    cudaFuncSetAttribute((const void*)gemm_f16<EPI_LN_RES, 16>, cudaFuncAttributeMaxDynamicSharedMemorySize, SMEM_K16);

    // ---- one-time weight packing ----
    pack_all<<<(4 * 65536 + 2 * 8 * 131072) / 256, 256>>>(Wq, Wk, Wv, Wm, w1, w2,
                                                          p.WTh, p.w1Th, p.w2Th);

    const size_t tensorBytes = (size_t)M_ * D_ * sizeof(float);
    cudaMemcpyAsync(p.x0, desc0, tensorBytes, cudaMemcpyDeviceToDevice);
    cudaMemcpyAsync(p.x1, desc1, tensorBytes, cudaMemcpyDeviceToDevice);

    const int w1sz = D_ * 2 * D_;
    const int w2sz = 2 * D_ * D_;

    for (int li = 0; li < 8; li++) {
        const __half* lw1 = p.w1Th + (size_t)li * w1sz;
        const __half* lw2 = p.w2Th + (size_t)li * w2sz;
        const float* lg1 = g1 + li * D_;
        const float* lb1 = b1 + li * D_;
        const float* lg2 = g2 + li * D_;
        const float* lb2 = b2 + li * D_;
        const __half* WqP  = p.WTh + 0 * D_ * D_;
        const __half* WkvP = p.WTh + 1 * D_ * D_;   // Wk | Wv contiguous packed blocks
        const __half* WmP  = p.WTh + 3 * D_ * D_;
        if ((li & 1) == 0) {
            run_layer(p.x0, p.x0, mask0, mask0, WqP, bq, WkvP, bk, bv, WmP, bm,
                      lw1, lw2, lg1, lb1, lg2, lb2, p);
            run_layer(p.x1, p.x1, mask1, mask1, WqP, bq, WkvP, bk, bv, WmP, bm,
                      lw1, lw2, lg1, lb1, lg2, lb2, p);
        } else {
            run_layer(p.x0, p.x1, mask0, mask1, WqP, bq, WkvP, bk, bv, WmP, bm,
                      lw1, lw2, lg1, lb1, lg2, lb2, p);
            run_layer(p.x1, p.x0, mask1, mask0, WqP, bq, WkvP, bk, bv, WmP, bm,
                      lw1, lw2, lg1, lb1, lg2, lb2, p);
        }
    }

    cudaMemcpyAsync((float*)d_out,                   p.x0, tensorBytes, cudaMemcpyDeviceToDevice);
    cudaMemcpyAsync((float*)d_out + (size_t)M_ * D_, p.x1, tensorBytes, cudaMemcpyDeviceToDevice);
}

// round 10
// speedup vs baseline: 1.1811x; 1.1811x over previous
#include <cuda_runtime.h>
#include <cuda_fp16.h>
#include <math.h>
#include <stdint.h>

// ================= problem constants =================
namespace {
constexpr int B_ = 8, L_ = 4800, D_ = 256, H_ = 8, DIM_ = 32;
constexpr int M_ = B_ * L_;            // 38400 rows
constexpr float EPS_ATTN = 1e-6f, EPS_LN = 1e-5f;
constexpr int KV_ELEMS = B_ * H_ * DIM_ * DIM_;   // 65536
constexpr int KS_ELEMS = B_ * H_ * DIM_;          // 2048

constexpr int BM = 64;                 // CTA rows; 8 warps; warp tile 64x32
constexpr int SMEM_K8  = (8  * 1024 + 768) * 4;   // 35840 B
constexpr int SMEM_K16 = (16 * 1024 + 768) * 4;   // 68608 B
}

// ================= scratch (static device globals) =================
__device__ float  g_x0[M_ * D_];
__device__ float  g_x1[M_ * D_];
__device__ __half g_Q  [M_ * D_];             // fp16 intermediates
__device__ __half g_KVc[M_ * 2 * D_];         // K (cols 0-255) | V (cols 256-511)
__device__ __half g_A  [M_ * D_];
__device__ __half g_Msg[M_ * D_];
__device__ __half g_Hid[M_ * 2 * D_];
__device__ float  g_KV[KV_ELEMS];
__device__ float  g_Ks[KS_ELEMS];
__device__ __half g_WTh [4 * D_ * D_];        // frag-major fp16: Wq,Wk,Wv,Wm
__device__ __half g_w1Th[8 * 2 * D_ * D_];
__device__ __half g_w2Th[8 * D_ * 2 * D_];

// ================= mma helper =================
__device__ __forceinline__ void mma_f16(float d[4], const uint32_t a[4],
                                        uint32_t b0, uint32_t b1) {
    asm volatile(
        "mma.sync.aligned.m16n8k16.row.col.f32.f16.f16.f32 "
        "{%0,%1,%2,%3}, {%4,%5,%6,%7}, {%8,%9}, {%0,%1,%2,%3};\n"
        : "+f"(d[0]), "+f"(d[1]), "+f"(d[2]), "+f"(d[3])
        : "r"(a[0]), "r"(a[1]), "r"(a[2]), "r"(a[3]), "r"(b0), "r"(b1));
}

// ================= weight pack: [K,N] f32 -> frag-major fp16 =================
__device__ __forceinline__ void pack_one(const float* __restrict__ in,
                                         __half* __restrict__ out,
                                         int t, int K, int N)
{
    int k = t / N, n = t % N;
    int nblk = n >> 8, nloc = n & 255;
    int wn = nloc >> 5, j = (nloc >> 3) & 3, gid = nloc & 7;
    int p = j >> 1, jh = j & 1;
    int kch = k >> 5, kin = k & 31, kstep = kin >> 4, c16 = kin & 15;
    int qid = (c16 >> 1) & 3, kh = (c16 >> 3) & 1, h = c16 & 1;
    int lane = gid * 4 + qid;
    int NKCH = K >> 5;
    size_t idx = ((((((size_t)nblk * NKCH + kch) * 2 + kstep) * 8 + wn) * 2 + p) * 32
                  + lane) * 8 + jh * 4 + kh * 2 + h;
    out[idx] = __float2half_rn(in[t]);
}

__global__ void pack_all(const float* __restrict__ Wq, const float* __restrict__ Wk,
                         const float* __restrict__ Wv, const float* __restrict__ Wm,
                         const float* __restrict__ w1, const float* __restrict__ w2,
                         __half* __restrict__ WTh, __half* __restrict__ w1Th,
                         __half* __restrict__ w2Th)
{
    long idx = (long)blockIdx.x * 256 + threadIdx.x;
    const long S0 = 4L * 65536, S1 = 8L * 131072;
    if (idx < S0) {
        int which = (int)(idx >> 16), t = (int)(idx & 65535);
        const float* src = which == 0 ? Wq : which == 1 ? Wk : which == 2 ? Wv : Wm;
        pack_one(src, WTh + (long)which * 65536, t, 256, 256);
    } else if (idx < S0 + S1) {
        long i2 = idx - S0;
        int layer = (int)(i2 >> 17), t = (int)(i2 & 131071);
        pack_one(w1 + (long)layer * 131072, w1Th + (long)layer * 131072, t, 256, 512);
    } else {
        long i2 = idx - S0 - S1;
        int layer = (int)(i2 >> 17), t = (int)(i2 & 131071);
        pack_one(w2 + (long)layer * 131072, w2Th + (long)layer * 131072, t, 512, 256);
    }
}

// ================= fp16 tensor-core GEMM =================
// AH: A input is fp16 row-major (else fp32). OH: C output is fp16 (else fp32).
enum { EPI_QK = 1, EPI_RELU = 3, EPI_BIAS_LN = 5, EPI_LN_RES = 6, EPI_KV = 7 };

template<int EPI, int KCH, bool AH, bool OH>
__global__ __launch_bounds__(256, 2)
void gemm_f16(const void* __restrict__ Ain, const __half* __restrict__ Bp,
              const float* __restrict__ bias, const float* __restrict__ mask,
              const float* __restrict__ lng, const float* __restrict__ lnb,
              void* __restrict__ Cout, int N)
{
    constexpr int K = KCH * 32;
    extern __shared__ float sm[];
    uint32_t* As = (uint32_t*)sm;                  // KCH slots x 1024 u32 (A frags)
    float* sbias = sm + KCH * 1024;
    float* sg    = sbias + 256;
    float* sb    = sg + 256;
    float* red1 = sm;                 // epilogue scratch (reuses A region)
    float* red2 = sm + 512;
    float* smu  = sm + 1024;
    float* srs  = sm + 1088;

    const int tid = threadIdx.x;
    const int wn = tid >> 5, lane = tid & 31;
    const int gid = lane >> 2, qid = lane & 3;
    const int rowBase = blockIdx.y * BM;
    const int colBase = blockIdx.x * 256;

    if (EPI == EPI_QK || EPI == EPI_BIAS_LN)
        sbias[tid] = bias[colBase + tid];
    if (EPI == EPI_KV)
        sbias[tid] = (blockIdx.x == 0 ? bias : lng)[tid];   // bk | bv
    if (EPI == EPI_BIAS_LN || EPI == EPI_LN_RES) { sg[tid] = lng[tid]; sb[tid] = lnb[tid]; }

    // ---- stage FULL A tile (64 x K) as fp16 fragments, once ----
    {
        const int arow = tid >> 2, aq = tid & 3;
        const int a_base = ((aq >> 1) * 4 + (arow >> 4)) * 128 + (arow & 7) * 16
                         + (aq & 1) * 2 + ((arow >> 3) & 1);
        if (AH) {
            const __half* Aptr = (const __half*)Ain + (size_t)(rowBase + arow) * K + aq * 8;
            #pragma unroll
            for (int c = 0; c < KCH; c++) {
                uint4 v = *(const uint4*)(Aptr + (size_t)c * 32);
                uint32_t* d = As + c * 1024 + a_base;
                d[0] = v.x; d[4] = v.y; d[8] = v.z; d[12] = v.w;
            }
        } else {
            const float* Aptr = (const float*)Ain + (size_t)(rowBase + arow) * K + aq * 8;
            #pragma unroll
            for (int c = 0; c < KCH; c++) {
                float4 v0 = *(const float4*)(Aptr + (size_t)c * 32);
                float4 v1 = *(const float4*)(Aptr + (size_t)c * 32 + 4);
                uint32_t* d = As + c * 1024 + a_base;
                const float* f0 = (const float*)&v0;
                const float* f1 = (const float*)&v1;
                #pragma unroll
                for (int q = 0; q < 2; q++) {
                    __half2 h = __float22half2_rn(make_float2(f0[2*q], f0[2*q+1]));
                    d[q * 4] = *(const uint32_t*)&h;
                }
                #pragma unroll
                for (int q = 0; q < 2; q++) {
                    __half2 h = __float22half2_rn(make_float2(f1[2*q], f1[2*q+1]));
                    d[(q + 2) * 4] = *(const uint32_t*)&h;
                }
            }
        }
    }
    __syncthreads();

    // ---- mainloop: barrier-free, A+B double-buffered one kk ahead ----
    float acc[4][4][4];
    #pragma unroll
    for (int mi = 0; mi < 4; mi++)
        #pragma unroll
        for (int j = 0; j < 4; j++)
            #pragma unroll
            for (int q = 0; q < 4; q++) acc[mi][j][q] = 0.f;

    const uint32_t* Asl = As + lane * 4;
    const __half* Bch = Bp + (size_t)blockIdx.x * KCH * 8192
                        + (size_t)wn * 512 + lane * 8;

    uint4 af[2][4], bf[2][2];
    #pragma unroll
    for (int mi = 0; mi < 4; mi++)
        af[0][mi] = *(const uint4*)(Asl + mi * 128);
    bf[0][0] = *(const uint4*)(Bch);
    bf[0][1] = *(const uint4*)(Bch + 256);

    #pragma unroll
    for (int kk = 0; kk < 2 * KCH; kk++) {
        const int cur = kk & 1, nxt = cur ^ 1;
        if (kk + 1 < 2 * KCH) {
            const uint32_t* asn = Asl + (kk + 1) * 512;
            #pragma unroll
            for (int mi = 0; mi < 4; mi++)
                af[nxt][mi] = *(const uint4*)(asn + mi * 128);
            const __half* s = Bch + (size_t)(kk + 1) * 4096;
            bf[nxt][0] = *(const uint4*)(s);
            bf[nxt][1] = *(const uint4*)(s + 256);
        }
        #pragma unroll
        for (int mi = 0; mi < 4; mi++) {
            const uint32_t a4[4] = {af[cur][mi].x, af[cur][mi].y,
                                    af[cur][mi].z, af[cur][mi].w};
            mma_f16(acc[mi][0], a4, bf[cur][0].x, bf[cur][0].y);
            mma_f16(acc[mi][1], a4, bf[cur][0].z, bf[cur][0].w);
            mma_f16(acc[mi][2], a4, bf[cur][1].x, bf[cur][1].y);
            mma_f16(acc[mi][3], a4, bf[cur][1].z, bf[cur][1].w);
        }
    }
    __syncthreads();   // A region free for epilogue scratch

    // ================= epilogue =================
    // element (mi,j,q): row = rowBase + mi*16 + (q>>1)*8 + gid
    //                   col = colBase + wn*32 + j*8 + qid*2 + (q&1)
    if (EPI == EPI_QK || EPI == EPI_BIAS_LN || EPI == EPI_KV) {
        #pragma unroll
        for (int mi = 0; mi < 4; mi++)
            #pragma unroll
            for (int j = 0; j < 4; j++) {
                const int c = wn * 32 + j * 8 + qid * 2;
                acc[mi][j][0] += sbias[c];   acc[mi][j][1] += sbias[c + 1];
                acc[mi][j][2] += sbias[c];   acc[mi][j][3] += sbias[c + 1];
            }
    }
    if (EPI == EPI_QK || EPI == EPI_KV) {
        const bool do_elu = (EPI == EPI_QK) || (EPI == EPI_KV && blockIdx.x == 0);
        float mk[4][2];
        #pragma unroll
        for (int mi = 0; mi < 4; mi++)
            #pragma unroll
            for (int r = 0; r < 2; r++)
                mk[mi][r] = mask[rowBase + mi * 16 + r * 8 + gid];
        #pragma unroll
        for (int mi = 0; mi < 4; mi++)
            #pragma unroll
            for (int j = 0; j < 4; j++)
                #pragma unroll
                for (int q = 0; q < 4; q++) {
                    float t = acc[mi][j][q];
                    if (do_elu) t = (t > 0.f) ? (t + 1.f) : expf(t);
                    acc[mi][j][q] = t * mk[mi][q >> 1];
                }
    }
    if (EPI == EPI_RELU) {
        #pragma unroll
        for (int mi = 0; mi < 4; mi++)
            #pragma unroll
            for (int j = 0; j < 4; j++)
                #pragma unroll
                for (int q = 0; q < 4; q++)
                    acc[mi][j][q] = acc[mi][j][q] > 0.f ? acc[mi][j][q] : 0.f;
    }

    if (EPI == EPI_BIAS_LN || EPI == EPI_LN_RES) {
        float s1[4][2], s2[4][2];
        #pragma unroll
        for (int mi = 0; mi < 4; mi++)
            #pragma unroll
            for (int r = 0; r < 2; r++) { s1[mi][r] = 0.f; s2[mi][r] = 0.f; }
        #pragma unroll
        for (int mi = 0; mi < 4; mi++)
            #pragma unroll
            for (int j = 0; j < 4; j++)
                #pragma unroll
                for (int q = 0; q < 4; q++) {
                    float v = acc[mi][j][q];
                    s1[mi][q >> 1] += v;
                    s2[mi][q >> 1] = fmaf(v, v, s2[mi][q >> 1]);
                }
        #pragma unroll
        for (int o = 1; o <= 2; o <<= 1)
            #pragma unroll
            for (int mi = 0; mi < 4; mi++)
                #pragma unroll
                for (int r = 0; r < 2; r++) {
                    s1[mi][r] += __shfl_xor_sync(0xffffffffu, s1[mi][r], o);
                    s2[mi][r] += __shfl_xor_sync(0xffffffffu, s2[mi][r], o);
                }
        if (qid == 0) {
            #pragma unroll
            for (int mi = 0; mi < 4; mi++)
                #pragma unroll
                for (int r = 0; r < 2; r++) {
                    int rl = mi * 16 + r * 8 + gid;
                    red1[rl * 8 + wn] = s1[mi][r];
                    red2[rl * 8 + wn] = s2[mi][r];
                }
        }
        __syncthreads();
        if (tid < 64) {
            float a = 0.f, b2 = 0.f;
            #pragma unroll
            for (int w = 0; w < 8; w++) { a += red1[tid * 8 + w]; b2 += red2[tid * 8 + w]; }
            float mu = a * (1.f / 256.f);
            float var = b2 * (1.f / 256.f) - mu * mu;
            smu[tid] = mu;
            srs[tid] = rsqrtf(var + EPS_LN);
        }
        __syncthreads();
        #pragma unroll
        for (int mi = 0; mi < 4; mi++)
            #pragma unroll
            for (int j = 0; j < 4; j++)
                #pragma unroll
                for (int q = 0; q < 4; q++) {
                    int rl = mi * 16 + (q >> 1) * 8 + gid;
                    int c  = wn * 32 + j * 8 + qid * 2 + (q & 1);
                    acc[mi][j][q] = (acc[mi][j][q] - smu[rl]) * srs[rl] * sg[c] + sb[c];
                }
    }

    // store
    #pragma unroll
    for (int mi = 0; mi < 4; mi++) {
        #pragma unroll
        for (int j = 0; j < 4; j++) {
            const int c  = colBase + wn * 32 + j * 8 + qid * 2;
            const int r0 = rowBase + mi * 16 + gid;
            const int r1 = r0 + 8;
            if (OH) {
                __half* Ch = (__half*)Cout;
                __half2 h0 = __float22half2_rn(make_float2(acc[mi][j][0], acc[mi][j][1]));
                __half2 h1 = __float22half2_rn(make_float2(acc[mi][j][2], acc[mi][j][3]));
                *(uint32_t*)&Ch[(size_t)r0 * N + c] = *(const uint32_t*)&h0;
                *(uint32_t*)&Ch[(size_t)r1 * N + c] = *(const uint32_t*)&h1;
            } else {
                float* Cf = (float*)Cout;
                float2 v0 = make_float2(acc[mi][j][0], acc[mi][j][1]);
                float2 v1 = make_float2(acc[mi][j][2], acc[mi][j][3]);
                if (EPI == EPI_LN_RES) {
                    float2 x0 = *(const float2*)&Cf[(size_t)r0 * N + c];
                    float2 x1 = *(const float2*)&Cf[(size_t)r1 * N + c];
                    v0.x += x0.x; v0.y += x0.y;
                    v1.x += x1.x; v1.y += x1.y;
                }
                *(float2*)&Cf[(size_t)r0 * N + c] = v0;
                *(float2*)&Cf[(size_t)r1 * N + c] = v1;
            }
        }
    }
}

// ================= zero KV / Ksum =================
__global__ void zero_kv(float* __restrict__ kv, float* __restrict__ ks)
{
    int i = blockIdx.x * 256 + threadIdx.x;
    if (i < KV_ELEMS) kv[i] = 0.f;
    if (i < KS_ELEMS) ks[i] = 0.f;
}

// ================= KV reduction (reads combined fp16 K|V buffer, stride 512) =====
__global__ __launch_bounds__(256)
void kv_kernel(const __half* __restrict__ KVc,
               float* __restrict__ KV, float* __restrict__ Ks, int rowsPerSplit)
{
    const int bh = blockIdx.x;
    const int b = bh >> 3, h = bh & 7;
    const int l0 = blockIdx.y * rowsPerSplit;
    const int tid = threadIdx.x;
    const int lr = tid >> 5;
    const int ld = tid & 31;

    __shared__ float Kt[8][32];
    __shared__ float Vt[8][32];

    float a0 = 0.f, a1 = 0.f, a2 = 0.f, a3 = 0.f, ks = 0.f;

    for (int c = 0; c < rowsPerSplit; c += 8) {
        int l = l0 + c + lr;
        size_t base = ((size_t)b * L_ + l) * (2 * D_) + h * DIM_ + ld;
        Kt[lr][ld] = __half2float(KVc[base]);
        Vt[lr][ld] = __half2float(KVc[base + D_]);
        __syncthreads();
        #pragma unroll
        for (int r = 0; r < 8; r++) {
            float kv = Kt[r][ld];
            a0 = fmaf(kv, Vt[r][lr +  0], a0);
            a1 = fmaf(kv, Vt[r][lr +  8], a1);
            a2 = fmaf(kv, Vt[r][lr + 16], a2);
            a3 = fmaf(kv, Vt[r][lr + 24], a3);
        }
        if (tid < 32) {
            #pragma unroll
            for (int r = 0; r < 8; r++) ks += Kt[r][tid];
        }
        __syncthreads();
    }

    float* kvb = KV + (size_t)bh * DIM_ * DIM_;
    atomicAdd(&kvb[(lr +  0) * DIM_ + ld], a0);
    atomicAdd(&kvb[(lr +  8) * DIM_ + ld], a1);
    atomicAdd(&kvb[(lr + 16) * DIM_ + ld], a2);
    atomicAdd(&kvb[(lr + 24) * DIM_ + ld], a3);
    if (tid < 32) atomicAdd(&Ks[bh * DIM_ + tid], ks);
}

// ================= attention apply (fp16 Q in, fp16 A out) =================
__global__ __launch_bounds__(256)
void attn_apply(const __half* __restrict__ Q, const float* __restrict__ KV,
                const float* __restrict__ Ks, __half* __restrict__ Out)
{
    __shared__ float sKV[H_ * DIM_ * DIM_];
    __shared__ float sKs[H_ * DIM_];
    const int b = blockIdx.y;
    const int tid = threadIdx.x;

    for (int i = tid; i < H_ * DIM_ * DIM_; i += 256)
        sKV[i] = KV[(size_t)b * H_ * DIM_ * DIM_ + i];
    if (tid < H_ * DIM_) sKs[tid] = Ks[b * H_ * DIM_ + tid];
    __syncthreads();

    const int token = blockIdx.x * 256 + tid;
    if (token >= L_) return;
    const size_t row = (size_t)b * L_ + token;
    const __half* q = Q + row * D_;
    __half* o = Out + row * D_;

    for (int h = 0; h < H_; h++) {
        float qr[DIM_];
        uint4 uu[4];
        #pragma unroll
        for (int t = 0; t < 4; t++)
            uu[t] = *(const uint4*)(q + h * DIM_ + t * 8);
        const __half2* hh = (const __half2*)uu;
        #pragma unroll
        for (int t = 0; t < 16; t++) {
            float2 f = __half22float2(hh[t]);
            qr[2 * t] = f.x; qr[2 * t + 1] = f.y;
        }
        float s = 0.f;
        #pragma unroll
        for (int d = 0; d < DIM_; d++) s = fmaf(qr[d], sKs[h * DIM_ + d], s);
        float z = 1.f / (s + EPS_ATTN);
        const float* kvh = &sKV[h * DIM_ * DIM_];
        #pragma unroll 4
        for (int m = 0; m < DIM_; m += 2) {
            float acc0 = 0.f, acc1 = 0.f;
            #pragma unroll
            for (int d = 0; d < DIM_; d++) {
                acc0 = fmaf(kvh[m * DIM_ + d], qr[d], acc0);
                acc1 = fmaf(kvh[(m + 1) * DIM_ + d], qr[d], acc1);
            }
            __half2 hv = __float22half2_rn(make_float2(acc0 * z, acc1 * z));
            *(uint32_t*)&o[h * DIM_ + m] = *(const uint32_t*)&hv;
        }
    }
}

// ================= host orchestration =================
namespace {

struct Ptrs {
    float *x0, *x1, *KV, *Ks;
    __half *Q, *KVc, *A, *Msg, *Hid, *WTh, *w1Th, *w2Th;
};

void run_layer(float* x, const float* src, const float* xm, const float* sm,
               const __half* WqP, const float* bq, const __half* WkvP,
               const float* bk, const float* bv,
               const __half* WmP, const float* bm,
               const __half* w1P, const __half* w2P, const float* g1, const float* b1,
               const float* g2, const float* b2, const Ptrs& p)
{
    dim3 g1d(1, M_ / BM);   // (1, 600)
    dim3 g2d(2, M_ / BM);   // (2, 600)

    zero_kv<<<(KV_ELEMS + 255) / 256, 256>>>(p.KV, p.Ks);
    gemm_f16<EPI_QK, 8, false, true><<<g1d, 256, SMEM_K8>>>(x,   WqP,  bq, xm, nullptr, nullptr, p.Q,   256);
    gemm_f16<EPI_KV, 8, false, true><<<g2d, 256, SMEM_K8>>>(src, WkvP, bk, sm, bv,      nullptr, p.KVc, 512);
    kv_kernel<<<dim3(B_ * H_, 20), 256>>>(p.KVc, p.KV, p.Ks, L_ / 20);
    attn_apply<<<dim3((L_ + 255) / 256, B_), 256>>>(p.Q, p.KV, p.Ks, p.A);

    gemm_f16<EPI_BIAS_LN, 8, true, true><<<g1d, 256, SMEM_K8>>>(p.A,   WmP, bm, nullptr, g1, b1, p.Msg, 256);
    gemm_f16<EPI_RELU  , 8, true, true><<<g2d, 256, SMEM_K8>>>(p.Msg, w1P, nullptr, nullptr, nullptr, nullptr, p.Hid, 512);
    gemm_f16<EPI_LN_RES, 16, true, false><<<g1d, 256, SMEM_K16>>>(p.Hid, w2P, nullptr, nullptr, g2, b2, x, 256);
}

} // namespace

extern "C" void kernel_launch(void* const* d_in, const int* in_sizes, int n_in,
                              void* d_out, int out_size)
{
    const float* desc0 = (const float*)d_in[0];
    const float* desc1 = (const float*)d_in[1];
    const float* mask0 = (const float*)d_in[2];
    const float* mask1 = (const float*)d_in[3];
    const float* Wq = (const float*)d_in[4];
    const float* bq = (const float*)d_in[5];
    const float* Wk = (const float*)d_in[6];
    const float* bk = (const float*)d_in[7];
    const float* Wv = (const float*)d_in[8];
    const float* bv = (const float*)d_in[9];
    const float* Wm = (const float*)d_in[10];
    const float* bm = (const float*)d_in[11];
    const float* w1 = (const float*)d_in[12];
    const float* w2 = (const float*)d_in[13];
    const float* g1 = (const float*)d_in[14];
    const float* b1 = (const float*)d_in[15];
    const float* g2 = (const float*)d_in[16];
    const float* b2 = (const float*)d_in[17];

    Ptrs p;
    cudaGetSymbolAddress((void**)&p.x0,  g_x0);
    cudaGetSymbolAddress((void**)&p.x1,  g_x1);
    cudaGetSymbolAddress((void**)&p.Q,   g_Q);
    cudaGetSymbolAddress((void**)&p.KVc, g_KVc);
    cudaGetSymbolAddress((void**)&p.A,   g_A);
    cudaGetSymbolAddress((void**)&p.Msg, g_Msg);
    cudaGetSymbolAddress((void**)&p.Hid, g_Hid);
    cudaGetSymbolAddress((void**)&p.KV,  g_KV);
    cudaGetSymbolAddress((void**)&p.Ks,  g_Ks);
    cudaGetSymbolAddress((void**)&p.WTh,  g_WTh);
    cudaGetSymbolAddress((void**)&p.w1Th, g_w1Th);
    cudaGetSymbolAddress((void**)&p.w2Th, g_w2Th);

    cudaFuncSetAttribute((const void*)gemm_f16<EPI_QK, 8, false, true>,      cudaFuncAttributeMaxDynamicSharedMemorySize, SMEM_K8);
    cudaFuncSetAttribute((const void*)gemm_f16<EPI_KV, 8, false, true>,      cudaFuncAttributeMaxDynamicSharedMemorySize, SMEM_K8);
    cudaFuncSetAttribute((const void*)gemm_f16<EPI_BIAS_LN, 8, true, true>,  cudaFuncAttributeMaxDynamicSharedMemorySize, SMEM_K8);
    cudaFuncSetAttribute((const void*)gemm_f16<EPI_RELU, 8, true, true>,     cudaFuncAttributeMaxDynamicSharedMemorySize, SMEM_K8);
    cudaFuncSetAttribute((const void*)gemm_f16<EPI_LN_RES, 16, true, false>, cudaFuncAttributeMaxDynamicSharedMemorySize, SMEM_K16);

    // ---- one-time weight packing ----
    pack_all<<<(4 * 65536 + 2 * 8 * 131072) / 256, 256>>>(Wq, Wk, Wv, Wm, w1, w2,
                                                          p.WTh, p.w1Th, p.w2Th);

    const size_t tensorBytes = (size_t)M_ * D_ * sizeof(float);
    cudaMemcpyAsync(p.x0, desc0, tensorBytes, cudaMemcpyDeviceToDevice);
    cudaMemcpyAsync(p.x1, desc1, tensorBytes, cudaMemcpyDeviceToDevice);

    const int w1sz = D_ * 2 * D_;
    const int w2sz = 2 * D_ * D_;

    for (int li = 0; li < 8; li++) {
        const __half* lw1 = p.w1Th + (size_t)li * w1sz;
        const __half* lw2 = p.w2Th + (size_t)li * w2sz;
        const float* lg1 = g1 + li * D_;
        const float* lb1 = b1 + li * D_;
        const float* lg2 = g2 + li * D_;
        const float* lb2 = b2 + li * D_;
        const __half* WqP  = p.WTh + 0 * D_ * D_;
        const __half* WkvP = p.WTh + 1 * D_ * D_;   // Wk | Wv contiguous packed blocks
        const __half* WmP  = p.WTh + 3 * D_ * D_;
        if ((li & 1) == 0) {
            run_layer(p.x0, p.x0, mask0, mask0, WqP, bq, WkvP, bk, bv, WmP, bm,
                      lw1, lw2, lg1, lb1, lg2, lb2, p);
            run_layer(p.x1, p.x1, mask1, mask1, WqP, bq, WkvP, bk, bv, WmP, bm,
                      lw1, lw2, lg1, lb1, lg2, lb2, p);
        } else {
            run_layer(p.x0, p.x1, mask0, mask1, WqP, bq, WkvP, bk, bv, WmP, bm,
                      lw1, lw2, lg1, lb1, lg2, lb2, p);
            run_layer(p.x1, p.x0, mask1, mask0, WqP, bq, WkvP, bk, bv, WmP, bm,
                      lw1, lw2, lg1, lb1, lg2, lb2, p);
        }
    }

    cudaMemcpyAsync((float*)d_out,                   p.x0, tensorBytes, cudaMemcpyDeviceToDevice);
    cudaMemcpyAsync((float*)d_out + (size_t)M_ * D_, p.x1, tensorBytes, cudaMemcpyDeviceToDevice);
}

// round 11
// speedup vs baseline: 1.1981x; 1.0144x over previous
#include <cuda_runtime.h>
#include <cuda_fp16.h>
#include <math.h>
#include <stdint.h>

// ================= problem constants =================
namespace {
constexpr int B_ = 8, L_ = 4800, D_ = 256, H_ = 8, DIM_ = 32;
constexpr int M_ = B_ * L_;            // 38400 rows
constexpr float EPS_ATTN = 1e-6f, EPS_LN = 1e-5f;
constexpr int KV_ELEMS = B_ * H_ * DIM_ * DIM_;   // 65536
constexpr int KS_ELEMS = B_ * H_ * DIM_;          // 2048

constexpr int BM = 64;                 // CTA rows; 8 warps; warp tile 64x32
constexpr int SMEM_K8  = (8  * 1024 + 768) * 4;   // 35840 B
constexpr int SMEM_K16 = (16 * 1024 + 768) * 4;   // 68608 B
}

// ================= scratch (static device globals) =================
__device__ float  g_x0[M_ * D_];
__device__ float  g_x1[M_ * D_];
__device__ __half g_xh0[M_ * D_];             // fp16 shadow of x0 (bit-identical to staging rounding)
__device__ __half g_xh1[M_ * D_];
__device__ __half g_Q  [M_ * D_];
__device__ __half g_KVc[M_ * 2 * D_];         // K (cols 0-255) | V (cols 256-511)
__device__ __half g_A  [M_ * D_];
__device__ __half g_Msg[M_ * D_];
__device__ __half g_Hid[M_ * 2 * D_];
__device__ float  g_KV[KV_ELEMS];
__device__ float  g_Ks[KS_ELEMS];
__device__ __half g_WTh [4 * D_ * D_];        // frag-major fp16: Wq,Wk,Wv,Wm
__device__ __half g_w1Th[8 * 2 * D_ * D_];
__device__ __half g_w2Th[8 * D_ * 2 * D_];

// ================= mma helper =================
__device__ __forceinline__ void mma_f16(float d[4], const uint32_t a[4],
                                        uint32_t b0, uint32_t b1) {
    asm volatile(
        "mma.sync.aligned.m16n8k16.row.col.f32.f16.f16.f32 "
        "{%0,%1,%2,%3}, {%4,%5,%6,%7}, {%8,%9}, {%0,%1,%2,%3};\n"
        : "+f"(d[0]), "+f"(d[1]), "+f"(d[2]), "+f"(d[3])
        : "r"(a[0]), "r"(a[1]), "r"(a[2]), "r"(a[3]), "r"(b0), "r"(b1));
}

// ================= weight pack: [K,N] f32 -> frag-major fp16 =================
__device__ __forceinline__ void pack_one(const float* __restrict__ in,
                                         __half* __restrict__ out,
                                         int t, int K, int N)
{
    int k = t / N, n = t % N;
    int nblk = n >> 8, nloc = n & 255;
    int wn = nloc >> 5, j = (nloc >> 3) & 3, gid = nloc & 7;
    int p = j >> 1, jh = j & 1;
    int kch = k >> 5, kin = k & 31, kstep = kin >> 4, c16 = kin & 15;
    int qid = (c16 >> 1) & 3, kh = (c16 >> 3) & 1, h = c16 & 1;
    int lane = gid * 4 + qid;
    int NKCH = K >> 5;
    size_t idx = ((((((size_t)nblk * NKCH + kch) * 2 + kstep) * 8 + wn) * 2 + p) * 32
                  + lane) * 8 + jh * 4 + kh * 2 + h;
    out[idx] = __float2half_rn(in[t]);
}

__global__ void pack_all(const float* __restrict__ Wq, const float* __restrict__ Wk,
                         const float* __restrict__ Wv, const float* __restrict__ Wm,
                         const float* __restrict__ w1, const float* __restrict__ w2,
                         __half* __restrict__ WTh, __half* __restrict__ w1Th,
                         __half* __restrict__ w2Th)
{
    long idx = (long)blockIdx.x * 256 + threadIdx.x;
    const long S0 = 4L * 65536, S1 = 8L * 131072;
    if (idx < S0) {
        int which = (int)(idx >> 16), t = (int)(idx & 65535);
        const float* src = which == 0 ? Wq : which == 1 ? Wk : which == 2 ? Wv : Wm;
        pack_one(src, WTh + (long)which * 65536, t, 256, 256);
    } else if (idx < S0 + S1) {
        long i2 = idx - S0;
        int layer = (int)(i2 >> 17), t = (int)(i2 & 131071);
        pack_one(w1 + (long)layer * 131072, w1Th + (long)layer * 131072, t, 256, 512);
    } else {
        long i2 = idx - S0 - S1;
        int layer = (int)(i2 >> 17), t = (int)(i2 & 131071);
        pack_one(w2 + (long)layer * 131072, w2Th + (long)layer * 131072, t, 512, 256);
    }
}

// ================= x -> fp16 shadow (initial) =================
__global__ void x_to_h(const float* __restrict__ x0, const float* __restrict__ x1,
                       __half* __restrict__ h0, __half* __restrict__ h1)
{
    size_t i = ((size_t)blockIdx.x * 256 + threadIdx.x) * 4;
    if (i >= (size_t)M_ * D_) return;
    const float* x = blockIdx.y == 0 ? x0 : x1;
    __half* h = blockIdx.y == 0 ? h0 : h1;
    float4 v = *(const float4*)(x + i);
    __half2 a = __float22half2_rn(make_float2(v.x, v.y));
    __half2 b = __float22half2_rn(make_float2(v.z, v.w));
    uint32_t u[2] = {*(const uint32_t*)&a, *(const uint32_t*)&b};
    *(uint2*)(h + i) = *(const uint2*)u;
}

// ================= fp16 tensor-core GEMM =================
// AH: A input fp16 row-major. OH: C output fp16.
// EPI_QK additionally zeroes KV/Ks scratch (runs before kv_kernel).
// EPI_LN_RES writes fp32 x (+residual) AND its fp16 shadow xh.
enum { EPI_QK = 1, EPI_RELU = 3, EPI_BIAS_LN = 5, EPI_LN_RES = 6, EPI_KV = 7 };

template<int EPI, int KCH, bool AH, bool OH>
__global__ __launch_bounds__(256, 2)
void gemm_f16(const void* __restrict__ Ain, const __half* __restrict__ Bp,
              const float* __restrict__ bias, const float* __restrict__ mask,
              const float* __restrict__ lng, const float* __restrict__ lnb,
              void* __restrict__ Cout, int N,
              __half* __restrict__ xh, float* __restrict__ kvz, float* __restrict__ ksz)
{
    constexpr int K = KCH * 32;
    extern __shared__ float sm[];
    uint32_t* As = (uint32_t*)sm;                  // KCH slots x 1024 u32 (A frags)
    float* sbias = sm + KCH * 1024;
    float* sg    = sbias + 256;
    float* sb    = sg + 256;
    float* red1 = sm;                 // epilogue scratch (reuses A region)
    float* red2 = sm + 512;
    float* smu  = sm + 1024;
    float* srs  = sm + 1088;

    const int tid = threadIdx.x;
    const int wn = tid >> 5, lane = tid & 31;
    const int gid = lane >> 2, qid = lane & 3;
    const int rowBase = blockIdx.y * BM;
    const int colBase = blockIdx.x * 256;

    if (EPI == EPI_QK) {
        // fold KV/Ks zeroing into this kernel (precedes kv_kernel on-stream)
        const int by = blockIdx.y;
        if (by < 256) kvz[by * 256 + tid] = 0.f;
        else if (by < 264) ksz[(by - 256) * 256 + tid] = 0.f;
    }

    if (EPI == EPI_QK || EPI == EPI_BIAS_LN)
        sbias[tid] = bias[colBase + tid];
    if (EPI == EPI_KV)
        sbias[tid] = (blockIdx.x == 0 ? bias : lng)[tid];   // bk | bv
    if (EPI == EPI_BIAS_LN || EPI == EPI_LN_RES) { sg[tid] = lng[tid]; sb[tid] = lnb[tid]; }

    // ---- stage FULL A tile (64 x K) as fp16 fragments, once ----
    {
        const int arow = tid >> 2, aq = tid & 3;
        const int a_base = ((aq >> 1) * 4 + (arow >> 4)) * 128 + (arow & 7) * 16
                         + (aq & 1) * 2 + ((arow >> 3) & 1);
        if (AH) {
            const __half* Aptr = (const __half*)Ain + (size_t)(rowBase + arow) * K + aq * 8;
            #pragma unroll
            for (int c = 0; c < KCH; c++) {
                uint4 v = *(const uint4*)(Aptr + (size_t)c * 32);
                uint32_t* d = As + c * 1024 + a_base;
                d[0] = v.x; d[4] = v.y; d[8] = v.z; d[12] = v.w;
            }
        } else {
            const float* Aptr = (const float*)Ain + (size_t)(rowBase + arow) * K + aq * 8;
            #pragma unroll
            for (int c = 0; c < KCH; c++) {
                float4 v0 = *(const float4*)(Aptr + (size_t)c * 32);
                float4 v1 = *(const float4*)(Aptr + (size_t)c * 32 + 4);
                uint32_t* d = As + c * 1024 + a_base;
                const float* f0 = (const float*)&v0;
                const float* f1 = (const float*)&v1;
                #pragma unroll
                for (int q = 0; q < 2; q++) {
                    __half2 h = __float22half2_rn(make_float2(f0[2*q], f0[2*q+1]));
                    d[q * 4] = *(const uint32_t*)&h;
                }
                #pragma unroll
                for (int q = 0; q < 2; q++) {
                    __half2 h = __float22half2_rn(make_float2(f1[2*q], f1[2*q+1]));
                    d[(q + 2) * 4] = *(const uint32_t*)&h;
                }
            }
        }
    }
    __syncthreads();

    // ---- mainloop: barrier-free, A+B double-buffered one kk ahead ----
    float acc[4][4][4];
    #pragma unroll
    for (int mi = 0; mi < 4; mi++)
        #pragma unroll
        for (int j = 0; j < 4; j++)
            #pragma unroll
            for (int q = 0; q < 4; q++) acc[mi][j][q] = 0.f;

    const uint32_t* Asl = As + lane * 4;
    const __half* Bch = Bp + (size_t)blockIdx.x * KCH * 8192
                        + (size_t)wn * 512 + lane * 8;

    uint4 af[2][4], bf[2][2];
    #pragma unroll
    for (int mi = 0; mi < 4; mi++)
        af[0][mi] = *(const uint4*)(Asl + mi * 128);
    bf[0][0] = *(const uint4*)(Bch);
    bf[0][1] = *(const uint4*)(Bch + 256);

    #pragma unroll
    for (int kk = 0; kk < 2 * KCH; kk++) {
        const int cur = kk & 1, nxt = cur ^ 1;
        if (kk + 1 < 2 * KCH) {
            const uint32_t* asn = Asl + (kk + 1) * 512;
            #pragma unroll
            for (int mi = 0; mi < 4; mi++)
                af[nxt][mi] = *(const uint4*)(asn + mi * 128);
            const __half* s = Bch + (size_t)(kk + 1) * 4096;
            bf[nxt][0] = *(const uint4*)(s);
            bf[nxt][1] = *(const uint4*)(s + 256);
        }
        #pragma unroll
        for (int mi = 0; mi < 4; mi++) {
            const uint32_t a4[4] = {af[cur][mi].x, af[cur][mi].y,
                                    af[cur][mi].z, af[cur][mi].w};
            mma_f16(acc[mi][0], a4, bf[cur][0].x, bf[cur][0].y);
            mma_f16(acc[mi][1], a4, bf[cur][0].z, bf[cur][0].w);
            mma_f16(acc[mi][2], a4, bf[cur][1].x, bf[cur][1].y);
            mma_f16(acc[mi][3], a4, bf[cur][1].z, bf[cur][1].w);
        }
    }
    __syncthreads();   // A region free for epilogue scratch

    // ================= epilogue =================
    // element (mi,j,q): row = rowBase + mi*16 + (q>>1)*8 + gid
    //                   col = colBase + wn*32 + j*8 + qid*2 + (q&1)
    if (EPI == EPI_QK || EPI == EPI_BIAS_LN || EPI == EPI_KV) {
        #pragma unroll
        for (int mi = 0; mi < 4; mi++)
            #pragma unroll
            for (int j = 0; j < 4; j++) {
                const int c = wn * 32 + j * 8 + qid * 2;
                acc[mi][j][0] += sbias[c];   acc[mi][j][1] += sbias[c + 1];
                acc[mi][j][2] += sbias[c];   acc[mi][j][3] += sbias[c + 1];
            }
    }
    if (EPI == EPI_QK || EPI == EPI_KV) {
        const bool do_elu = (EPI == EPI_QK) || (EPI == EPI_KV && blockIdx.x == 0);
        float mk[4][2];
        #pragma unroll
        for (int mi = 0; mi < 4; mi++)
            #pragma unroll
            for (int r = 0; r < 2; r++)
                mk[mi][r] = mask[rowBase + mi * 16 + r * 8 + gid];
        #pragma unroll
        for (int mi = 0; mi < 4; mi++)
            #pragma unroll
            for (int j = 0; j < 4; j++)
                #pragma unroll
                for (int q = 0; q < 4; q++) {
                    float t = acc[mi][j][q];
                    if (do_elu) t = (t > 0.f) ? (t + 1.f) : expf(t);
                    acc[mi][j][q] = t * mk[mi][q >> 1];
                }
    }
    if (EPI == EPI_RELU) {
        #pragma unroll
        for (int mi = 0; mi < 4; mi++)
            #pragma unroll
            for (int j = 0; j < 4; j++)
                #pragma unroll
                for (int q = 0; q < 4; q++)
                    acc[mi][j][q] = acc[mi][j][q] > 0.f ? acc[mi][j][q] : 0.f;
    }

    if (EPI == EPI_BIAS_LN || EPI == EPI_LN_RES) {
        float s1[4][2], s2[4][2];
        #pragma unroll
        for (int mi = 0; mi < 4; mi++)
            #pragma unroll
            for (int r = 0; r < 2; r++) { s1[mi][r] = 0.f; s2[mi][r] = 0.f; }
        #pragma unroll
        for (int mi = 0; mi < 4; mi++)
            #pragma unroll
            for (int j = 0; j < 4; j++)
                #pragma unroll
                for (int q = 0; q < 4; q++) {
                    float v = acc[mi][j][q];
                    s1[mi][q >> 1] += v;
                    s2[mi][q >> 1] = fmaf(v, v, s2[mi][q >> 1]);
                }
        #pragma unroll
        for (int o = 1; o <= 2; o <<= 1)
            #pragma unroll
            for (int mi = 0; mi < 4; mi++)
                #pragma unroll
                for (int r = 0; r < 2; r++) {
                    s1[mi][r] += __shfl_xor_sync(0xffffffffu, s1[mi][r], o);
                    s2[mi][r] += __shfl_xor_sync(0xffffffffu, s2[mi][r], o);
                }
        if (qid == 0) {
            #pragma unroll
            for (int mi = 0; mi < 4; mi++)
                #pragma unroll
                for (int r = 0; r < 2; r++) {
                    int rl = mi * 16 + r * 8 + gid;
                    red1[rl * 8 + wn] = s1[mi][r];
                    red2[rl * 8 + wn] = s2[mi][r];
                }
        }
        __syncthreads();
        if (tid < 64) {
            float a = 0.f, b2 = 0.f;
            #pragma unroll
            for (int w = 0; w < 8; w++) { a += red1[tid * 8 + w]; b2 += red2[tid * 8 + w]; }
            float mu = a * (1.f / 256.f);
            float var = b2 * (1.f / 256.f) - mu * mu;
            smu[tid] = mu;
            srs[tid] = rsqrtf(var + EPS_LN);
        }
        __syncthreads();
        #pragma unroll
        for (int mi = 0; mi < 4; mi++)
            #pragma unroll
            for (int j = 0; j < 4; j++)
                #pragma unroll
                for (int q = 0; q < 4; q++) {
                    int rl = mi * 16 + (q >> 1) * 8 + gid;
                    int c  = wn * 32 + j * 8 + qid * 2 + (q & 1);
                    acc[mi][j][q] = (acc[mi][j][q] - smu[rl]) * srs[rl] * sg[c] + sb[c];
                }
    }

    // store
    #pragma unroll
    for (int mi = 0; mi < 4; mi++) {
        #pragma unroll
        for (int j = 0; j < 4; j++) {
            const int c  = colBase + wn * 32 + j * 8 + qid * 2;
            const int r0 = rowBase + mi * 16 + gid;
            const int r1 = r0 + 8;
            if (OH) {
                __half* Ch = (__half*)Cout;
                __half2 h0 = __float22half2_rn(make_float2(acc[mi][j][0], acc[mi][j][1]));
                __half2 h1 = __float22half2_rn(make_float2(acc[mi][j][2], acc[mi][j][3]));
                *(uint32_t*)&Ch[(size_t)r0 * N + c] = *(const uint32_t*)&h0;
                *(uint32_t*)&Ch[(size_t)r1 * N + c] = *(const uint32_t*)&h1;
            } else {
                float* Cf = (float*)Cout;
                float2 v0 = make_float2(acc[mi][j][0], acc[mi][j][1]);
                float2 v1 = make_float2(acc[mi][j][2], acc[mi][j][3]);
                if (EPI == EPI_LN_RES) {
                    float2 x0 = *(const float2*)&Cf[(size_t)r0 * N + c];
                    float2 x1 = *(const float2*)&Cf[(size_t)r1 * N + c];
                    v0.x += x0.x; v0.y += x0.y;
                    v1.x += x1.x; v1.y += x1.y;
                }
                *(float2*)&Cf[(size_t)r0 * N + c] = v0;
                *(float2*)&Cf[(size_t)r1 * N + c] = v1;
                if (EPI == EPI_LN_RES) {
                    // fp16 shadow of the residual stream
                    __half2 h0 = __float22half2_rn(v0);
                    __half2 h1 = __float22half2_rn(v1);
                    *(uint32_t*)&xh[(size_t)r0 * N + c] = *(const uint32_t*)&h0;
                    *(uint32_t*)&xh[(size_t)r1 * N + c] = *(const uint32_t*)&h1;
                }
            }
        }
    }
}

// ================= KV reduction (reads combined fp16 K|V buffer, stride 512) =====
__global__ __launch_bounds__(256)
void kv_kernel(const __half* __restrict__ KVc,
               float* __restrict__ KV, float* __restrict__ Ks, int rowsPerSplit)
{
    const int bh = blockIdx.x;
    const int b = bh >> 3, h = bh & 7;
    const int l0 = blockIdx.y * rowsPerSplit;
    const int tid = threadIdx.x;
    const int lr = tid >> 5;
    const int ld = tid & 31;

    __shared__ float Kt[8][32];
    __shared__ float Vt[8][32];

    float a0 = 0.f, a1 = 0.f, a2 = 0.f, a3 = 0.f, ks = 0.f;

    for (int c = 0; c < rowsPerSplit; c += 8) {
        int l = l0 + c + lr;
        size_t base = ((size_t)b * L_ + l) * (2 * D_) + h * DIM_ + ld;
        Kt[lr][ld] = __half2float(KVc[base]);
        Vt[lr][ld] = __half2float(KVc[base + D_]);
        __syncthreads();
        #pragma unroll
        for (int r = 0; r < 8; r++) {
            float kv = Kt[r][ld];
            a0 = fmaf(kv, Vt[r][lr +  0], a0);
            a1 = fmaf(kv, Vt[r][lr +  8], a1);
            a2 = fmaf(kv, Vt[r][lr + 16], a2);
            a3 = fmaf(kv, Vt[r][lr + 24], a3);
        }
        if (tid < 32) {
            #pragma unroll
            for (int r = 0; r < 8; r++) ks += Kt[r][tid];
        }
        __syncthreads();
    }

    float* kvb = KV + (size_t)bh * DIM_ * DIM_;
    atomicAdd(&kvb[(lr +  0) * DIM_ + ld], a0);
    atomicAdd(&kvb[(lr +  8) * DIM_ + ld], a1);
    atomicAdd(&kvb[(lr + 16) * DIM_ + ld], a2);
    atomicAdd(&kvb[(lr + 24) * DIM_ + ld], a3);
    if (tid < 32) atomicAdd(&Ks[bh * DIM_ + tid], ks);
}

// ================= attention apply (fp16 Q in, fp16 A out) =================
__global__ __launch_bounds__(256)
void attn_apply(const __half* __restrict__ Q, const float* __restrict__ KV,
                const float* __restrict__ Ks, __half* __restrict__ Out)
{
    __shared__ float sKV[H_ * DIM_ * DIM_];
    __shared__ float sKs[H_ * DIM_];
    const int b = blockIdx.y;
    const int tid = threadIdx.x;

    for (int i = tid; i < H_ * DIM_ * DIM_; i += 256)
        sKV[i] = KV[(size_t)b * H_ * DIM_ * DIM_ + i];
    if (tid < H_ * DIM_) sKs[tid] = Ks[b * H_ * DIM_ + tid];
    __syncthreads();

    const int token = blockIdx.x * 256 + tid;
    if (token >= L_) return;
    const size_t row = (size_t)b * L_ + token;
    const __half* q = Q + row * D_;
    __half* o = Out + row * D_;

    for (int h = 0; h < H_; h++) {
        float qr[DIM_];
        uint4 uu[4];
        #pragma unroll
        for (int t = 0; t < 4; t++)
            uu[t] = *(const uint4*)(q + h * DIM_ + t * 8);
        const __half2* hh = (const __half2*)uu;
        #pragma unroll
        for (int t = 0; t < 16; t++) {
            float2 f = __half22float2(hh[t]);
            qr[2 * t] = f.x; qr[2 * t + 1] = f.y;
        }
        float s = 0.f;
        #pragma unroll
        for (int d = 0; d < DIM_; d++) s = fmaf(qr[d], sKs[h * DIM_ + d], s);
        float z = 1.f / (s + EPS_ATTN);
        const float* kvh = &sKV[h * DIM_ * DIM_];
        #pragma unroll 4
        for (int m = 0; m < DIM_; m += 2) {
            float acc0 = 0.f, acc1 = 0.f;
            #pragma unroll
            for (int d = 0; d < DIM_; d++) {
                acc0 = fmaf(kvh[m * DIM_ + d], qr[d], acc0);
                acc1 = fmaf(kvh[(m + 1) * DIM_ + d], qr[d], acc1);
            }
            __half2 hv = __float22half2_rn(make_float2(acc0 * z, acc1 * z));
            *(uint32_t*)&o[h * DIM_ + m] = *(const uint32_t*)&hv;
        }
    }
}

// ================= host orchestration =================
namespace {

struct Ptrs {
    float *x0, *x1, *KV, *Ks;
    __half *xh0, *xh1, *Q, *KVc, *A, *Msg, *Hid, *WTh, *w1Th, *w2Th;
};

void run_layer(float* x, __half* xh, const __half* srch,
               const float* xm, const float* sm,
               const __half* WqP, const float* bq, const __half* WkvP,
               const float* bk, const float* bv,
               const __half* WmP, const float* bm,
               const __half* w1P, const __half* w2P, const float* g1, const float* b1,
               const float* g2, const float* b2, const Ptrs& p)
{
    dim3 g1d(1, M_ / BM);   // (1, 600)
    dim3 g2d(2, M_ / BM);   // (2, 600)

    gemm_f16<EPI_QK, 8, true, true><<<g1d, 256, SMEM_K8>>>(
        xh, WqP, bq, xm, nullptr, nullptr, p.Q, 256, nullptr, p.KV, p.Ks);
    gemm_f16<EPI_KV, 8, true, true><<<g2d, 256, SMEM_K8>>>(
        srch, WkvP, bk, sm, bv, nullptr, p.KVc, 512, nullptr, nullptr, nullptr);
    kv_kernel<<<dim3(B_ * H_, 20), 256>>>(p.KVc, p.KV, p.Ks, L_ / 20);
    attn_apply<<<dim3((L_ + 255) / 256, B_), 256>>>(p.Q, p.KV, p.Ks, p.A);

    gemm_f16<EPI_BIAS_LN, 8, true, true><<<g1d, 256, SMEM_K8>>>(
        p.A, WmP, bm, nullptr, g1, b1, p.Msg, 256, nullptr, nullptr, nullptr);
    gemm_f16<EPI_RELU, 8, true, true><<<g2d, 256, SMEM_K8>>>(
        p.Msg, w1P, nullptr, nullptr, nullptr, nullptr, p.Hid, 512, nullptr, nullptr, nullptr);
    gemm_f16<EPI_LN_RES, 16, true, false><<<g1d, 256, SMEM_K16>>>(
        p.Hid, w2P, nullptr, nullptr, g2, b2, x, 256, xh, nullptr, nullptr);
}

} // namespace

extern "C" void kernel_launch(void* const* d_in, const int* in_sizes, int n_in,
                              void* d_out, int out_size)
{
    const float* desc0 = (const float*)d_in[0];
    const float* desc1 = (const float*)d_in[1];
    const float* mask0 = (const float*)d_in[2];
    const float* mask1 = (const float*)d_in[3];
    const float* Wq = (const float*)d_in[4];
    const float* bq = (const float*)d_in[5];
    const float* Wk = (const float*)d_in[6];
    const float* bk = (const float*)d_in[7];
    const float* Wv = (const float*)d_in[8];
    const float* bv = (const float*)d_in[9];
    const float* Wm = (const float*)d_in[10];
    const float* bm = (const float*)d_in[11];
    const float* w1 = (const float*)d_in[12];
    const float* w2 = (const float*)d_in[13];
    const float* g1 = (const float*)d_in[14];
    const float* b1 = (const float*)d_in[15];
    const float* g2 = (const float*)d_in[16];
    const float* b2 = (const float*)d_in[17];

    Ptrs p;
    cudaGetSymbolAddress((void**)&p.x0,  g_x0);
    cudaGetSymbolAddress((void**)&p.x1,  g_x1);
    cudaGetSymbolAddress((void**)&p.xh0, g_xh0);
    cudaGetSymbolAddress((void**)&p.xh1, g_xh1);
    cudaGetSymbolAddress((void**)&p.Q,   g_Q);
    cudaGetSymbolAddress((void**)&p.KVc, g_KVc);
    cudaGetSymbolAddress((void**)&p.A,   g_A);
    cudaGetSymbolAddress((void**)&p.Msg, g_Msg);
    cudaGetSymbolAddress((void**)&p.Hid, g_Hid);
    cudaGetSymbolAddress((void**)&p.KV,  g_KV);
    cudaGetSymbolAddress((void**)&p.Ks,  g_Ks);
    cudaGetSymbolAddress((void**)&p.WTh,  g_WTh);
    cudaGetSymbolAddress((void**)&p.w1Th, g_w1Th);
    cudaGetSymbolAddress((void**)&p.w2Th, g_w2Th);

    cudaFuncSetAttribute((const void*)gemm_f16<EPI_QK, 8, true, true>,       cudaFuncAttributeMaxDynamicSharedMemorySize, SMEM_K8);
    cudaFuncSetAttribute((const void*)gemm_f16<EPI_KV, 8, true, true>,       cudaFuncAttributeMaxDynamicSharedMemorySize, SMEM_K8);
    cudaFuncSetAttribute((const void*)gemm_f16<EPI_BIAS_LN, 8, true, true>,  cudaFuncAttributeMaxDynamicSharedMemorySize, SMEM_K8);
    cudaFuncSetAttribute((const void*)gemm_f16<EPI_RELU, 8, true, true>,     cudaFuncAttributeMaxDynamicSharedMemorySize, SMEM_K8);
    cudaFuncSetAttribute((const void*)gemm_f16<EPI_LN_RES, 16, true, false>, cudaFuncAttributeMaxDynamicSharedMemorySize, SMEM_K16);

    // ---- one-time prep ----
    pack_all<<<(4 * 65536 + 2 * 8 * 131072) / 256, 256>>>(Wq, Wk, Wv, Wm, w1, w2,
                                                          p.WTh, p.w1Th, p.w2Th);

    const size_t tensorBytes = (size_t)M_ * D_ * sizeof(float);
    cudaMemcpyAsync(p.x0, desc0, tensorBytes, cudaMemcpyDeviceToDevice);
    cudaMemcpyAsync(p.x1, desc1, tensorBytes, cudaMemcpyDeviceToDevice);
    x_to_h<<<dim3((M_ * D_ / 4 + 255) / 256, 2), 256>>>(p.x0, p.x1, p.xh0, p.xh1);

    const int w1sz = D_ * 2 * D_;
    const int w2sz = 2 * D_ * D_;

    for (int li = 0; li < 8; li++) {
        const __half* lw1 = p.w1Th + (size_t)li * w1sz;
        const __half* lw2 = p.w2Th + (size_t)li * w2sz;
        const float* lg1 = g1 + li * D_;
        const float* lb1 = b1 + li * D_;
        const float* lg2 = g2 + li * D_;
        const float* lb2 = b2 + li * D_;
        const __half* WqP  = p.WTh + 0 * D_ * D_;
        const __half* WkvP = p.WTh + 1 * D_ * D_;   // Wk | Wv contiguous packed blocks
        const __half* WmP  = p.WTh + 3 * D_ * D_;
        if ((li & 1) == 0) {
            run_layer(p.x0, p.xh0, p.xh0, mask0, mask0, WqP, bq, WkvP, bk, bv, WmP, bm,
                      lw1, lw2, lg1, lb1, lg2, lb2, p);
            run_layer(p.x1, p.xh1, p.xh1, mask1, mask1, WqP, bq, WkvP, bk, bv, WmP, bm,
                      lw1, lw2, lg1, lb1, lg2, lb2, p);
        } else {
            run_layer(p.x0, p.xh0, p.xh1, mask0, mask1, WqP, bq, WkvP, bk, bv, WmP, bm,
                      lw1, lw2, lg1, lb1, lg2, lb2, p);
            run_layer(p.x1, p.xh1, p.xh0, mask1, mask0, WqP, bq, WkvP, bk, bv, WmP, bm,
                      lw1, lw2, lg1, lb1, lg2, lb2, p);
        }
    }

    cudaMemcpyAsync((float*)d_out,                   p.x0, tensorBytes, cudaMemcpyDeviceToDevice);
    cudaMemcpyAsync((float*)d_out + (size_t)M_ * D_, p.x1, tensorBytes, cudaMemcpyDeviceToDevice);
}

// round 12
// speedup vs baseline: 1.2127x; 1.0122x over previous
#include <cuda_runtime.h>
#include <cuda_fp16.h>
#include <math.h>
#include <stdint.h>

// ================= problem constants =================
namespace {
constexpr int B_ = 8, L_ = 4800, D_ = 256, H_ = 8, DIM_ = 32;
constexpr int M_ = B_ * L_;            // 38400 rows
constexpr float EPS_ATTN = 1e-6f, EPS_LN = 1e-5f;
constexpr int KV_ELEMS = B_ * H_ * DIM_ * DIM_;   // 65536
constexpr int KS_ELEMS = B_ * H_ * DIM_;          // 2048

constexpr int BM = 64;                 // CTA rows; 8 warps; warp tile 64x32
constexpr int SMEM_K8  = (8  * 1024 + 768) * 4;   // 35840 B
constexpr int SMEM_K16 = (16 * 1024 + 768) * 4;   // 68608 B
}

// ================= scratch (static device globals) =================
__device__ float  g_x0[M_ * D_];
__device__ float  g_x1[M_ * D_];
__device__ __half g_xh0[M_ * D_];             // fp16 shadow of x0
__device__ __half g_xh1[M_ * D_];
__device__ __half g_Q  [M_ * D_];
__device__ __half g_KVc[M_ * 2 * D_];         // K (cols 0-255) | V (cols 256-511)
__device__ __half g_A  [M_ * D_];
__device__ __half g_Msg[M_ * D_];
__device__ __half g_Hid[M_ * 2 * D_];
__device__ float  g_KV[KV_ELEMS];
__device__ float  g_Ks[KS_ELEMS];
__device__ __half g_WTh [4 * D_ * D_];        // frag-major fp16: Wq,Wk,Wv,Wm
__device__ __half g_w1Th[8 * 2 * D_ * D_];
__device__ __half g_w2Th[8 * D_ * 2 * D_];

// ================= mma helper =================
__device__ __forceinline__ void mma_f16(float d[4], const uint32_t a[4],
                                        uint32_t b0, uint32_t b1) {
    asm volatile(
        "mma.sync.aligned.m16n8k16.row.col.f32.f16.f16.f32 "
        "{%0,%1,%2,%3}, {%4,%5,%6,%7}, {%8,%9}, {%0,%1,%2,%3};\n"
        : "+f"(d[0]), "+f"(d[1]), "+f"(d[2]), "+f"(d[3])
        : "r"(a[0]), "r"(a[1]), "r"(a[2]), "r"(a[3]), "r"(b0), "r"(b1));
}

// ================= weight pack: [K,N] f32 -> frag-major fp16 =================
__device__ __forceinline__ void pack_one(const float* __restrict__ in,
                                         __half* __restrict__ out,
                                         int t, int K, int N)
{
    int k = t / N, n = t % N;
    int nblk = n >> 8, nloc = n & 255;
    int wn = nloc >> 5, j = (nloc >> 3) & 3, gid = nloc & 7;
    int p = j >> 1, jh = j & 1;
    int kch = k >> 5, kin = k & 31, kstep = kin >> 4, c16 = kin & 15;
    int qid = (c16 >> 1) & 3, kh = (c16 >> 3) & 1, h = c16 & 1;
    int lane = gid * 4 + qid;
    int NKCH = K >> 5;
    size_t idx = ((((((size_t)nblk * NKCH + kch) * 2 + kstep) * 8 + wn) * 2 + p) * 32
                  + lane) * 8 + jh * 4 + kh * 2 + h;
    out[idx] = __float2half_rn(in[t]);
}

__global__ void pack_all(const float* __restrict__ Wq, const float* __restrict__ Wk,
                         const float* __restrict__ Wv, const float* __restrict__ Wm,
                         const float* __restrict__ w1, const float* __restrict__ w2,
                         __half* __restrict__ WTh, __half* __restrict__ w1Th,
                         __half* __restrict__ w2Th)
{
    long idx = (long)blockIdx.x * 256 + threadIdx.x;
    const long S0 = 4L * 65536, S1 = 8L * 131072;
    if (idx < S0) {
        int which = (int)(idx >> 16), t = (int)(idx & 65535);
        const float* src = which == 0 ? Wq : which == 1 ? Wk : which == 2 ? Wv : Wm;
        pack_one(src, WTh + (long)which * 65536, t, 256, 256);
    } else if (idx < S0 + S1) {
        long i2 = idx - S0;
        int layer = (int)(i2 >> 17), t = (int)(i2 & 131071);
        pack_one(w1 + (long)layer * 131072, w1Th + (long)layer * 131072, t, 256, 512);
    } else {
        long i2 = idx - S0 - S1;
        int layer = (int)(i2 >> 17), t = (int)(i2 & 131071);
        pack_one(w2 + (long)layer * 131072, w2Th + (long)layer * 131072, t, 512, 256);
    }
}

// ================= x -> fp16 shadow (initial) =================
__global__ void x_to_h(const float* __restrict__ x0, const float* __restrict__ x1,
                       __half* __restrict__ h0, __half* __restrict__ h1)
{
    size_t i = ((size_t)blockIdx.x * 256 + threadIdx.x) * 4;
    if (i >= (size_t)M_ * D_) return;
    const float* x = blockIdx.y == 0 ? x0 : x1;
    __half* h = blockIdx.y == 0 ? h0 : h1;
    float4 v = *(const float4*)(x + i);
    __half2 a = __float22half2_rn(make_float2(v.x, v.y));
    __half2 b = __float22half2_rn(make_float2(v.z, v.w));
    uint32_t u[2] = {*(const uint32_t*)&a, *(const uint32_t*)&b};
    *(uint2*)(h + i) = *(const uint2*)u;
}

// ================= fp16 tensor-core GEMM =================
// Grid: blockIdx.x = M-tile (fastest -> co-resident CTAs share B), blockIdx.y = N-block.
// AH: A input fp16 row-major. OH: C output fp16.
enum { EPI_QK = 1, EPI_RELU = 3, EPI_BIAS_LN = 5, EPI_LN_RES = 6, EPI_KV = 7 };

template<int EPI, int KCH, bool AH, bool OH>
__global__ __launch_bounds__(256, 2)
void gemm_f16(const void* __restrict__ Ain, const __half* __restrict__ Bp,
              const float* __restrict__ bias, const float* __restrict__ mask,
              const float* __restrict__ lng, const float* __restrict__ lnb,
              void* __restrict__ Cout, int N,
              __half* __restrict__ xh, float* __restrict__ kvz, float* __restrict__ ksz)
{
    constexpr int K = KCH * 32;
    extern __shared__ float sm[];
    uint32_t* As = (uint32_t*)sm;                  // KCH slots x 1024 u32 (A frags)
    float* sbias = sm + KCH * 1024;
    float* sg    = sbias + 256;
    float* sb    = sg + 256;
    float* red1 = sm;                 // epilogue scratch (reuses A region)
    float* red2 = sm + 512;
    float* smu  = sm + 1024;
    float* srs  = sm + 1088;

    const int tid = threadIdx.x;
    const int wn = tid >> 5, lane = tid & 31;
    const int gid = lane >> 2, qid = lane & 3;
    const int mtile = blockIdx.x, nblk = blockIdx.y;
    const int rowBase = mtile * BM;
    const int colBase = nblk * 256;

    if (EPI == EPI_QK) {
        // fold KV/Ks zeroing into this kernel (precedes kv_kernel on-stream)
        if (mtile < 256) kvz[mtile * 256 + tid] = 0.f;
        else if (mtile < 264) ksz[(mtile - 256) * 256 + tid] = 0.f;
    }

    if (EPI == EPI_QK || EPI == EPI_BIAS_LN)
        sbias[tid] = bias[colBase + tid];
    if (EPI == EPI_KV)
        sbias[tid] = (nblk == 0 ? bias : lng)[tid];   // bk | bv
    if (EPI == EPI_BIAS_LN || EPI == EPI_LN_RES) { sg[tid] = lng[tid]; sb[tid] = lnb[tid]; }

    // ---- stage FULL A tile (64 x K) as fp16 fragments, once ----
    {
        const int arow = tid >> 2, aq = tid & 3;
        const int a_base = ((aq >> 1) * 4 + (arow >> 4)) * 128 + (arow & 7) * 16
                         + (aq & 1) * 2 + ((arow >> 3) & 1);
        if (AH) {
            const __half* Aptr = (const __half*)Ain + (size_t)(rowBase + arow) * K + aq * 8;
            #pragma unroll
            for (int c = 0; c < KCH; c++) {
                uint4 v = *(const uint4*)(Aptr + (size_t)c * 32);
                uint32_t* d = As + c * 1024 + a_base;
                d[0] = v.x; d[4] = v.y; d[8] = v.z; d[12] = v.w;
            }
        } else {
            const float* Aptr = (const float*)Ain + (size_t)(rowBase + arow) * K + aq * 8;
            #pragma unroll
            for (int c = 0; c < KCH; c++) {
                float4 v0 = *(const float4*)(Aptr + (size_t)c * 32);
                float4 v1 = *(const float4*)(Aptr + (size_t)c * 32 + 4);
                uint32_t* d = As + c * 1024 + a_base;
                const float* f0 = (const float*)&v0;
                const float* f1 = (const float*)&v1;
                #pragma unroll
                for (int q = 0; q < 2; q++) {
                    __half2 h = __float22half2_rn(make_float2(f0[2*q], f0[2*q+1]));
                    d[q * 4] = *(const uint32_t*)&h;
                }
                #pragma unroll
                for (int q = 0; q < 2; q++) {
                    __half2 h = __float22half2_rn(make_float2(f1[2*q], f1[2*q+1]));
                    d[(q + 2) * 4] = *(const uint32_t*)&h;
                }
            }
        }
    }
    __syncthreads();

    // ---- mainloop: barrier-free, A+B double-buffered one kk ahead ----
    float acc[4][4][4];
    #pragma unroll
    for (int mi = 0; mi < 4; mi++)
        #pragma unroll
        for (int j = 0; j < 4; j++)
            #pragma unroll
            for (int q = 0; q < 4; q++) acc[mi][j][q] = 0.f;

    const uint32_t* Asl = As + lane * 4;
    const __half* Bch = Bp + (size_t)nblk * KCH * 8192
                        + (size_t)wn * 512 + lane * 8;

    uint4 af[2][4], bf[2][2];
    #pragma unroll
    for (int mi = 0; mi < 4; mi++)
        af[0][mi] = *(const uint4*)(Asl + mi * 128);
    bf[0][0] = *(const uint4*)(Bch);
    bf[0][1] = *(const uint4*)(Bch + 256);

    #pragma unroll
    for (int kk = 0; kk < 2 * KCH; kk++) {
        const int cur = kk & 1, nxt = cur ^ 1;
        if (kk + 1 < 2 * KCH) {
            const uint32_t* asn = Asl + (kk + 1) * 512;
            #pragma unroll
            for (int mi = 0; mi < 4; mi++)
                af[nxt][mi] = *(const uint4*)(asn + mi * 128);
            const __half* s = Bch + (size_t)(kk + 1) * 4096;
            bf[nxt][0] = *(const uint4*)(s);
            bf[nxt][1] = *(const uint4*)(s + 256);
        }
        #pragma unroll
        for (int mi = 0; mi < 4; mi++) {
            const uint32_t a4[4] = {af[cur][mi].x, af[cur][mi].y,
                                    af[cur][mi].z, af[cur][mi].w};
            mma_f16(acc[mi][0], a4, bf[cur][0].x, bf[cur][0].y);
            mma_f16(acc[mi][1], a4, bf[cur][0].z, bf[cur][0].w);
            mma_f16(acc[mi][2], a4, bf[cur][1].x, bf[cur][1].y);
            mma_f16(acc[mi][3], a4, bf[cur][1].z, bf[cur][1].w);
        }
    }
    __syncthreads();   // A region free for epilogue scratch

    // ================= epilogue =================
    // element (mi,j,q): row = rowBase + mi*16 + (q>>1)*8 + gid
    //                   col = colBase + wn*32 + j*8 + qid*2 + (q&1)
    if (EPI == EPI_QK || EPI == EPI_BIAS_LN || EPI == EPI_KV) {
        #pragma unroll
        for (int mi = 0; mi < 4; mi++)
            #pragma unroll
            for (int j = 0; j < 4; j++) {
                const int c = wn * 32 + j * 8 + qid * 2;
                acc[mi][j][0] += sbias[c];   acc[mi][j][1] += sbias[c + 1];
                acc[mi][j][2] += sbias[c];   acc[mi][j][3] += sbias[c + 1];
            }
    }
    if (EPI == EPI_QK || EPI == EPI_KV) {
        const bool do_elu = (EPI == EPI_QK) || (EPI == EPI_KV && nblk == 0);
        float mk[4][2];
        #pragma unroll
        for (int mi = 0; mi < 4; mi++)
            #pragma unroll
            for (int r = 0; r < 2; r++)
                mk[mi][r] = mask[rowBase + mi * 16 + r * 8 + gid];
        #pragma unroll
        for (int mi = 0; mi < 4; mi++)
            #pragma unroll
            for (int j = 0; j < 4; j++)
                #pragma unroll
                for (int q = 0; q < 4; q++) {
                    float t = acc[mi][j][q];
                    if (do_elu) t = (t > 0.f) ? (t + 1.f) : expf(t);
                    acc[mi][j][q] = t * mk[mi][q >> 1];
                }
    }
    if (EPI == EPI_RELU) {
        #pragma unroll
        for (int mi = 0; mi < 4; mi++)
            #pragma unroll
            for (int j = 0; j < 4; j++)
                #pragma unroll
                for (int q = 0; q < 4; q++)
                    acc[mi][j][q] = acc[mi][j][q] > 0.f ? acc[mi][j][q] : 0.f;
    }

    if (EPI == EPI_BIAS_LN || EPI == EPI_LN_RES) {
        float s1[4][2], s2[4][2];
        #pragma unroll
        for (int mi = 0; mi < 4; mi++)
            #pragma unroll
            for (int r = 0; r < 2; r++) { s1[mi][r] = 0.f; s2[mi][r] = 0.f; }
        #pragma unroll
        for (int mi = 0; mi < 4; mi++)
            #pragma unroll
            for (int j = 0; j < 4; j++)
                #pragma unroll
                for (int q = 0; q < 4; q++) {
                    float v = acc[mi][j][q];
                    s1[mi][q >> 1] += v;
                    s2[mi][q >> 1] = fmaf(v, v, s2[mi][q >> 1]);
                }
        #pragma unroll
        for (int o = 1; o <= 2; o <<= 1)
            #pragma unroll
            for (int mi = 0; mi < 4; mi++)
                #pragma unroll
                for (int r = 0; r < 2; r++) {
                    s1[mi][r] += __shfl_xor_sync(0xffffffffu, s1[mi][r], o);
                    s2[mi][r] += __shfl_xor_sync(0xffffffffu, s2[mi][r], o);
                }
        if (qid == 0) {
            #pragma unroll
            for (int mi = 0; mi < 4; mi++)
                #pragma unroll
                for (int r = 0; r < 2; r++) {
                    int rl = mi * 16 + r * 8 + gid;
                    red1[rl * 8 + wn] = s1[mi][r];
                    red2[rl * 8 + wn] = s2[mi][r];
                }
        }
        __syncthreads();
        if (tid < 64) {
            float a = 0.f, b2 = 0.f;
            #pragma unroll
            for (int w = 0; w < 8; w++) { a += red1[tid * 8 + w]; b2 += red2[tid * 8 + w]; }
            float mu = a * (1.f / 256.f);
            float var = b2 * (1.f / 256.f) - mu * mu;
            smu[tid] = mu;
            srs[tid] = rsqrtf(var + EPS_LN);
        }
        __syncthreads();
        #pragma unroll
        for (int mi = 0; mi < 4; mi++)
            #pragma unroll
            for (int j = 0; j < 4; j++)
                #pragma unroll
                for (int q = 0; q < 4; q++) {
                    int rl = mi * 16 + (q >> 1) * 8 + gid;
                    int c  = wn * 32 + j * 8 + qid * 2 + (q & 1);
                    acc[mi][j][q] = (acc[mi][j][q] - smu[rl]) * srs[rl] * sg[c] + sb[c];
                }
    }

    // store
    #pragma unroll
    for (int mi = 0; mi < 4; mi++) {
        #pragma unroll
        for (int j = 0; j < 4; j++) {
            const int c  = colBase + wn * 32 + j * 8 + qid * 2;
            const int r0 = rowBase + mi * 16 + gid;
            const int r1 = r0 + 8;
            if (OH) {
                __half* Ch = (__half*)Cout;
                __half2 h0 = __float22half2_rn(make_float2(acc[mi][j][0], acc[mi][j][1]));
                __half2 h1 = __float22half2_rn(make_float2(acc[mi][j][2], acc[mi][j][3]));
                *(uint32_t*)&Ch[(size_t)r0 * N + c] = *(const uint32_t*)&h0;
                *(uint32_t*)&Ch[(size_t)r1 * N + c] = *(const uint32_t*)&h1;
            } else {
                float* Cf = (float*)Cout;
                float2 v0 = make_float2(acc[mi][j][0], acc[mi][j][1]);
                float2 v1 = make_float2(acc[mi][j][2], acc[mi][j][3]);
                if (EPI == EPI_LN_RES) {
                    float2 x0 = *(const float2*)&Cf[(size_t)r0 * N + c];
                    float2 x1 = *(const float2*)&Cf[(size_t)r1 * N + c];
                    v0.x += x0.x; v0.y += x0.y;
                    v1.x += x1.x; v1.y += x1.y;
                }
                *(float2*)&Cf[(size_t)r0 * N + c] = v0;
                *(float2*)&Cf[(size_t)r1 * N + c] = v1;
                if (EPI == EPI_LN_RES) {
                    __half2 h0 = __float22half2_rn(v0);
                    __half2 h1 = __float22half2_rn(v1);
                    *(uint32_t*)&xh[(size_t)r0 * N + c] = *(const uint32_t*)&h0;
                    *(uint32_t*)&xh[(size_t)r1 * N + c] = *(const uint32_t*)&h1;
                }
            }
        }
    }
}

// ================= KV reduction (reads combined fp16 K|V buffer, stride 512) =====
__global__ __launch_bounds__(256)
void kv_kernel(const __half* __restrict__ KVc,
               float* __restrict__ KV, float* __restrict__ Ks, int rowsPerSplit)
{
    const int bh = blockIdx.x;
    const int b = bh >> 3, h = bh & 7;
    const int l0 = blockIdx.y * rowsPerSplit;
    const int tid = threadIdx.x;
    const int lr = tid >> 5;
    const int ld = tid & 31;

    __shared__ float Kt[8][32];
    __shared__ float Vt[8][32];

    float a0 = 0.f, a1 = 0.f, a2 = 0.f, a3 = 0.f, ks = 0.f;

    for (int c = 0; c < rowsPerSplit; c += 8) {
        int l = l0 + c + lr;
        size_t base = ((size_t)b * L_ + l) * (2 * D_) + h * DIM_ + ld;
        Kt[lr][ld] = __half2float(KVc[base]);
        Vt[lr][ld] = __half2float(KVc[base + D_]);
        __syncthreads();
        #pragma unroll
        for (int r = 0; r < 8; r++) {
            float kv = Kt[r][ld];
            a0 = fmaf(kv, Vt[r][lr +  0], a0);
            a1 = fmaf(kv, Vt[r][lr +  8], a1);
            a2 = fmaf(kv, Vt[r][lr + 16], a2);
            a3 = fmaf(kv, Vt[r][lr + 24], a3);
        }
        if (tid < 32) {
            #pragma unroll
            for (int r = 0; r < 8; r++) ks += Kt[r][tid];
        }
        __syncthreads();
    }

    float* kvb = KV + (size_t)bh * DIM_ * DIM_;
    atomicAdd(&kvb[(lr +  0) * DIM_ + ld], a0);
    atomicAdd(&kvb[(lr +  8) * DIM_ + ld], a1);
    atomicAdd(&kvb[(lr + 16) * DIM_ + ld], a2);
    atomicAdd(&kvb[(lr + 24) * DIM_ + ld], a3);
    if (tid < 32) atomicAdd(&Ks[bh * DIM_ + tid], ks);
}

// ================= attention apply (fp16 Q in, fp16 A out) =================
__global__ __launch_bounds__(256)
void attn_apply(const __half* __restrict__ Q, const float* __restrict__ KV,
                const float* __restrict__ Ks, __half* __restrict__ Out)
{
    __shared__ float sKV[H_ * DIM_ * DIM_];
    __shared__ float sKs[H_ * DIM_];
    const int b = blockIdx.y;
    const int tid = threadIdx.x;

    for (int i = tid; i < H_ * DIM_ * DIM_; i += 256)
        sKV[i] = KV[(size_t)b * H_ * DIM_ * DIM_ + i];
    if (tid < H_ * DIM_) sKs[tid] = Ks[b * H_ * DIM_ + tid];
    __syncthreads();

    const int token = blockIdx.x * 256 + tid;
    if (token >= L_) return;
    const size_t row = (size_t)b * L_ + token;
    const __half* q = Q + row * D_;
    __half* o = Out + row * D_;

    for (int h = 0; h < H_; h++) {
        float qr[DIM_];
        uint4 uu[4];
        #pragma unroll
        for (int t = 0; t < 4; t++)
            uu[t] = *(const uint4*)(q + h * DIM_ + t * 8);
        const __half2* hh = (const __half2*)uu;
        #pragma unroll
        for (int t = 0; t < 16; t++) {
            float2 f = __half22float2(hh[t]);
            qr[2 * t] = f.x; qr[2 * t + 1] = f.y;
        }
        float s = 0.f;
        #pragma unroll
        for (int d = 0; d < DIM_; d++) s = fmaf(qr[d], sKs[h * DIM_ + d], s);
        float z = 1.f / (s + EPS_ATTN);
        const float* kvh = &sKV[h * DIM_ * DIM_];
        #pragma unroll 4
        for (int m = 0; m < DIM_; m += 2) {
            float acc0 = 0.f, acc1 = 0.f;
            #pragma unroll
            for (int d = 0; d < DIM_; d++) {
                acc0 = fmaf(kvh[m * DIM_ + d], qr[d], acc0);
                acc1 = fmaf(kvh[(m + 1) * DIM_ + d], qr[d], acc1);
            }
            __half2 hv = __float22half2_rn(make_float2(acc0 * z, acc1 * z));
            *(uint32_t*)&o[h * DIM_ + m] = *(const uint32_t*)&hv;
        }
    }
}

// ================= host orchestration =================
namespace {

struct Ptrs {
    float *x0, *x1, *KV, *Ks;
    __half *xh0, *xh1, *Q, *KVc, *A, *Msg, *Hid, *WTh, *w1Th, *w2Th;
};

void run_layer(float* x, __half* xh, const __half* srch,
               const float* xm, const float* sm,
               const __half* WqP, const float* bq, const __half* WkvP,
               const float* bk, const float* bv,
               const __half* WmP, const float* bm,
               const __half* w1P, const __half* w2P, const float* g1, const float* b1,
               const float* g2, const float* b2, const Ptrs& p)
{
    dim3 g1d(M_ / BM, 1);   // (600, 1) — M fastest
    dim3 g2d(M_ / BM, 2);   // (600, 2)

    gemm_f16<EPI_QK, 8, true, true><<<g1d, 256, SMEM_K8>>>(
        xh, WqP, bq, xm, nullptr, nullptr, p.Q, 256, nullptr, p.KV, p.Ks);
    gemm_f16<EPI_KV, 8, true, true><<<g2d, 256, SMEM_K8>>>(
        srch, WkvP, bk, sm, bv, nullptr, p.KVc, 512, nullptr, nullptr, nullptr);
    kv_kernel<<<dim3(B_ * H_, 20), 256>>>(p.KVc, p.KV, p.Ks, L_ / 20);
    attn_apply<<<dim3((L_ + 255) / 256, B_), 256>>>(p.Q, p.KV, p.Ks, p.A);

    gemm_f16<EPI_BIAS_LN, 8, true, true><<<g1d, 256, SMEM_K8>>>(
        p.A, WmP, bm, nullptr, g1, b1, p.Msg, 256, nullptr, nullptr, nullptr);
    gemm_f16<EPI_RELU, 8, true, true><<<g2d, 256, SMEM_K8>>>(
        p.Msg, w1P, nullptr, nullptr, nullptr, nullptr, p.Hid, 512, nullptr, nullptr, nullptr);
    gemm_f16<EPI_LN_RES, 16, true, false><<<g1d, 256, SMEM_K16>>>(
        p.Hid, w2P, nullptr, nullptr, g2, b2, x, 256, xh, nullptr, nullptr);
}

} // namespace

extern "C" void kernel_launch(void* const* d_in, const int* in_sizes, int n_in,
                              void* d_out, int out_size)
{
    const float* desc0 = (const float*)d_in[0];
    const float* desc1 = (const float*)d_in[1];
    const float* mask0 = (const float*)d_in[2];
    const float* mask1 = (const float*)d_in[3];
    const float* Wq = (const float*)d_in[4];
    const float* bq = (const float*)d_in[5];
    const float* Wk = (const float*)d_in[6];
    const float* bk = (const float*)d_in[7];
    const float* Wv = (const float*)d_in[8];
    const float* bv = (const float*)d_in[9];
    const float* Wm = (const float*)d_in[10];
    const float* bm = (const float*)d_in[11];
    const float* w1 = (const float*)d_in[12];
    const float* w2 = (const float*)d_in[13];
    const float* g1 = (const float*)d_in[14];
    const float* b1 = (const float*)d_in[15];
    const float* g2 = (const float*)d_in[16];
    const float* b2 = (const float*)d_in[17];

    Ptrs p;
    cudaGetSymbolAddress((void**)&p.x0,  g_x0);
    cudaGetSymbolAddress((void**)&p.x1,  g_x1);
    cudaGetSymbolAddress((void**)&p.xh0, g_xh0);
    cudaGetSymbolAddress((void**)&p.xh1, g_xh1);
    cudaGetSymbolAddress((void**)&p.Q,   g_Q);
    cudaGetSymbolAddress((void**)&p.KVc, g_KVc);
    cudaGetSymbolAddress((void**)&p.A,   g_A);
    cudaGetSymbolAddress((void**)&p.Msg, g_Msg);
    cudaGetSymbolAddress((void**)&p.Hid, g_Hid);
    cudaGetSymbolAddress((void**)&p.KV,  g_KV);
    cudaGetSymbolAddress((void**)&p.Ks,  g_Ks);
    cudaGetSymbolAddress((void**)&p.WTh,  g_WTh);
    cudaGetSymbolAddress((void**)&p.w1Th, g_w1Th);
    cudaGetSymbolAddress((void**)&p.w2Th, g_w2Th);

    cudaFuncSetAttribute((const void*)gemm_f16<EPI_QK, 8, true, true>,       cudaFuncAttributeMaxDynamicSharedMemorySize, SMEM_K8);
    cudaFuncSetAttribute((const void*)gemm_f16<EPI_KV, 8, true, true>,       cudaFuncAttributeMaxDynamicSharedMemorySize, SMEM_K8);
    cudaFuncSetAttribute((const void*)gemm_f16<EPI_BIAS_LN, 8, true, true>,  cudaFuncAttributeMaxDynamicSharedMemorySize, SMEM_K8);
    cudaFuncSetAttribute((const void*)gemm_f16<EPI_RELU, 8, true, true>,     cudaFuncAttributeMaxDynamicSharedMemorySize, SMEM_K8);
    cudaFuncSetAttribute((const void*)gemm_f16<EPI_LN_RES, 16, true, false>, cudaFuncAttributeMaxDynamicSharedMemorySize, SMEM_K16);

    // ---- one-time prep ----
    pack_all<<<(4 * 65536 + 2 * 8 * 131072) / 256, 256>>>(Wq, Wk, Wv, Wm, w1, w2,
                                                          p.WTh, p.w1Th, p.w2Th);

    const size_t tensorBytes = (size_t)M_ * D_ * sizeof(float);
    cudaMemcpyAsync(p.x0, desc0, tensorBytes, cudaMemcpyDeviceToDevice);
    cudaMemcpyAsync(p.x1, desc1, tensorBytes, cudaMemcpyDeviceToDevice);
    x_to_h<<<dim3((M_ * D_ / 4 + 255) / 256, 2), 256>>>(p.x0, p.x1, p.xh0, p.xh1);

    const int w1sz = D_ * 2 * D_;
    const int w2sz = 2 * D_ * D_;

    for (int li = 0; li < 8; li++) {
        const __half* lw1 = p.w1Th + (size_t)li * w1sz;
        const __half* lw2 = p.w2Th + (size_t)li * w2sz;
        const float* lg1 = g1 + li * D_;
        const float* lb1 = b1 + li * D_;
        const float* lg2 = g2 + li * D_;
        const float* lb2 = b2 + li * D_;
        const __half* WqP  = p.WTh + 0 * D_ * D_;
        const __half* WkvP = p.WTh + 1 * D_ * D_;   // Wk | Wv contiguous packed blocks
        const __half* WmP  = p.WTh + 3 * D_ * D_;
        if ((li & 1) == 0) {
            run_layer(p.x0, p.xh0, p.xh0, mask0, mask0, WqP, bq, WkvP, bk, bv, WmP, bm,
                      lw1, lw2, lg1, lb1, lg2, lb2, p);
            run_layer(p.x1, p.xh1, p.xh1, mask1, mask1, WqP, bq, WkvP, bk, bv, WmP, bm,
                      lw1, lw2, lg1, lb1, lg2, lb2, p);
        } else {
            run_layer(p.x0, p.xh0, p.xh1, mask0, mask1, WqP, bq, WkvP, bk, bv, WmP, bm,
                      lw1, lw2, lg1, lb1, lg2, lb2, p);
            run_layer(p.x1, p.xh1, p.xh0, mask1, mask0, WqP, bq, WkvP, bk, bv, WmP, bm,
                      lw1, lw2, lg1, lb1, lg2, lb2, p);
        }
    }

    cudaMemcpyAsync((float*)d_out,                   p.x0, tensorBytes, cudaMemcpyDeviceToDevice);
    cudaMemcpyAsync((float*)d_out + (size_t)M_ * D_, p.x1, tensorBytes, cudaMemcpyDeviceToDevice);
}

// round 13
// speedup vs baseline: 1.2734x; 1.0501x over previous
#include <cuda_runtime.h>
#include <cuda_fp16.h>
#include <math.h>
#include <stdint.h>

// ================= problem constants =================
namespace {
constexpr int B_ = 8, L_ = 4800, D_ = 256, H_ = 8, DIM_ = 32;
constexpr int M_ = B_ * L_;            // 38400 rows
constexpr float EPS_ATTN = 1e-6f, EPS_LN = 1e-5f;
constexpr int KV_ELEMS = B_ * H_ * DIM_ * DIM_;   // 65536
constexpr int KS_ELEMS = B_ * H_ * DIM_;          // 2048
constexpr int MD = M_ * D_;

constexpr int BM = 64;                 // CTA rows; 8 warps; warp tile 64x32
constexpr int SMEM_K8  = (8  * 1024 + 768) * 4;   // 35840 B
constexpr int SMEM_K16 = (16 * 1024 + 768) * 4;   // 68608 B
}

// ================= scratch (static device globals) =================
__device__ float  g_x0[MD];
__device__ float  g_x1[MD];
__device__ __half g_xh0[MD];                  // fp16 shadow of x0
__device__ __half g_xh1[MD];
__device__ __half g_Q  [2 * MD];              // per-desc
__device__ __half g_KVc[2 * 2 * MD];          // per-desc K|V combined
__device__ __half g_A  [2 * MD];
__device__ __half g_Msg[2 * MD];
__device__ __half g_Hid[2 * 2 * MD];
__device__ float  g_KV[2 * KV_ELEMS];
__device__ float  g_Ks[2 * KS_ELEMS];
__device__ __half g_WTh [4 * D_ * D_];        // frag-major fp16: Wq,Wk,Wv,Wm
__device__ __half g_w1Th[8 * 2 * D_ * D_];
__device__ __half g_w2Th[8 * D_ * 2 * D_];

// ================= mma helper =================
__device__ __forceinline__ void mma_f16(float d[4], const uint32_t a[4],
                                        uint32_t b0, uint32_t b1) {
    asm volatile(
        "mma.sync.aligned.m16n8k16.row.col.f32.f16.f16.f32 "
        "{%0,%1,%2,%3}, {%4,%5,%6,%7}, {%8,%9}, {%0,%1,%2,%3};\n"
        : "+f"(d[0]), "+f"(d[1]), "+f"(d[2]), "+f"(d[3])
        : "r"(a[0]), "r"(a[1]), "r"(a[2]), "r"(a[3]), "r"(b0), "r"(b1));
}

// ================= weight pack: [K,N] f32 -> frag-major fp16 =================
__device__ __forceinline__ void pack_one(const float* __restrict__ in,
                                         __half* __restrict__ out,
                                         int t, int K, int N)
{
    int k = t / N, n = t % N;
    int nblk = n >> 8, nloc = n & 255;
    int wn = nloc >> 5, j = (nloc >> 3) & 3, gid = nloc & 7;
    int p = j >> 1, jh = j & 1;
    int kch = k >> 5, kin = k & 31, kstep = kin >> 4, c16 = kin & 15;
    int qid = (c16 >> 1) & 3, kh = (c16 >> 3) & 1, h = c16 & 1;
    int lane = gid * 4 + qid;
    int NKCH = K >> 5;
    size_t idx = ((((((size_t)nblk * NKCH + kch) * 2 + kstep) * 8 + wn) * 2 + p) * 32
                  + lane) * 8 + jh * 4 + kh * 2 + h;
    out[idx] = __float2half_rn(in[t]);
}

__global__ void pack_all(const float* __restrict__ Wq, const float* __restrict__ Wk,
                         const float* __restrict__ Wv, const float* __restrict__ Wm,
                         const float* __restrict__ w1, const float* __restrict__ w2,
                         __half* __restrict__ WTh, __half* __restrict__ w1Th,
                         __half* __restrict__ w2Th)
{
    long idx = (long)blockIdx.x * 256 + threadIdx.x;
    const long S0 = 4L * 65536, S1 = 8L * 131072;
    if (idx < S0) {
        int which = (int)(idx >> 16), t = (int)(idx & 65535);
        const float* src = which == 0 ? Wq : which == 1 ? Wk : which == 2 ? Wv : Wm;
        pack_one(src, WTh + (long)which * 65536, t, 256, 256);
    } else if (idx < S0 + S1) {
        long i2 = idx - S0;
        int layer = (int)(i2 >> 17), t = (int)(i2 & 131071);
        pack_one(w1 + (long)layer * 131072, w1Th + (long)layer * 131072, t, 256, 512);
    } else {
        long i2 = idx - S0 - S1;
        int layer = (int)(i2 >> 17), t = (int)(i2 & 131071);
        pack_one(w2 + (long)layer * 131072, w2Th + (long)layer * 131072, t, 512, 256);
    }
}

// ================= x -> fp16 shadow (initial) =================
__global__ void x_to_h(const float* __restrict__ x0, const float* __restrict__ x1,
                       __half* __restrict__ h0, __half* __restrict__ h1)
{
    size_t i = ((size_t)blockIdx.x * 256 + threadIdx.x) * 4;
    if (i >= (size_t)MD) return;
    const float* x = blockIdx.y == 0 ? x0 : x1;
    __half* h = blockIdx.y == 0 ? h0 : h1;
    float4 v = *(const float4*)(x + i);
    __half2 a = __float22half2_rn(make_float2(v.x, v.y));
    __half2 b = __float22half2_rn(make_float2(v.z, v.w));
    uint32_t u[2] = {*(const uint32_t*)&a, *(const uint32_t*)&b};
    *(uint2*)(h + i) = *(const uint2*)u;
}

// ================= shared GEMM core (staging + barrier-free mainloop) =========
// A: fp16 row-major, K = KCH*32. Bblk: frag-major weight block base.
template<int KCH>
__device__ __forceinline__ void gemm_main(const __half* __restrict__ A, int rowBase,
                                          const __half* __restrict__ Bblk,
                                          uint32_t* __restrict__ As,
                                          int tid, int wn, int lane,
                                          float acc[4][4][4])
{
    constexpr int K = KCH * 32;
    {
        const int arow = tid >> 2, aq = tid & 3;
        const int a_base = ((aq >> 1) * 4 + (arow >> 4)) * 128 + (arow & 7) * 16
                         + (aq & 1) * 2 + ((arow >> 3) & 1);
        const __half* Aptr = A + (size_t)(rowBase + arow) * K + aq * 8;
        #pragma unroll
        for (int c = 0; c < KCH; c++) {
            uint4 v = *(const uint4*)(Aptr + (size_t)c * 32);
            uint32_t* d = As + c * 1024 + a_base;
            d[0] = v.x; d[4] = v.y; d[8] = v.z; d[12] = v.w;
        }
    }
    __syncthreads();

    #pragma unroll
    for (int mi = 0; mi < 4; mi++)
        #pragma unroll
        for (int j = 0; j < 4; j++)
            #pragma unroll
            for (int q = 0; q < 4; q++) acc[mi][j][q] = 0.f;

    const uint32_t* Asl = As + lane * 4;
    const __half* Bch = Bblk + (size_t)wn * 512 + lane * 8;

    uint4 af[2][4], bf[2][2];
    #pragma unroll
    for (int mi = 0; mi < 4; mi++)
        af[0][mi] = *(const uint4*)(Asl + mi * 128);
    bf[0][0] = *(const uint4*)(Bch);
    bf[0][1] = *(const uint4*)(Bch + 256);

    #pragma unroll
    for (int kk = 0; kk < 2 * KCH; kk++) {
        const int cur = kk & 1, nxt = cur ^ 1;
        if (kk + 1 < 2 * KCH) {
            const uint32_t* asn = Asl + (kk + 1) * 512;
            #pragma unroll
            for (int mi = 0; mi < 4; mi++)
                af[nxt][mi] = *(const uint4*)(asn + mi * 128);
            const __half* s = Bch + (size_t)(kk + 1) * 4096;
            bf[nxt][0] = *(const uint4*)(s);
            bf[nxt][1] = *(const uint4*)(s + 256);
        }
        #pragma unroll
        for (int mi = 0; mi < 4; mi++) {
            const uint32_t a4[4] = {af[cur][mi].x, af[cur][mi].y,
                                    af[cur][mi].z, af[cur][mi].w};
            mma_f16(acc[mi][0], a4, bf[cur][0].x, bf[cur][0].y);
            mma_f16(acc[mi][1], a4, bf[cur][0].z, bf[cur][0].w);
            mma_f16(acc[mi][2], a4, bf[cur][1].x, bf[cur][1].y);
            mma_f16(acc[mi][3], a4, bf[cur][1].z, bf[cur][1].w);
        }
    }
    __syncthreads();   // As reusable
}

// ================= fused Q|K|V GEMM =================
// grid: (600, 3*ndesc). y -> d = y/3, part = y%3.
// part 0: Q[d] = elu(xq@Wq+bq)+1 masked (N=256)
// part 1: KVc[d][:,0:256]   = elu(xs@Wk+bk)+1 masked
// part 2: KVc[d][:,256:512] = (xs@Wv+bv) masked
__global__ __launch_bounds__(256, 2)
void gemm_qkv(const __half* __restrict__ xq0, const __half* __restrict__ xq1,
              const __half* __restrict__ xs0, const __half* __restrict__ xs1,
              const float* __restrict__ mq0, const float* __restrict__ mq1,
              const float* __restrict__ ms0, const float* __restrict__ ms1,
              const __half* __restrict__ Wqkv,
              const float* __restrict__ bq, const float* __restrict__ bk,
              const float* __restrict__ bv,
              __half* __restrict__ Q0, __half* __restrict__ Q1,
              __half* __restrict__ KVc0, __half* __restrict__ KVc1,
              float* __restrict__ kvz, float* __restrict__ ksz)
{
    extern __shared__ float sm[];
    uint32_t* As = (uint32_t*)sm;
    float* sbias = sm + 8 * 1024;

    const int tid = threadIdx.x;
    const int wn = tid >> 5, lane = tid & 31;
    const int gid = lane >> 2, qid = lane & 3;
    const int mtile = blockIdx.x;
    const int d = blockIdx.y / 3, part = blockIdx.y % 3;
    const int rowBase = mtile * BM;

    const __half* Ain = (part == 0) ? (d ? xq1 : xq0) : (d ? xs1 : xs0);
    const float* msk  = (part == 0) ? (d ? mq1 : mq0) : (d ? ms1 : ms0);
    const float* bs   = (part == 0) ? bq : (part == 1 ? bk : bv);
    __half* Cp;
    int Nst, colO;
    if (part == 0) { Cp = d ? Q1 : Q0;     Nst = 256; colO = 0; }
    else           { Cp = d ? KVc1 : KVc0; Nst = 512; colO = (part - 1) * 256; }
    const bool do_elu = (part < 2);

    if (part == 0) {   // fold per-desc KV/Ks zeroing
        if (mtile < 256) kvz[d * KV_ELEMS + mtile * 256 + tid] = 0.f;
        else if (mtile < 264) ksz[d * KS_ELEMS + (mtile - 256) * 256 + tid] = 0.f;
    }
    sbias[tid] = bs[tid];

    float acc[4][4][4];
    gemm_main<8>(Ain, rowBase, Wqkv + part * 65536, As, tid, wn, lane, acc);

    float mk[4][2];
    #pragma unroll
    for (int mi = 0; mi < 4; mi++)
        #pragma unroll
        for (int r = 0; r < 2; r++)
            mk[mi][r] = msk[rowBase + mi * 16 + r * 8 + gid];

    #pragma unroll
    for (int mi = 0; mi < 4; mi++) {
        #pragma unroll
        for (int j = 0; j < 4; j++) {
            const int c = wn * 32 + j * 8 + qid * 2;
            float b0 = sbias[c], b1 = sbias[c + 1];
            float v[4] = {acc[mi][j][0] + b0, acc[mi][j][1] + b1,
                          acc[mi][j][2] + b0, acc[mi][j][3] + b1};
            #pragma unroll
            for (int q = 0; q < 4; q++) {
                float t = v[q];
                if (do_elu) t = (t > 0.f) ? (t + 1.f) : expf(t);
                v[q] = t * mk[mi][q >> 1];
            }
            const int cc = colO + c;
            const int r0 = rowBase + mi * 16 + gid, r1 = r0 + 8;
            __half2 h0 = __float22half2_rn(make_float2(v[0], v[1]));
            __half2 h1 = __float22half2_rn(make_float2(v[2], v[3]));
            *(uint32_t*)&Cp[(size_t)r0 * Nst + cc] = *(const uint32_t*)&h0;
            *(uint32_t*)&Cp[(size_t)r1 * Nst + cc] = *(const uint32_t*)&h1;
        }
    }
}

// ================= std GEMM (BIAS_LN / RELU / LN_RES), desc-batched ============
enum { EPI_RELU = 3, EPI_BIAS_LN = 5, EPI_LN_RES = 6 };

template<int EPI, int KCH, int NB>
__global__ __launch_bounds__(256, 2)
void gemm_std(const __half* __restrict__ A0, const __half* __restrict__ A1,
              const __half* __restrict__ Bp,
              const float* __restrict__ bias,
              const float* __restrict__ lng, const float* __restrict__ lnb,
              void* __restrict__ C0, void* __restrict__ C1,
              __half* __restrict__ xh0, __half* __restrict__ xh1, int N)
{
    extern __shared__ float sm[];
    uint32_t* As = (uint32_t*)sm;
    float* sbias = sm + KCH * 1024;
    float* sg    = sbias + 256;
    float* sb    = sg + 256;
    float* red1 = sm;
    float* red2 = sm + 512;
    float* smu  = sm + 1024;
    float* srs  = sm + 1088;

    const int tid = threadIdx.x;
    const int wn = tid >> 5, lane = tid & 31;
    const int gid = lane >> 2, qid = lane & 3;
    const int mtile = blockIdx.x;
    const int d = blockIdx.y / NB, nblk = blockIdx.y % NB;
    const int rowBase = mtile * BM;
    const int colBase = nblk * 256;

    const __half* Ain = d ? A1 : A0;
    void* Cout = d ? C1 : C0;
    __half* xh = d ? xh1 : xh0;

    if (EPI == EPI_BIAS_LN) sbias[tid] = bias[colBase + tid];
    if (EPI == EPI_BIAS_LN || EPI == EPI_LN_RES) { sg[tid] = lng[tid]; sb[tid] = lnb[tid]; }

    float acc[4][4][4];
    gemm_main<KCH>(Ain, rowBase, Bp + (size_t)nblk * KCH * 8192, As, tid, wn, lane, acc);

    if (EPI == EPI_BIAS_LN) {
        #pragma unroll
        for (int mi = 0; mi < 4; mi++)
            #pragma unroll
            for (int j = 0; j < 4; j++) {
                const int c = wn * 32 + j * 8 + qid * 2;
                acc[mi][j][0] += sbias[c];   acc[mi][j][1] += sbias[c + 1];
                acc[mi][j][2] += sbias[c];   acc[mi][j][3] += sbias[c + 1];
            }
    }
    if (EPI == EPI_RELU) {
        #pragma unroll
        for (int mi = 0; mi < 4; mi++)
            #pragma unroll
            for (int j = 0; j < 4; j++)
                #pragma unroll
                for (int q = 0; q < 4; q++)
                    acc[mi][j][q] = acc[mi][j][q] > 0.f ? acc[mi][j][q] : 0.f;
    }

    if (EPI == EPI_BIAS_LN || EPI == EPI_LN_RES) {
        float s1[4][2], s2[4][2];
        #pragma unroll
        for (int mi = 0; mi < 4; mi++)
            #pragma unroll
            for (int r = 0; r < 2; r++) { s1[mi][r] = 0.f; s2[mi][r] = 0.f; }
        #pragma unroll
        for (int mi = 0; mi < 4; mi++)
            #pragma unroll
            for (int j = 0; j < 4; j++)
                #pragma unroll
                for (int q = 0; q < 4; q++) {
                    float v = acc[mi][j][q];
                    s1[mi][q >> 1] += v;
                    s2[mi][q >> 1] = fmaf(v, v, s2[mi][q >> 1]);
                }
        #pragma unroll
        for (int o = 1; o <= 2; o <<= 1)
            #pragma unroll
            for (int mi = 0; mi < 4; mi++)
                #pragma unroll
                for (int r = 0; r < 2; r++) {
                    s1[mi][r] += __shfl_xor_sync(0xffffffffu, s1[mi][r], o);
                    s2[mi][r] += __shfl_xor_sync(0xffffffffu, s2[mi][r], o);
                }
        if (qid == 0) {
            #pragma unroll
            for (int mi = 0; mi < 4; mi++)
                #pragma unroll
                for (int r = 0; r < 2; r++) {
                    int rl = mi * 16 + r * 8 + gid;
                    red1[rl * 8 + wn] = s1[mi][r];
                    red2[rl * 8 + wn] = s2[mi][r];
                }
        }
        __syncthreads();
        if (tid < 64) {
            float a = 0.f, b2 = 0.f;
            #pragma unroll
            for (int w = 0; w < 8; w++) { a += red1[tid * 8 + w]; b2 += red2[tid * 8 + w]; }
            float mu = a * (1.f / 256.f);
            float var = b2 * (1.f / 256.f) - mu * mu;
            smu[tid] = mu;
            srs[tid] = rsqrtf(var + EPS_LN);
        }
        __syncthreads();
        #pragma unroll
        for (int mi = 0; mi < 4; mi++)
            #pragma unroll
            for (int j = 0; j < 4; j++)
                #pragma unroll
                for (int q = 0; q < 4; q++) {
                    int rl = mi * 16 + (q >> 1) * 8 + gid;
                    int c  = wn * 32 + j * 8 + qid * 2 + (q & 1);
                    acc[mi][j][q] = (acc[mi][j][q] - smu[rl]) * srs[rl] * sg[c] + sb[c];
                }
    }

    #pragma unroll
    for (int mi = 0; mi < 4; mi++) {
        #pragma unroll
        for (int j = 0; j < 4; j++) {
            const int c  = colBase + wn * 32 + j * 8 + qid * 2;
            const int r0 = rowBase + mi * 16 + gid;
            const int r1 = r0 + 8;
            if (EPI != EPI_LN_RES) {
                __half* Ch = (__half*)Cout;
                __half2 h0 = __float22half2_rn(make_float2(acc[mi][j][0], acc[mi][j][1]));
                __half2 h1 = __float22half2_rn(make_float2(acc[mi][j][2], acc[mi][j][3]));
                *(uint32_t*)&Ch[(size_t)r0 * N + c] = *(const uint32_t*)&h0;
                *(uint32_t*)&Ch[(size_t)r1 * N + c] = *(const uint32_t*)&h1;
            } else {
                float* Cf = (float*)Cout;
                float2 v0 = make_float2(acc[mi][j][0], acc[mi][j][1]);
                float2 v1 = make_float2(acc[mi][j][2], acc[mi][j][3]);
                float2 x0 = *(const float2*)&Cf[(size_t)r0 * N + c];
                float2 x1 = *(const float2*)&Cf[(size_t)r1 * N + c];
                v0.x += x0.x; v0.y += x0.y;
                v1.x += x1.x; v1.y += x1.y;
                *(float2*)&Cf[(size_t)r0 * N + c] = v0;
                *(float2*)&Cf[(size_t)r1 * N + c] = v1;
                __half2 h0 = __float22half2_rn(v0);
                __half2 h1 = __float22half2_rn(v1);
                *(uint32_t*)&xh[(size_t)r0 * N + c] = *(const uint32_t*)&h0;
                *(uint32_t*)&xh[(size_t)r1 * N + c] = *(const uint32_t*)&h1;
            }
        }
    }
}

// ================= KV reduction (desc via blockIdx.z) =================
__global__ __launch_bounds__(256)
void kv_kernel(const __half* __restrict__ KVc0, const __half* __restrict__ KVc1,
               float* __restrict__ KVb, float* __restrict__ Ksb, int rowsPerSplit)
{
    const int z = blockIdx.z;
    const __half* KVc = z ? KVc1 : KVc0;
    float* KV = KVb + z * KV_ELEMS;
    float* Ks = Ksb + z * KS_ELEMS;

    const int bh = blockIdx.x;
    const int b = bh >> 3, h = bh & 7;
    const int l0 = blockIdx.y * rowsPerSplit;
    const int tid = threadIdx.x;
    const int lr = tid >> 5;
    const int ld = tid & 31;

    __shared__ float Kt[8][32];
    __shared__ float Vt[8][32];

    float a0 = 0.f, a1 = 0.f, a2 = 0.f, a3 = 0.f, ks = 0.f;

    for (int c = 0; c < rowsPerSplit; c += 8) {
        int l = l0 + c + lr;
        size_t base = ((size_t)b * L_ + l) * (2 * D_) + h * DIM_ + ld;
        Kt[lr][ld] = __half2float(KVc[base]);
        Vt[lr][ld] = __half2float(KVc[base + D_]);
        __syncthreads();
        #pragma unroll
        for (int r = 0; r < 8; r++) {
            float kv = Kt[r][ld];
            a0 = fmaf(kv, Vt[r][lr +  0], a0);
            a1 = fmaf(kv, Vt[r][lr +  8], a1);
            a2 = fmaf(kv, Vt[r][lr + 16], a2);
            a3 = fmaf(kv, Vt[r][lr + 24], a3);
        }
        if (tid < 32) {
            #pragma unroll
            for (int r = 0; r < 8; r++) ks += Kt[r][tid];
        }
        __syncthreads();
    }

    float* kvb = KV + (size_t)bh * DIM_ * DIM_;
    atomicAdd(&kvb[(lr +  0) * DIM_ + ld], a0);
    atomicAdd(&kvb[(lr +  8) * DIM_ + ld], a1);
    atomicAdd(&kvb[(lr + 16) * DIM_ + ld], a2);
    atomicAdd(&kvb[(lr + 24) * DIM_ + ld], a3);
    if (tid < 32) atomicAdd(&Ks[bh * DIM_ + tid], ks);
}

// ================= attention apply (desc via blockIdx.z) =================
__global__ __launch_bounds__(256)
void attn_apply(const __half* __restrict__ Q0, const __half* __restrict__ Q1,
                const float* __restrict__ KVb, const float* __restrict__ Ksb,
                __half* __restrict__ O0, __half* __restrict__ O1)
{
    __shared__ float sKV[H_ * DIM_ * DIM_];
    __shared__ float sKs[H_ * DIM_];
    const int z = blockIdx.z;
    const __half* Q = z ? Q1 : Q0;
    __half* Out = z ? O1 : O0;
    const float* KV = KVb + z * KV_ELEMS;
    const float* Ks = Ksb + z * KS_ELEMS;
    const int b = blockIdx.y;
    const int tid = threadIdx.x;

    for (int i = tid; i < H_ * DIM_ * DIM_; i += 256)
        sKV[i] = KV[(size_t)b * H_ * DIM_ * DIM_ + i];
    if (tid < H_ * DIM_) sKs[tid] = Ks[b * H_ * DIM_ + tid];
    __syncthreads();

    const int token = blockIdx.x * 256 + tid;
    if (token >= L_) return;
    const size_t row = (size_t)b * L_ + token;
    const __half* q = Q + row * D_;
    __half* o = Out + row * D_;

    for (int h = 0; h < H_; h++) {
        float qr[DIM_];
        uint4 uu[4];
        #pragma unroll
        for (int t = 0; t < 4; t++)
            uu[t] = *(const uint4*)(q + h * DIM_ + t * 8);
        const __half2* hh = (const __half2*)uu;
        #pragma unroll
        for (int t = 0; t < 16; t++) {
            float2 f = __half22float2(hh[t]);
            qr[2 * t] = f.x; qr[2 * t + 1] = f.y;
        }
        float s = 0.f;
        #pragma unroll
        for (int d = 0; d < DIM_; d++) s = fmaf(qr[d], sKs[h * DIM_ + d], s);
        float z2 = 1.f / (s + EPS_ATTN);
        const float* kvh = &sKV[h * DIM_ * DIM_];
        #pragma unroll 4
        for (int m = 0; m < DIM_; m += 2) {
            float acc0 = 0.f, acc1 = 0.f;
            #pragma unroll
            for (int d = 0; d < DIM_; d++) {
                acc0 = fmaf(kvh[m * DIM_ + d], qr[d], acc0);
                acc1 = fmaf(kvh[(m + 1) * DIM_ + d], qr[d], acc1);
            }
            __half2 hv = __float22half2_rn(make_float2(acc0 * z2, acc1 * z2));
            *(uint32_t*)&o[h * DIM_ + m] = *(const uint32_t*)&hv;
        }
    }
}

// ================= host orchestration =================
namespace {

struct Ptrs {
    float *x0, *x1, *KV, *Ks;
    __half *xh0, *xh1, *Q, *KVc, *A, *Msg, *Hid, *WTh, *w1Th, *w2Th;
};

// nd = 1 or 2 descriptor streams processed together.
void run_block(int nd,
               float* x[2], __half* xh[2], const __half* src[2],
               const float* mq[2], const float* ms[2],
               const float* bq, const float* bk, const float* bv,
               const float* bm, const __half* w1P, const __half* w2P,
               const float* g1, const float* b1, const float* g2, const float* b2,
               const Ptrs& p)
{
    const int G = M_ / BM;   // 600
    __half* Q0 = p.Q;            __half* Q1 = p.Q + MD;
    __half* KVc0 = p.KVc;        __half* KVc1 = p.KVc + 2 * MD;
    __half* A0 = p.A;            __half* A1 = p.A + MD;
    __half* Ms0 = p.Msg;         __half* Ms1 = p.Msg + MD;
    __half* H0 = p.Hid;          __half* H1 = p.Hid + 2 * MD;
    const __half* WmP = p.WTh + 3 * 65536;

    gemm_qkv<<<dim3(G, 3 * nd), 256, SMEM_K8>>>(
        xh[0], xh[1], src[0], src[1], mq[0], mq[1], ms[0], ms[1],
        p.WTh, bq, bk, bv, Q0, Q1, KVc0, KVc1, p.KV, p.Ks);
    kv_kernel<<<dim3(B_ * H_, 20, nd), 256>>>(KVc0, KVc1, p.KV, p.Ks, L_ / 20);
    attn_apply<<<dim3((L_ + 255) / 256, B_, nd), 256>>>(Q0, Q1, p.KV, p.Ks, A0, A1);

    gemm_std<EPI_BIAS_LN, 8, 1><<<dim3(G, nd), 256, SMEM_K8>>>(
        A0, A1, WmP, bm, g1, b1, Ms0, Ms1, nullptr, nullptr, 256);
    gemm_std<EPI_RELU, 8, 2><<<dim3(G, 2 * nd), 256, SMEM_K8>>>(
        Ms0, Ms1, w1P, nullptr, nullptr, nullptr, H0, H1, nullptr, nullptr, 512);
    gemm_std<EPI_LN_RES, 16, 1><<<dim3(G, nd), 256, SMEM_K16>>>(
        H0, H1, w2P, nullptr, g2, b2, x[0], x[1], xh[0], xh[1], 256);
}

} // namespace

extern "C" void kernel_launch(void* const* d_in, const int* in_sizes, int n_in,
                              void* d_out, int out_size)
{
    const float* desc0 = (const float*)d_in[0];
    const float* desc1 = (const float*)d_in[1];
    const float* mask0 = (const float*)d_in[2];
    const float* mask1 = (const float*)d_in[3];
    const float* Wq = (const float*)d_in[4];
    const float* bq = (const float*)d_in[5];
    const float* Wk = (const float*)d_in[6];
    const float* bk = (const float*)d_in[7];
    const float* Wv = (const float*)d_in[8];
    const float* bv = (const float*)d_in[9];
    const float* Wm = (const float*)d_in[10];
    const float* bm = (const float*)d_in[11];
    const float* w1 = (const float*)d_in[12];
    const float* w2 = (const float*)d_in[13];
    const float* g1 = (const float*)d_in[14];
    const float* b1 = (const float*)d_in[15];
    const float* g2 = (const float*)d_in[16];
    const float* b2 = (const float*)d_in[17];

    Ptrs p;
    cudaGetSymbolAddress((void**)&p.x0,  g_x0);
    cudaGetSymbolAddress((void**)&p.x1,  g_x1);
    cudaGetSymbolAddress((void**)&p.xh0, g_xh0);
    cudaGetSymbolAddress((void**)&p.xh1, g_xh1);
    cudaGetSymbolAddress((void**)&p.Q,   g_Q);
    cudaGetSymbolAddress((void**)&p.KVc, g_KVc);
    cudaGetSymbolAddress((void**)&p.A,   g_A);
    cudaGetSymbolAddress((void**)&p.Msg, g_Msg);
    cudaGetSymbolAddress((void**)&p.Hid, g_Hid);
    cudaGetSymbolAddress((void**)&p.KV,  g_KV);
    cudaGetSymbolAddress((void**)&p.Ks,  g_Ks);
    cudaGetSymbolAddress((void**)&p.WTh,  g_WTh);
    cudaGetSymbolAddress((void**)&p.w1Th, g_w1Th);
    cudaGetSymbolAddress((void**)&p.w2Th, g_w2Th);

    cudaFuncSetAttribute((const void*)gemm_qkv,                    cudaFuncAttributeMaxDynamicSharedMemorySize, SMEM_K8);
    cudaFuncSetAttribute((const void*)gemm_std<EPI_BIAS_LN, 8, 1>, cudaFuncAttributeMaxDynamicSharedMemorySize, SMEM_K8);
    cudaFuncSetAttribute((const void*)gemm_std<EPI_RELU, 8, 2>,    cudaFuncAttributeMaxDynamicSharedMemorySize, SMEM_K8);
    cudaFuncSetAttribute((const void*)gemm_std<EPI_LN_RES, 16, 1>, cudaFuncAttributeMaxDynamicSharedMemorySize, SMEM_K16);

    // ---- one-time prep ----
    pack_all<<<(4 * 65536 + 2 * 8 * 131072) / 256, 256>>>(Wq, Wk, Wv, Wm, w1, w2,
                                                          p.WTh, p.w1Th, p.w2Th);

    const size_t tensorBytes = (size_t)MD * sizeof(float);
    cudaMemcpyAsync(p.x0, desc0, tensorBytes, cudaMemcpyDeviceToDevice);
    cudaMemcpyAsync(p.x1, desc1, tensorBytes, cudaMemcpyDeviceToDevice);
    x_to_h<<<dim3((MD / 4 + 255) / 256, 2), 256>>>(p.x0, p.x1, p.xh0, p.xh1);

    const int w1sz = D_ * 2 * D_;
    const int w2sz = 2 * D_ * D_;

    for (int li = 0; li < 8; li++) {
        const __half* lw1 = p.w1Th + (size_t)li * w1sz;
        const __half* lw2 = p.w2Th + (size_t)li * w2sz;
        const float* lg1 = g1 + li * D_;
        const float* lb1 = b1 + li * D_;
        const float* lg2 = g2 + li * D_;
        const float* lb2 = b2 + li * D_;

        if ((li & 1) == 0) {
            // self: both streams independent -> one batched pass
            float* x[2] = {p.x0, p.x1};
            __half* xh[2] = {p.xh0, p.xh1};
            const __half* src[2] = {p.xh0, p.xh1};
            const float* mq[2] = {mask0, mask1};
            const float* ms[2] = {mask0, mask1};
            run_block(2, x, xh, src, mq, ms, bq, bk, bv, bm,
                      lw1, lw2, lg1, lb1, lg2, lb2, p);
        } else {
            // cross: desc0 first (uses old desc1), then desc1 (uses updated desc0)
            {
                float* x[2] = {p.x0, p.x0};
                __half* xh[2] = {p.xh0, p.xh0};
                const __half* src[2] = {p.xh1, p.xh1};
                const float* mq[2] = {mask0, mask0};
                const float* ms[2] = {mask1, mask1};
                run_block(1, x, xh, src, mq, ms, bq, bk, bv, bm,
                          lw1, lw2, lg1, lb1, lg2, lb2, p);
            }
            {
                float* x[2] = {p.x1, p.x1};
                __half* xh[2] = {p.xh1, p.xh1};
                const __half* src[2] = {p.xh0, p.xh0};
                const float* mq[2] = {mask1, mask1};
                const float* ms[2] = {mask0, mask0};
                run_block(1, x, xh, src, mq, ms, bq, bk, bv, bm,
                          lw1, lw2, lg1, lb1, lg2, lb2, p);
            }
        }
    }

    cudaMemcpyAsync((float*)d_out,                p.x0, tensorBytes, cudaMemcpyDeviceToDevice);
    cudaMemcpyAsync((float*)d_out + (size_t)MD,   p.x1, tensorBytes, cudaMemcpyDeviceToDevice);
}

// round 14
// speedup vs baseline: 1.3572x; 1.0658x over previous
#include <cuda_runtime.h>
#include <cuda_fp16.h>
#include <math.h>
#include <stdint.h>

// ================= problem constants =================
namespace {
constexpr int B_ = 8, L_ = 4800, D_ = 256, H_ = 8, DIM_ = 32;
constexpr int M_ = B_ * L_;            // 38400 rows
constexpr float EPS_ATTN = 1e-6f, EPS_LN = 1e-5f;
constexpr int KV_ELEMS = B_ * H_ * DIM_ * DIM_;   // 65536
constexpr int KS_ELEMS = B_ * H_ * DIM_;          // 2048
constexpr int MD = M_ * D_;

constexpr int BM = 64;                 // CTA rows; 8 warps; warp tile 64x32
constexpr int SMEM_K8  = (8  * 1024 + 768) * 4;   // 35840 B
constexpr int SMEM_K16 = (16 * 1024 + 768) * 4;   // 68608 B
constexpr int KV_SPLITS = 15;          // 320 rows per split, 5 chunks of 64
}

// ================= scratch (static device globals) =================
__device__ float  g_x0[MD];
__device__ float  g_x1[MD];
__device__ __half g_xh0[MD];                  // fp16 shadow of x0
__device__ __half g_xh1[MD];
__device__ __half g_Q  [2 * MD];              // per-desc
__device__ __half g_KVc[2 * 2 * MD];          // per-desc K|V combined
__device__ __half g_A  [2 * MD];
__device__ __half g_Msg[2 * MD];
__device__ __half g_Hid[2 * 2 * MD];
__device__ float  g_KV[2 * KV_ELEMS];
__device__ float  g_Ks[2 * KS_ELEMS];
__device__ __half g_WTh [4 * D_ * D_];        // frag-major fp16: Wq,Wk,Wv,Wm
__device__ __half g_w1Th[8 * 2 * D_ * D_];
__device__ __half g_w2Th[8 * D_ * 2 * D_];

// ================= mma helper =================
__device__ __forceinline__ void mma_f16(float d[4], const uint32_t a[4],
                                        uint32_t b0, uint32_t b1) {
    asm volatile(
        "mma.sync.aligned.m16n8k16.row.col.f32.f16.f16.f32 "
        "{%0,%1,%2,%3}, {%4,%5,%6,%7}, {%8,%9}, {%0,%1,%2,%3};\n"
        : "+f"(d[0]), "+f"(d[1]), "+f"(d[2]), "+f"(d[3])
        : "r"(a[0]), "r"(a[1]), "r"(a[2]), "r"(a[3]), "r"(b0), "r"(b1));
}

// ================= weight pack: [K,N] f32 -> frag-major fp16 =================
__device__ __forceinline__ void pack_one(const float* __restrict__ in,
                                         __half* __restrict__ out,
                                         int t, int K, int N)
{
    int k = t / N, n = t % N;
    int nblk = n >> 8, nloc = n & 255;
    int wn = nloc >> 5, j = (nloc >> 3) & 3, gid = nloc & 7;
    int p = j >> 1, jh = j & 1;
    int kch = k >> 5, kin = k & 31, kstep = kin >> 4, c16 = kin & 15;
    int qid = (c16 >> 1) & 3, kh = (c16 >> 3) & 1, h = c16 & 1;
    int lane = gid * 4 + qid;
    int NKCH = K >> 5;
    size_t idx = ((((((size_t)nblk * NKCH + kch) * 2 + kstep) * 8 + wn) * 2 + p) * 32
                  + lane) * 8 + jh * 4 + kh * 2 + h;
    out[idx] = __float2half_rn(in[t]);
}

__global__ void pack_all(const float* __restrict__ Wq, const float* __restrict__ Wk,
                         const float* __restrict__ Wv, const float* __restrict__ Wm,
                         const float* __restrict__ w1, const float* __restrict__ w2,
                         __half* __restrict__ WTh, __half* __restrict__ w1Th,
                         __half* __restrict__ w2Th)
{
    long idx = (long)blockIdx.x * 256 + threadIdx.x;
    const long S0 = 4L * 65536, S1 = 8L * 131072;
    if (idx < S0) {
        int which = (int)(idx >> 16), t = (int)(idx & 65535);
        const float* src = which == 0 ? Wq : which == 1 ? Wk : which == 2 ? Wv : Wm;
        pack_one(src, WTh + (long)which * 65536, t, 256, 256);
    } else if (idx < S0 + S1) {
        long i2 = idx - S0;
        int layer = (int)(i2 >> 17), t = (int)(i2 & 131071);
        pack_one(w1 + (long)layer * 131072, w1Th + (long)layer * 131072, t, 256, 512);
    } else {
        long i2 = idx - S0 - S1;
        int layer = (int)(i2 >> 17), t = (int)(i2 & 131071);
        pack_one(w2 + (long)layer * 131072, w2Th + (long)layer * 131072, t, 512, 256);
    }
}

// ================= x -> fp16 shadow (initial) =================
__global__ void x_to_h(const float* __restrict__ x0, const float* __restrict__ x1,
                       __half* __restrict__ h0, __half* __restrict__ h1)
{
    size_t i = ((size_t)blockIdx.x * 256 + threadIdx.x) * 4;
    if (i >= (size_t)MD) return;
    const float* x = blockIdx.y == 0 ? x0 : x1;
    __half* h = blockIdx.y == 0 ? h0 : h1;
    float4 v = *(const float4*)(x + i);
    __half2 a = __float22half2_rn(make_float2(v.x, v.y));
    __half2 b = __float22half2_rn(make_float2(v.z, v.w));
    uint32_t u[2] = {*(const uint32_t*)&a, *(const uint32_t*)&b};
    *(uint2*)(h + i) = *(const uint2*)u;
}

// ================= shared GEMM core =================
template<int KCH>
__device__ __forceinline__ void gemm_main(const __half* __restrict__ A, int rowBase,
                                          const __half* __restrict__ Bblk,
                                          uint32_t* __restrict__ As,
                                          int tid, int wn, int lane,
                                          float acc[4][4][4])
{
    constexpr int K = KCH * 32;
    {
        const int arow = tid >> 2, aq = tid & 3;
        const int a_base = ((aq >> 1) * 4 + (arow >> 4)) * 128 + (arow & 7) * 16
                         + (aq & 1) * 2 + ((arow >> 3) & 1);
        const __half* Aptr = A + (size_t)(rowBase + arow) * K + aq * 8;
        #pragma unroll
        for (int c = 0; c < KCH; c++) {
            uint4 v = *(const uint4*)(Aptr + (size_t)c * 32);
            uint32_t* d = As + c * 1024 + a_base;
            d[0] = v.x; d[4] = v.y; d[8] = v.z; d[12] = v.w;
        }
    }
    __syncthreads();

    #pragma unroll
    for (int mi = 0; mi < 4; mi++)
        #pragma unroll
        for (int j = 0; j < 4; j++)
            #pragma unroll
            for (int q = 0; q < 4; q++) acc[mi][j][q] = 0.f;

    const uint32_t* Asl = As + lane * 4;
    const __half* Bch = Bblk + (size_t)wn * 512 + lane * 8;

    uint4 af[2][4], bf[2][2];
    #pragma unroll
    for (int mi = 0; mi < 4; mi++)
        af[0][mi] = *(const uint4*)(Asl + mi * 128);
    bf[0][0] = *(const uint4*)(Bch);
    bf[0][1] = *(const uint4*)(Bch + 256);

    #pragma unroll
    for (int kk = 0; kk < 2 * KCH; kk++) {
        const int cur = kk & 1, nxt = cur ^ 1;
        if (kk + 1 < 2 * KCH) {
            const uint32_t* asn = Asl + (kk + 1) * 512;
            #pragma unroll
            for (int mi = 0; mi < 4; mi++)
                af[nxt][mi] = *(const uint4*)(asn + mi * 128);
            const __half* s = Bch + (size_t)(kk + 1) * 4096;
            bf[nxt][0] = *(const uint4*)(s);
            bf[nxt][1] = *(const uint4*)(s + 256);
        }
        #pragma unroll
        for (int mi = 0; mi < 4; mi++) {
            const uint32_t a4[4] = {af[cur][mi].x, af[cur][mi].y,
                                    af[cur][mi].z, af[cur][mi].w};
            mma_f16(acc[mi][0], a4, bf[cur][0].x, bf[cur][0].y);
            mma_f16(acc[mi][1], a4, bf[cur][0].z, bf[cur][0].w);
            mma_f16(acc[mi][2], a4, bf[cur][1].x, bf[cur][1].y);
            mma_f16(acc[mi][3], a4, bf[cur][1].z, bf[cur][1].w);
        }
    }
    __syncthreads();
}

// ================= fused Q|K|V GEMM =================
__global__ __launch_bounds__(256, 2)
void gemm_qkv(const __half* __restrict__ xq0, const __half* __restrict__ xq1,
              const __half* __restrict__ xs0, const __half* __restrict__ xs1,
              const float* __restrict__ mq0, const float* __restrict__ mq1,
              const float* __restrict__ ms0, const float* __restrict__ ms1,
              const __half* __restrict__ Wqkv,
              const float* __restrict__ bq, const float* __restrict__ bk,
              const float* __restrict__ bv,
              __half* __restrict__ Q0, __half* __restrict__ Q1,
              __half* __restrict__ KVc0, __half* __restrict__ KVc1,
              float* __restrict__ kvz, float* __restrict__ ksz)
{
    extern __shared__ float sm[];
    uint32_t* As = (uint32_t*)sm;
    float* sbias = sm + 8 * 1024;

    const int tid = threadIdx.x;
    const int wn = tid >> 5, lane = tid & 31;
    const int gid = lane >> 2, qid = lane & 3;
    const int mtile = blockIdx.x;
    const int d = blockIdx.y / 3, part = blockIdx.y % 3;
    const int rowBase = mtile * BM;

    const __half* Ain = (part == 0) ? (d ? xq1 : xq0) : (d ? xs1 : xs0);
    const float* msk  = (part == 0) ? (d ? mq1 : mq0) : (d ? ms1 : ms0);
    const float* bs   = (part == 0) ? bq : (part == 1 ? bk : bv);
    __half* Cp;
    int Nst, colO;
    if (part == 0) { Cp = d ? Q1 : Q0;     Nst = 256; colO = 0; }
    else           { Cp = d ? KVc1 : KVc0; Nst = 512; colO = (part - 1) * 256; }
    const bool do_elu = (part < 2);

    if (part == 0) {
        if (mtile < 256) kvz[d * KV_ELEMS + mtile * 256 + tid] = 0.f;
        else if (mtile < 264) ksz[d * KS_ELEMS + (mtile - 256) * 256 + tid] = 0.f;
    }
    sbias[tid] = bs[tid];

    float acc[4][4][4];
    gemm_main<8>(Ain, rowBase, Wqkv + part * 65536, As, tid, wn, lane, acc);

    float mk[4][2];
    #pragma unroll
    for (int mi = 0; mi < 4; mi++)
        #pragma unroll
        for (int r = 0; r < 2; r++)
            mk[mi][r] = msk[rowBase + mi * 16 + r * 8 + gid];

    #pragma unroll
    for (int mi = 0; mi < 4; mi++) {
        #pragma unroll
        for (int j = 0; j < 4; j++) {
            const int c = wn * 32 + j * 8 + qid * 2;
            float b0 = sbias[c], b1 = sbias[c + 1];
            float v[4] = {acc[mi][j][0] + b0, acc[mi][j][1] + b1,
                          acc[mi][j][2] + b0, acc[mi][j][3] + b1};
            #pragma unroll
            for (int q = 0; q < 4; q++) {
                float t = v[q];
                if (do_elu) t = (t > 0.f) ? (t + 1.f) : expf(t);
                v[q] = t * mk[mi][q >> 1];
            }
            const int cc = colO + c;
            const int r0 = rowBase + mi * 16 + gid, r1 = r0 + 8;
            __half2 h0 = __float22half2_rn(make_float2(v[0], v[1]));
            __half2 h1 = __float22half2_rn(make_float2(v[2], v[3]));
            *(uint32_t*)&Cp[(size_t)r0 * Nst + cc] = *(const uint32_t*)&h0;
            *(uint32_t*)&Cp[(size_t)r1 * Nst + cc] = *(const uint32_t*)&h1;
        }
    }
}

// ================= std GEMM (BIAS_LN / RELU / LN_RES), desc-batched ============
enum { EPI_RELU = 3, EPI_BIAS_LN = 5, EPI_LN_RES = 6 };

template<int EPI, int KCH, int NB>
__global__ __launch_bounds__(256, 2)
void gemm_std(const __half* __restrict__ A0, const __half* __restrict__ A1,
              const __half* __restrict__ Bp,
              const float* __restrict__ bias,
              const float* __restrict__ lng, const float* __restrict__ lnb,
              void* __restrict__ C0, void* __restrict__ C1,
              __half* __restrict__ xh0, __half* __restrict__ xh1, int N)
{
    extern __shared__ float sm[];
    uint32_t* As = (uint32_t*)sm;
    float* sbias = sm + KCH * 1024;
    float* sg    = sbias + 256;
    float* sb    = sg + 256;
    float* red1 = sm;
    float* red2 = sm + 512;
    float* smu  = sm + 1024;
    float* srs  = sm + 1088;

    const int tid = threadIdx.x;
    const int wn = tid >> 5, lane = tid & 31;
    const int gid = lane >> 2, qid = lane & 3;
    const int mtile = blockIdx.x;
    const int d = blockIdx.y / NB, nblk = blockIdx.y % NB;
    const int rowBase = mtile * BM;
    const int colBase = nblk * 256;

    const __half* Ain = d ? A1 : A0;
    void* Cout = d ? C1 : C0;
    __half* xh = d ? xh1 : xh0;

    if (EPI == EPI_BIAS_LN) sbias[tid] = bias[colBase + tid];
    if (EPI == EPI_BIAS_LN || EPI == EPI_LN_RES) { sg[tid] = lng[tid]; sb[tid] = lnb[tid]; }

    float acc[4][4][4];
    gemm_main<KCH>(Ain, rowBase, Bp + (size_t)nblk * KCH * 8192, As, tid, wn, lane, acc);

    if (EPI == EPI_BIAS_LN) {
        #pragma unroll
        for (int mi = 0; mi < 4; mi++)
            #pragma unroll
            for (int j = 0; j < 4; j++) {
                const int c = wn * 32 + j * 8 + qid * 2;
                acc[mi][j][0] += sbias[c];   acc[mi][j][1] += sbias[c + 1];
                acc[mi][j][2] += sbias[c];   acc[mi][j][3] += sbias[c + 1];
            }
    }
    if (EPI == EPI_RELU) {
        #pragma unroll
        for (int mi = 0; mi < 4; mi++)
            #pragma unroll
            for (int j = 0; j < 4; j++)
                #pragma unroll
                for (int q = 0; q < 4; q++)
                    acc[mi][j][q] = acc[mi][j][q] > 0.f ? acc[mi][j][q] : 0.f;
    }

    if (EPI == EPI_BIAS_LN || EPI == EPI_LN_RES) {
        float s1[4][2], s2[4][2];
        #pragma unroll
        for (int mi = 0; mi < 4; mi++)
            #pragma unroll
            for (int r = 0; r < 2; r++) { s1[mi][r] = 0.f; s2[mi][r] = 0.f; }
        #pragma unroll
        for (int mi = 0; mi < 4; mi++)
            #pragma unroll
            for (int j = 0; j < 4; j++)
                #pragma unroll
                for (int q = 0; q < 4; q++) {
                    float v = acc[mi][j][q];
                    s1[mi][q >> 1] += v;
                    s2[mi][q >> 1] = fmaf(v, v, s2[mi][q >> 1]);
                }
        #pragma unroll
        for (int o = 1; o <= 2; o <<= 1)
            #pragma unroll
            for (int mi = 0; mi < 4; mi++)
                #pragma unroll
                for (int r = 0; r < 2; r++) {
                    s1[mi][r] += __shfl_xor_sync(0xffffffffu, s1[mi][r], o);
                    s2[mi][r] += __shfl_xor_sync(0xffffffffu, s2[mi][r], o);
                }
        if (qid == 0) {
            #pragma unroll
            for (int mi = 0; mi < 4; mi++)
                #pragma unroll
                for (int r = 0; r < 2; r++) {
                    int rl = mi * 16 + r * 8 + gid;
                    red1[rl * 8 + wn] = s1[mi][r];
                    red2[rl * 8 + wn] = s2[mi][r];
                }
        }
        __syncthreads();
        if (tid < 64) {
            float a = 0.f, b2 = 0.f;
            #pragma unroll
            for (int w = 0; w < 8; w++) { a += red1[tid * 8 + w]; b2 += red2[tid * 8 + w]; }
            float mu = a * (1.f / 256.f);
            float var = b2 * (1.f / 256.f) - mu * mu;
            smu[tid] = mu;
            srs[tid] = rsqrtf(var + EPS_LN);
        }
        __syncthreads();
        #pragma unroll
        for (int mi = 0; mi < 4; mi++)
            #pragma unroll
            for (int j = 0; j < 4; j++)
                #pragma unroll
                for (int q = 0; q < 4; q++) {
                    int rl = mi * 16 + (q >> 1) * 8 + gid;
                    int c  = wn * 32 + j * 8 + qid * 2 + (q & 1);
                    acc[mi][j][q] = (acc[mi][j][q] - smu[rl]) * srs[rl] * sg[c] + sb[c];
                }
    }

    #pragma unroll
    for (int mi = 0; mi < 4; mi++) {
        #pragma unroll
        for (int j = 0; j < 4; j++) {
            const int c  = colBase + wn * 32 + j * 8 + qid * 2;
            const int r0 = rowBase + mi * 16 + gid;
            const int r1 = r0 + 8;
            if (EPI != EPI_LN_RES) {
                __half* Ch = (__half*)Cout;
                __half2 h0 = __float22half2_rn(make_float2(acc[mi][j][0], acc[mi][j][1]));
                __half2 h1 = __float22half2_rn(make_float2(acc[mi][j][2], acc[mi][j][3]));
                *(uint32_t*)&Ch[(size_t)r0 * N + c] = *(const uint32_t*)&h0;
                *(uint32_t*)&Ch[(size_t)r1 * N + c] = *(const uint32_t*)&h1;
            } else {
                float* Cf = (float*)Cout;
                float2 v0 = make_float2(acc[mi][j][0], acc[mi][j][1]);
                float2 v1 = make_float2(acc[mi][j][2], acc[mi][j][3]);
                float2 x0 = *(const float2*)&Cf[(size_t)r0 * N + c];
                float2 x1 = *(const float2*)&Cf[(size_t)r1 * N + c];
                v0.x += x0.x; v0.y += x0.y;
                v1.x += x1.x; v1.y += x1.y;
                *(float2*)&Cf[(size_t)r0 * N + c] = v0;
                *(float2*)&Cf[(size_t)r1 * N + c] = v1;
                __half2 h0 = __float22half2_rn(v0);
                __half2 h1 = __float22half2_rn(v1);
                *(uint32_t*)&xh[(size_t)r0 * N + c] = *(const uint32_t*)&h0;
                *(uint32_t*)&xh[(size_t)r1 * N + c] = *(const uint32_t*)&h1;
            }
        }
    }
}

// ================= KV reduction v2: 64-row chunks, transposed float smem ======
// grid: (64, KV_SPLITS, nd), block 256 (8 warps). warp lr owns m={lr,lr+8,lr+16,lr+24},
// lane owns d=ld. K read as conflict-free LDS.128, V as uniform-broadcast LDS.128.
__global__ __launch_bounds__(256)
void kv_kernel(const __half* __restrict__ KVc0, const __half* __restrict__ KVc1,
               float* __restrict__ KVb, float* __restrict__ Ksb)
{
    const int z = blockIdx.z;
    const __half* KVc = z ? KVc1 : KVc0;
    float* KV = KVb + z * KV_ELEMS;
    float* Ks = Ksb + z * KS_ELEMS;

    const int bh = blockIdx.x;
    const int b = bh >> 3, h = bh & 7;
    const int l0 = blockIdx.y * (L_ / KV_SPLITS);   // 320 rows
    const int tid = threadIdx.x;
    const int lr = tid >> 5, ld = tid & 31;

    __shared__ float Ktt[32][68];   // [d][row], pad 68 for bank spread + 16B align
    __shared__ float Vtt[32][68];   // [m][row]

    float acc[4] = {0.f, 0.f, 0.f, 0.f};
    float ks = 0.f;

    const int tt = tid & 127;
    const int lrow = tt >> 2, seg = tt & 3;   // row group 0..31, 8-half segment
    const bool isV = tid >= 128;
    const int colOff = (isV ? 256 : 0) + h * 32 + seg * 8;
    float* T = isV ? &Vtt[0][0] : &Ktt[0][0];

    for (int c = 0; c < 5; c++) {
        const size_t rbase = (size_t)b * L_ + l0 + c * 64;
        #pragma unroll
        for (int half = 0; half < 2; half++) {
            const int row = lrow + half * 32;
            uint4 v = *(const uint4*)(KVc + (rbase + row) * 512 + colOff);
            const __half2* hh = (const __half2*)&v;
            #pragma unroll
            for (int i = 0; i < 4; i++) {
                float2 f = __half22float2(hh[i]);
                T[(seg * 8 + 2 * i)     * 68 + row] = f.x;
                T[(seg * 8 + 2 * i + 1) * 68 + row] = f.y;
            }
        }
        __syncthreads();

        #pragma unroll
        for (int g = 0; g < 16; g++) {
            float4 kd = *(const float4*)&Ktt[ld][g * 4];
            #pragma unroll
            for (int j = 0; j < 4; j++) {
                float4 vm = *(const float4*)&Vtt[lr + j * 8][g * 4];
                acc[j] += kd.x * vm.x + kd.y * vm.y + kd.z * vm.z + kd.w * vm.w;
            }
            if (lr == 0) ks += kd.x + kd.y + kd.z + kd.w;
        }
        __syncthreads();
    }

    float* kvb = KV + (size_t)bh * (DIM_ * DIM_);
    #pragma unroll
    for (int j = 0; j < 4; j++)
        atomicAdd(&kvb[(lr + j * 8) * DIM_ + ld], acc[j]);
    if (lr == 0) atomicAdd(&Ks[bh * DIM_ + ld], ks);
}

// ================= attention apply v2: float4 broadcast LDS =================
__global__ __launch_bounds__(256)
void attn_apply(const __half* __restrict__ Q0, const __half* __restrict__ Q1,
                const float* __restrict__ KVb, const float* __restrict__ Ksb,
                __half* __restrict__ O0, __half* __restrict__ O1)
{
    __shared__ float sKV[H_ * DIM_ * DIM_];
    __shared__ float sKs[H_ * DIM_];
    const int z = blockIdx.z;
    const __half* Q = z ? Q1 : Q0;
    __half* Out = z ? O1 : O0;
    const float* KV = KVb + z * KV_ELEMS;
    const float* Ks = Ksb + z * KS_ELEMS;
    const int b = blockIdx.y;
    const int tid = threadIdx.x;

    for (int i = tid; i < H_ * DIM_ * DIM_; i += 256)
        sKV[i] = KV[(size_t)b * H_ * DIM_ * DIM_ + i];
    if (tid < H_ * DIM_) sKs[tid] = Ks[b * H_ * DIM_ + tid];
    __syncthreads();

    const int token = blockIdx.x * 256 + tid;
    if (token >= L_) return;
    const size_t row = (size_t)b * L_ + token;
    const __half* q = Q + row * D_;
    __half* o = Out + row * D_;

    for (int h = 0; h < H_; h++) {
        float qr[DIM_];
        uint4 uu[4];
        #pragma unroll
        for (int t = 0; t < 4; t++)
            uu[t] = *(const uint4*)(q + h * DIM_ + t * 8);
        const __half2* hh = (const __half2*)uu;
        #pragma unroll
        for (int t = 0; t < 16; t++) {
            float2 f = __half22float2(hh[t]);
            qr[2 * t] = f.x; qr[2 * t + 1] = f.y;
        }
        const float4* ks4 = (const float4*)&sKs[h * DIM_];
        float s = 0.f;
        #pragma unroll
        for (int d4 = 0; d4 < 8; d4++) {
            float4 kk = ks4[d4];
            s += kk.x * qr[d4 * 4] + kk.y * qr[d4 * 4 + 1]
               + kk.z * qr[d4 * 4 + 2] + kk.w * qr[d4 * 4 + 3];
        }
        float zz = 1.f / (s + EPS_ATTN);
        const float4* kv4 = (const float4*)&sKV[h * DIM_ * DIM_];
        #pragma unroll 4
        for (int m = 0; m < DIM_; m += 2) {
            float acc0 = 0.f, acc1 = 0.f;
            #pragma unroll
            for (int d4 = 0; d4 < 8; d4++) {
                float4 a = kv4[m * 8 + d4];
                float4 bb = kv4[(m + 1) * 8 + d4];
                acc0 += a.x * qr[d4 * 4] + a.y * qr[d4 * 4 + 1]
                      + a.z * qr[d4 * 4 + 2] + a.w * qr[d4 * 4 + 3];
                acc1 += bb.x * qr[d4 * 4] + bb.y * qr[d4 * 4 + 1]
                      + bb.z * qr[d4 * 4 + 2] + bb.w * qr[d4 * 4 + 3];
            }
            __half2 hv = __float22half2_rn(make_float2(acc0 * zz, acc1 * zz));
            *(uint32_t*)&o[h * DIM_ + m] = *(const uint32_t*)&hv;
        }
    }
}

// ================= host orchestration =================
namespace {

struct Ptrs {
    float *x0, *x1, *KV, *Ks;
    __half *xh0, *xh1, *Q, *KVc, *A, *Msg, *Hid, *WTh, *w1Th, *w2Th;
};

void run_block(int nd,
               float* x[2], __half* xh[2], const __half* src[2],
               const float* mq[2], const float* ms[2],
               const float* bq, const float* bk, const float* bv,
               const float* bm, const __half* w1P, const __half* w2P,
               const float* g1, const float* b1, const float* g2, const float* b2,
               const Ptrs& p)
{
    const int G = M_ / BM;   // 600
    __half* Q0 = p.Q;            __half* Q1 = p.Q + MD;
    __half* KVc0 = p.KVc;        __half* KVc1 = p.KVc + 2 * MD;
    __half* A0 = p.A;            __half* A1 = p.A + MD;
    __half* Ms0 = p.Msg;         __half* Ms1 = p.Msg + MD;
    __half* H0 = p.Hid;          __half* H1 = p.Hid + 2 * MD;
    const __half* WmP = p.WTh + 3 * 65536;

    gemm_qkv<<<dim3(G, 3 * nd), 256, SMEM_K8>>>(
        xh[0], xh[1], src[0], src[1], mq[0], mq[1], ms[0], ms[1],
        p.WTh, bq, bk, bv, Q0, Q1, KVc0, KVc1, p.KV, p.Ks);
    kv_kernel<<<dim3(B_ * H_, KV_SPLITS, nd), 256>>>(KVc0, KVc1, p.KV, p.Ks);
    attn_apply<<<dim3((L_ + 255) / 256, B_, nd), 256>>>(Q0, Q1, p.KV, p.Ks, A0, A1);

    gemm_std<EPI_BIAS_LN, 8, 1><<<dim3(G, nd), 256, SMEM_K8>>>(
        A0, A1, WmP, bm, g1, b1, Ms0, Ms1, nullptr, nullptr, 256);
    gemm_std<EPI_RELU, 8, 2><<<dim3(G, 2 * nd), 256, SMEM_K8>>>(
        Ms0, Ms1, w1P, nullptr, nullptr, nullptr, H0, H1, nullptr, nullptr, 512);
    gemm_std<EPI_LN_RES, 16, 1><<<dim3(G, nd), 256, SMEM_K16>>>(
        H0, H1, w2P, nullptr, g2, b2, x[0], x[1], xh[0], xh[1], 256);
}

} // namespace

extern "C" void kernel_launch(void* const* d_in, const int* in_sizes, int n_in,
                              void* d_out, int out_size)
{
    const float* desc0 = (const float*)d_in[0];
    const float* desc1 = (const float*)d_in[1];
    const float* mask0 = (const float*)d_in[2];
    const float* mask1 = (const float*)d_in[3];
    const float* Wq = (const float*)d_in[4];
    const float* bq = (const float*)d_in[5];
    const float* Wk = (const float*)d_in[6];
    const float* bk = (const float*)d_in[7];
    const float* Wv = (const float*)d_in[8];
    const float* bv = (const float*)d_in[9];
    const float* Wm = (const float*)d_in[10];
    const float* bm = (const float*)d_in[11];
    const float* w1 = (const float*)d_in[12];
    const float* w2 = (const float*)d_in[13];
    const float* g1 = (const float*)d_in[14];
    const float* b1 = (const float*)d_in[15];
    const float* g2 = (const float*)d_in[16];
    const float* b2 = (const float*)d_in[17];

    Ptrs p;
    cudaGetSymbolAddress((void**)&p.x0,  g_x0);
    cudaGetSymbolAddress((void**)&p.x1,  g_x1);
    cudaGetSymbolAddress((void**)&p.xh0, g_xh0);
    cudaGetSymbolAddress((void**)&p.xh1, g_xh1);
    cudaGetSymbolAddress((void**)&p.Q,   g_Q);
    cudaGetSymbolAddress((void**)&p.KVc, g_KVc);
    cudaGetSymbolAddress((void**)&p.A,   g_A);
    cudaGetSymbolAddress((void**)&p.Msg, g_Msg);
    cudaGetSymbolAddress((void**)&p.Hid, g_Hid);
    cudaGetSymbolAddress((void**)&p.KV,  g_KV);
    cudaGetSymbolAddress((void**)&p.Ks,  g_Ks);
    cudaGetSymbolAddress((void**)&p.WTh,  g_WTh);
    cudaGetSymbolAddress((void**)&p.w1Th, g_w1Th);
    cudaGetSymbolAddress((void**)&p.w2Th, g_w2Th);

    cudaFuncSetAttribute((const void*)gemm_qkv,                    cudaFuncAttributeMaxDynamicSharedMemorySize, SMEM_K8);
    cudaFuncSetAttribute((const void*)gemm_std<EPI_BIAS_LN, 8, 1>, cudaFuncAttributeMaxDynamicSharedMemorySize, SMEM_K8);
    cudaFuncSetAttribute((const void*)gemm_std<EPI_RELU, 8, 2>,    cudaFuncAttributeMaxDynamicSharedMemorySize, SMEM_K8);
    cudaFuncSetAttribute((const void*)gemm_std<EPI_LN_RES, 16, 1>, cudaFuncAttributeMaxDynamicSharedMemorySize, SMEM_K16);

    // ---- one-time prep ----
    pack_all<<<(4 * 65536 + 2 * 8 * 131072) / 256, 256>>>(Wq, Wk, Wv, Wm, w1, w2,
                                                          p.WTh, p.w1Th, p.w2Th);

    const size_t tensorBytes = (size_t)MD * sizeof(float);
    cudaMemcpyAsync(p.x0, desc0, tensorBytes, cudaMemcpyDeviceToDevice);
    cudaMemcpyAsync(p.x1, desc1, tensorBytes, cudaMemcpyDeviceToDevice);
    x_to_h<<<dim3((MD / 4 + 255) / 256, 2), 256>>>(p.x0, p.x1, p.xh0, p.xh1);

    const int w1sz = D_ * 2 * D_;
    const int w2sz = 2 * D_ * D_;

    for (int li = 0; li < 8; li++) {
        const __half* lw1 = p.w1Th + (size_t)li * w1sz;
        const __half* lw2 = p.w2Th + (size_t)li * w2sz;
        const float* lg1 = g1 + li * D_;
        const float* lb1 = b1 + li * D_;
        const float* lg2 = g2 + li * D_;
        const float* lb2 = b2 + li * D_;

        if ((li & 1) == 0) {
            float* x[2] = {p.x0, p.x1};
            __half* xh[2] = {p.xh0, p.xh1};
            const __half* src[2] = {p.xh0, p.xh1};
            const float* mq[2] = {mask0, mask1};
            const float* ms[2] = {mask0, mask1};
            run_block(2, x, xh, src, mq, ms, bq, bk, bv, bm,
                      lw1, lw2, lg1, lb1, lg2, lb2, p);
        } else {
            {
                float* x[2] = {p.x0, p.x0};
                __half* xh[2] = {p.xh0, p.xh0};
                const __half* src[2] = {p.xh1, p.xh1};
                const float* mq[2] = {mask0, mask0};
                const float* ms[2] = {mask1, mask1};
                run_block(1, x, xh, src, mq, ms, bq, bk, bv, bm,
                          lw1, lw2, lg1, lb1, lg2, lb2, p);
            }
            {
                float* x[2] = {p.x1, p.x1};
                __half* xh[2] = {p.xh1, p.xh1};
                const __half* src[2] = {p.xh0, p.xh0};
                const float* mq[2] = {mask1, mask1};
                const float* ms[2] = {mask0, mask0};
                run_block(1, x, xh, src, mq, ms, bq, bk, bv, bm,
                          lw1, lw2, lg1, lb1, lg2, lb2, p);
            }
        }
    }

    cudaMemcpyAsync((float*)d_out,                p.x0, tensorBytes, cudaMemcpyDeviceToDevice);
    cudaMemcpyAsync((float*)d_out + (size_t)MD,   p.x1, tensorBytes, cudaMemcpyDeviceToDevice);
}

// round 16
// speedup vs baseline: 1.3881x; 1.0228x over previous
#include <cuda_runtime.h>
#include <cuda_fp16.h>
#include <math.h>
#include <stdint.h>

// ================= problem constants =================
namespace {
constexpr int B_ = 8, L_ = 4800, D_ = 256, H_ = 8, DIM_ = 32;
constexpr int M_ = B_ * L_;            // 38400 rows
constexpr float EPS_ATTN = 1e-6f, EPS_LN = 1e-5f;
constexpr int KV_ELEMS = B_ * H_ * DIM_ * DIM_;   // 65536
constexpr int KS_ELEMS = B_ * H_ * DIM_;          // 2048
constexpr int MD = M_ * D_;

constexpr int BM = 64;                 // CTA rows; 8 warps; warp tile 64x32
constexpr int SMEM_K8  = (8  * 1024 + 768) * 4;   // 35840 B
constexpr int SMEM_K16 = (16 * 1024 + 768) * 4;   // 68608 B
constexpr int KV_SPLITS = 15;          // 320 rows per split, 5 chunks of 64
}

// ================= scratch (static device globals) =================
__device__ float  g_x0[MD];
__device__ float  g_x1[MD];
__device__ __half g_xh0[MD];                  // fp16 shadow of x0
__device__ __half g_xh1[MD];
__device__ __half g_Q  [2 * MD];              // per-desc
__device__ __half g_KVc[2 * 2 * MD];          // per-desc K|V combined
__device__ __half g_A  [2 * MD];
__device__ __half g_Msg[2 * MD];
__device__ __half g_Hid[2 * 2 * MD];
__device__ float  g_KV[2 * KV_ELEMS];
__device__ float  g_Ks[2 * KS_ELEMS];
__device__ __half g_WTh [4 * D_ * D_];        // frag-major fp16: Wq,Wk,Wv,Wm
__device__ __half g_w1Th[8 * 2 * D_ * D_];
__device__ __half g_w2Th[8 * D_ * 2 * D_];

// ================= mma helper =================
__device__ __forceinline__ void mma_f16(float d[4], const uint32_t a[4],
                                        uint32_t b0, uint32_t b1) {
    asm volatile(
        "mma.sync.aligned.m16n8k16.row.col.f32.f16.f16.f32 "
        "{%0,%1,%2,%3}, {%4,%5,%6,%7}, {%8,%9}, {%0,%1,%2,%3};\n"
        : "+f"(d[0]), "+f"(d[1]), "+f"(d[2]), "+f"(d[3])
        : "r"(a[0]), "r"(a[1]), "r"(a[2]), "r"(a[3]), "r"(b0), "r"(b1));
}

// ================= weight pack: [K,N] f32 -> frag-major fp16 =================
__device__ __forceinline__ void pack_one(const float* __restrict__ in,
                                         __half* __restrict__ out,
                                         int t, int K, int N)
{
    int k = t / N, n = t % N;
    int nblk = n >> 8, nloc = n & 255;
    int wn = nloc >> 5, j = (nloc >> 3) & 3, gid = nloc & 7;
    int p = j >> 1, jh = j & 1;
    int kch = k >> 5, kin = k & 31, kstep = kin >> 4, c16 = kin & 15;
    int qid = (c16 >> 1) & 3, kh = (c16 >> 3) & 1, h = c16 & 1;
    int lane = gid * 4 + qid;
    int NKCH = K >> 5;
    size_t idx = ((((((size_t)nblk * NKCH + kch) * 2 + kstep) * 8 + wn) * 2 + p) * 32
                  + lane) * 8 + jh * 4 + kh * 2 + h;
    out[idx] = __float2half_rn(in[t]);
}

__global__ void pack_all(const float* __restrict__ Wq, const float* __restrict__ Wk,
                         const float* __restrict__ Wv, const float* __restrict__ Wm,
                         const float* __restrict__ w1, const float* __restrict__ w2,
                         __half* __restrict__ WTh, __half* __restrict__ w1Th,
                         __half* __restrict__ w2Th)
{
    long idx = (long)blockIdx.x * 256 + threadIdx.x;
    const long S0 = 4L * 65536, S1 = 8L * 131072;
    if (idx < S0) {
        int which = (int)(idx >> 16), t = (int)(idx & 65535);
        const float* src = which == 0 ? Wq : which == 1 ? Wk : which == 2 ? Wv : Wm;
        pack_one(src, WTh + (long)which * 65536, t, 256, 256);
    } else if (idx < S0 + S1) {
        long i2 = idx - S0;
        int layer = (int)(i2 >> 17), t = (int)(i2 & 131071);
        pack_one(w1 + (long)layer * 131072, w1Th + (long)layer * 131072, t, 256, 512);
    } else {
        long i2 = idx - S0 - S1;
        int layer = (int)(i2 >> 17), t = (int)(i2 & 131071);
        pack_one(w2 + (long)layer * 131072, w2Th + (long)layer * 131072, t, 512, 256);
    }
}

// ================= x -> fp16 shadow (initial) =================
__global__ void x_to_h(const float* __restrict__ x0, const float* __restrict__ x1,
                       __half* __restrict__ h0, __half* __restrict__ h1)
{
    size_t i = ((size_t)blockIdx.x * 256 + threadIdx.x) * 4;
    if (i >= (size_t)MD) return;
    const float* x = blockIdx.y == 0 ? x0 : x1;
    __half* h = blockIdx.y == 0 ? h0 : h1;
    float4 v = *(const float4*)(x + i);
    __half2 a = __float22half2_rn(make_float2(v.x, v.y));
    __half2 b = __float22half2_rn(make_float2(v.z, v.w));
    uint32_t u[2] = {*(const uint32_t*)&a, *(const uint32_t*)&b};
    *(uint2*)(h + i) = *(const uint2*)u;
}

// ================= shared GEMM core =================
template<int KCH>
__device__ __forceinline__ void gemm_main(const __half* __restrict__ A, int rowBase,
                                          const __half* __restrict__ Bblk,
                                          uint32_t* __restrict__ As,
                                          int tid, int wn, int lane,
                                          float acc[4][4][4])
{
    constexpr int K = KCH * 32;
    {
        const int arow = tid >> 2, aq = tid & 3;
        const int a_base = ((aq >> 1) * 4 + (arow >> 4)) * 128 + (arow & 7) * 16
                         + (aq & 1) * 2 + ((arow >> 3) & 1);
        const __half* Aptr = A + (size_t)(rowBase + arow) * K + aq * 8;
        #pragma unroll
        for (int c = 0; c < KCH; c++) {
            uint4 v = *(const uint4*)(Aptr + (size_t)c * 32);
            uint32_t* d = As + c * 1024 + a_base;
            d[0] = v.x; d[4] = v.y; d[8] = v.z; d[12] = v.w;
        }
    }
    __syncthreads();

    #pragma unroll
    for (int mi = 0; mi < 4; mi++)
        #pragma unroll
        for (int j = 0; j < 4; j++)
            #pragma unroll
            for (int q = 0; q < 4; q++) acc[mi][j][q] = 0.f;

    const uint32_t* Asl = As + lane * 4;
    const __half* Bch = Bblk + (size_t)wn * 512 + lane * 8;

    uint4 af[2][4], bf[2][2];
    #pragma unroll
    for (int mi = 0; mi < 4; mi++)
        af[0][mi] = *(const uint4*)(Asl + mi * 128);
    bf[0][0] = *(const uint4*)(Bch);
    bf[0][1] = *(const uint4*)(Bch + 256);

    #pragma unroll
    for (int kk = 0; kk < 2 * KCH; kk++) {
        const int cur = kk & 1, nxt = cur ^ 1;
        if (kk + 1 < 2 * KCH) {
            const uint32_t* asn = Asl + (kk + 1) * 512;
            #pragma unroll
            for (int mi = 0; mi < 4; mi++)
                af[nxt][mi] = *(const uint4*)(asn + mi * 128);
            const __half* s = Bch + (size_t)(kk + 1) * 4096;
            bf[nxt][0] = *(const uint4*)(s);
            bf[nxt][1] = *(const uint4*)(s + 256);
        }
        #pragma unroll
        for (int mi = 0; mi < 4; mi++) {
            const uint32_t a4[4] = {af[cur][mi].x, af[cur][mi].y,
                                    af[cur][mi].z, af[cur][mi].w};
            mma_f16(acc[mi][0], a4, bf[cur][0].x, bf[cur][0].y);
            mma_f16(acc[mi][1], a4, bf[cur][0].z, bf[cur][0].w);
            mma_f16(acc[mi][2], a4, bf[cur][1].x, bf[cur][1].y);
            mma_f16(acc[mi][3], a4, bf[cur][1].z, bf[cur][1].w);
        }
    }
    __syncthreads();
}

// ================= fused Q|K|V GEMM =================
__global__ __launch_bounds__(256, 2)
void gemm_qkv(const __half* __restrict__ xq0, const __half* __restrict__ xq1,
              const __half* __restrict__ xs0, const __half* __restrict__ xs1,
              const float* __restrict__ mq0, const float* __restrict__ mq1,
              const float* __restrict__ ms0, const float* __restrict__ ms1,
              const __half* __restrict__ Wqkv,
              const float* __restrict__ bq, const float* __restrict__ bk,
              const float* __restrict__ bv,
              __half* __restrict__ Q0, __half* __restrict__ Q1,
              __half* __restrict__ KVc0, __half* __restrict__ KVc1,
              float* __restrict__ kvz, float* __restrict__ ksz)
{
    extern __shared__ float sm[];
    uint32_t* As = (uint32_t*)sm;
    float* sbias = sm + 8 * 1024;

    const int tid = threadIdx.x;
    const int wn = tid >> 5, lane = tid & 31;
    const int gid = lane >> 2, qid = lane & 3;
    const int mtile = blockIdx.x;
    const int d = blockIdx.y / 3, part = blockIdx.y % 3;
    const int rowBase = mtile * BM;

    const __half* Ain = (part == 0) ? (d ? xq1 : xq0) : (d ? xs1 : xs0);
    const float* msk  = (part == 0) ? (d ? mq1 : mq0) : (d ? ms1 : ms0);
    const float* bs   = (part == 0) ? bq : (part == 1 ? bk : bv);
    __half* Cp;
    int Nst, colO;
    if (part == 0) { Cp = d ? Q1 : Q0;     Nst = 256; colO = 0; }
    else           { Cp = d ? KVc1 : KVc0; Nst = 512; colO = (part - 1) * 256; }
    const bool do_elu = (part < 2);

    if (part == 0) {
        if (mtile < 256) kvz[d * KV_ELEMS + mtile * 256 + tid] = 0.f;
        else if (mtile < 264) ksz[d * KS_ELEMS + (mtile - 256) * 256 + tid] = 0.f;
    }
    sbias[tid] = bs[tid];

    float acc[4][4][4];
    gemm_main<8>(Ain, rowBase, Wqkv + part * 65536, As, tid, wn, lane, acc);

    float mk[4][2];
    #pragma unroll
    for (int mi = 0; mi < 4; mi++)
        #pragma unroll
        for (int r = 0; r < 2; r++)
            mk[mi][r] = msk[rowBase + mi * 16 + r * 8 + gid];

    #pragma unroll
    for (int mi = 0; mi < 4; mi++) {
        #pragma unroll
        for (int j = 0; j < 4; j++) {
            const int c = wn * 32 + j * 8 + qid * 2;
            float b0 = sbias[c], b1 = sbias[c + 1];
            float v[4] = {acc[mi][j][0] + b0, acc[mi][j][1] + b1,
                          acc[mi][j][2] + b0, acc[mi][j][3] + b1};
            #pragma unroll
            for (int q = 0; q < 4; q++) {
                float t = v[q];
                if (do_elu) t = (t > 0.f) ? (t + 1.f) : expf(t);
                v[q] = t * mk[mi][q >> 1];
            }
            const int cc = colO + c;
            const int r0 = rowBase + mi * 16 + gid, r1 = r0 + 8;
            __half2 h0 = __float22half2_rn(make_float2(v[0], v[1]));
            __half2 h1 = __float22half2_rn(make_float2(v[2], v[3]));
            *(uint32_t*)&Cp[(size_t)r0 * Nst + cc] = *(const uint32_t*)&h0;
            *(uint32_t*)&Cp[(size_t)r1 * Nst + cc] = *(const uint32_t*)&h1;
        }
    }
}

// ================= std GEMM (BIAS_LN / RELU / LN_RES), desc-batched ============
enum { EPI_RELU = 3, EPI_BIAS_LN = 5, EPI_LN_RES = 6 };

template<int EPI, int KCH, int NB>
__global__ __launch_bounds__(256, 2)
void gemm_std(const __half* __restrict__ A0, const __half* __restrict__ A1,
              const __half* __restrict__ Bp,
              const float* __restrict__ bias,
              const float* __restrict__ lng, const float* __restrict__ lnb,
              void* __restrict__ C0, void* __restrict__ C1,
              __half* __restrict__ xh0, __half* __restrict__ xh1, int N)
{
    extern __shared__ float sm[];
    uint32_t* As = (uint32_t*)sm;
    float* sbias = sm + KCH * 1024;
    float* sg    = sbias + 256;
    float* sb    = sg + 256;
    float* red1 = sm;
    float* red2 = sm + 512;
    float* smu  = sm + 1024;
    float* srs  = sm + 1088;

    const int tid = threadIdx.x;
    const int wn = tid >> 5, lane = tid & 31;
    const int gid = lane >> 2, qid = lane & 3;
    const int mtile = blockIdx.x;
    const int d = blockIdx.y / NB, nblk = blockIdx.y % NB;
    const int rowBase = mtile * BM;
    const int colBase = nblk * 256;

    const __half* Ain = d ? A1 : A0;
    void* Cout = d ? C1 : C0;
    __half* xh = d ? xh1 : xh0;

    if (EPI == EPI_BIAS_LN) sbias[tid] = bias[colBase + tid];
    if (EPI == EPI_BIAS_LN || EPI == EPI_LN_RES) { sg[tid] = lng[tid]; sb[tid] = lnb[tid]; }

    float acc[4][4][4];
    gemm_main<KCH>(Ain, rowBase, Bp + (size_t)nblk * KCH * 8192, As, tid, wn, lane, acc);

    if (EPI == EPI_BIAS_LN) {
        #pragma unroll
        for (int mi = 0; mi < 4; mi++)
            #pragma unroll
            for (int j = 0; j < 4; j++) {
                const int c = wn * 32 + j * 8 + qid * 2;
                acc[mi][j][0] += sbias[c];   acc[mi][j][1] += sbias[c + 1];
                acc[mi][j][2] += sbias[c];   acc[mi][j][3] += sbias[c + 1];
            }
    }
    if (EPI == EPI_RELU) {
        #pragma unroll
        for (int mi = 0; mi < 4; mi++)
            #pragma unroll
            for (int j = 0; j < 4; j++)
                #pragma unroll
                for (int q = 0; q < 4; q++)
                    acc[mi][j][q] = acc[mi][j][q] > 0.f ? acc[mi][j][q] : 0.f;
    }

    if (EPI == EPI_BIAS_LN || EPI == EPI_LN_RES) {
        float s1[4][2], s2[4][2];
        #pragma unroll
        for (int mi = 0; mi < 4; mi++)
            #pragma unroll
            for (int r = 0; r < 2; r++) { s1[mi][r] = 0.f; s2[mi][r] = 0.f; }
        #pragma unroll
        for (int mi = 0; mi < 4; mi++)
            #pragma unroll
            for (int j = 0; j < 4; j++)
                #pragma unroll
                for (int q = 0; q < 4; q++) {
                    float v = acc[mi][j][q];
                    s1[mi][q >> 1] += v;
                    s2[mi][q >> 1] = fmaf(v, v, s2[mi][q >> 1]);
                }
        #pragma unroll
        for (int o = 1; o <= 2; o <<= 1)
            #pragma unroll
            for (int mi = 0; mi < 4; mi++)
                #pragma unroll
                for (int r = 0; r < 2; r++) {
                    s1[mi][r] += __shfl_xor_sync(0xffffffffu, s1[mi][r], o);
                    s2[mi][r] += __shfl_xor_sync(0xffffffffu, s2[mi][r], o);
                }
        if (qid == 0) {
            #pragma unroll
            for (int mi = 0; mi < 4; mi++)
                #pragma unroll
                for (int r = 0; r < 2; r++) {
                    int rl = mi * 16 + r * 8 + gid;
                    red1[rl * 8 + wn] = s1[mi][r];
                    red2[rl * 8 + wn] = s2[mi][r];
                }
        }
        __syncthreads();
        if (tid < 64) {
            float a = 0.f, b2 = 0.f;
            #pragma unroll
            for (int w = 0; w < 8; w++) { a += red1[tid * 8 + w]; b2 += red2[tid * 8 + w]; }
            float mu = a * (1.f / 256.f);
            float var = b2 * (1.f / 256.f) - mu * mu;
            smu[tid] = mu;
            srs[tid] = rsqrtf(var + EPS_LN);
        }
        __syncthreads();
        #pragma unroll
        for (int mi = 0; mi < 4; mi++)
            #pragma unroll
            for (int j = 0; j < 4; j++)
                #pragma unroll
                for (int q = 0; q < 4; q++) {
                    int rl = mi * 16 + (q >> 1) * 8 + gid;
                    int c  = wn * 32 + j * 8 + qid * 2 + (q & 1);
                    acc[mi][j][q] = (acc[mi][j][q] - smu[rl]) * srs[rl] * sg[c] + sb[c];
                }
    }

    #pragma unroll
    for (int mi = 0; mi < 4; mi++) {
        #pragma unroll
        for (int j = 0; j < 4; j++) {
            const int c  = colBase + wn * 32 + j * 8 + qid * 2;
            const int r0 = rowBase + mi * 16 + gid;
            const int r1 = r0 + 8;
            if (EPI != EPI_LN_RES) {
                __half* Ch = (__half*)Cout;
                __half2 h0 = __float22half2_rn(make_float2(acc[mi][j][0], acc[mi][j][1]));
                __half2 h1 = __float22half2_rn(make_float2(acc[mi][j][2], acc[mi][j][3]));
                *(uint32_t*)&Ch[(size_t)r0 * N + c] = *(const uint32_t*)&h0;
                *(uint32_t*)&Ch[(size_t)r1 * N + c] = *(const uint32_t*)&h1;
            } else {
                float* Cf = (float*)Cout;
                float2 v0 = make_float2(acc[mi][j][0], acc[mi][j][1]);
                float2 v1 = make_float2(acc[mi][j][2], acc[mi][j][3]);
                float2 x0 = *(const float2*)&Cf[(size_t)r0 * N + c];
                float2 x1 = *(const float2*)&Cf[(size_t)r1 * N + c];
                v0.x += x0.x; v0.y += x0.y;
                v1.x += x1.x; v1.y += x1.y;
                *(float2*)&Cf[(size_t)r0 * N + c] = v0;
                *(float2*)&Cf[(size_t)r1 * N + c] = v1;
                __half2 h0 = __float22half2_rn(v0);
                __half2 h1 = __float22half2_rn(v1);
                *(uint32_t*)&xh[(size_t)r0 * N + c] = *(const uint32_t*)&h0;
                *(uint32_t*)&xh[(size_t)r1 * N + c] = *(const uint32_t*)&h1;
            }
        }
    }
}

// ================= KV reduction: transposed smem, swizzled stores ======
__global__ __launch_bounds__(256)
void kv_kernel(const __half* __restrict__ KVc0, const __half* __restrict__ KVc1,
               float* __restrict__ KVb, float* __restrict__ Ksb)
{
    const int z = blockIdx.z;
    const __half* KVc = z ? KVc1 : KVc0;
    float* KV = KVb + z * KV_ELEMS;
    float* Ks = Ksb + z * KS_ELEMS;

    const int bh = blockIdx.x;
    const int b = bh >> 3, h = bh & 7;
    const int l0 = blockIdx.y * (L_ / KV_SPLITS);   // 320 rows
    const int tid = threadIdx.x;
    const int lr = tid >> 5, ld = tid & 31;

    __shared__ float Ktt[32 * 68];   // [d][pos], pos = row ^ ((d>>3)*8)
    __shared__ float Vtt[32 * 68];

    float acc[4] = {0.f, 0.f, 0.f, 0.f};
    float ks = 0.f;

    const int tt = tid & 127;
    const int lrow = tt >> 2, seg = tt & 3;
    const bool isV = tid >= 128;
    const int colOff = (isV ? 256 : 0) + h * 32 + seg * 8;
    float* T = isV ? Vtt : Ktt;
    const int sw_seg = seg * 8;                 // store swizzle
    const int sw_ld = (ld >> 3) * 8;            // K-read swizzle

    for (int c = 0; c < 5; c++) {
        const size_t rbase = (size_t)b * L_ + l0 + c * 64;
        #pragma unroll
        for (int half = 0; half < 2; half++) {
            const int row = lrow + half * 32;
            const int scol = row ^ sw_seg;
            uint4 v = *(const uint4*)(KVc + (rbase + row) * 512 + colOff);
            const __half2* hh = (const __half2*)&v;
            #pragma unroll
            for (int i = 0; i < 4; i++) {
                float2 f = __half22float2(hh[i]);
                T[(seg * 8 + 2 * i)     * 68 + scol] = f.x;
                T[(seg * 8 + 2 * i + 1) * 68 + scol] = f.y;
            }
        }
        __syncthreads();

        #pragma unroll
        for (int g = 0; g < 16; g++) {
            float4 kd = *(const float4*)&Ktt[ld * 68 + ((g * 4) ^ sw_ld)];
            #pragma unroll
            for (int j = 0; j < 4; j++) {
                float4 vm = *(const float4*)&Vtt[(lr + j * 8) * 68 + ((g * 4) ^ (j * 8))];
                acc[j] += kd.x * vm.x + kd.y * vm.y + kd.z * vm.z + kd.w * vm.w;
            }
            if (lr == 0) ks += kd.x + kd.y + kd.z + kd.w;
        }
        __syncthreads();
    }

    float* kvb = KV + (size_t)bh * (DIM_ * DIM_);
    #pragma unroll
    for (int j = 0; j < 4; j++)
        atomicAdd(&kvb[(lr + j * 8) * DIM_ + ld], acc[j]);
    if (lr == 0) atomicAdd(&Ks[bh * DIM_ + ld], ks);
}

// ================= attention apply (scalar, known-good from R14) =========
__global__ __launch_bounds__(256)
void attn_apply(const __half* __restrict__ Q0, const __half* __restrict__ Q1,
                const float* __restrict__ KVb, const float* __restrict__ Ksb,
                __half* __restrict__ O0, __half* __restrict__ O1)
{
    __shared__ float sKV[H_ * DIM_ * DIM_];
    __shared__ float sKs[H_ * DIM_];
    const int z = blockIdx.z;
    const __half* Q = z ? Q1 : Q0;
    __half* Out = z ? O1 : O0;
    const float* KV = KVb + z * KV_ELEMS;
    const float* Ks = Ksb + z * KS_ELEMS;
    const int b = blockIdx.y;
    const int tid = threadIdx.x;

    for (int i = tid; i < H_ * DIM_ * DIM_; i += 256)
        sKV[i] = KV[(size_t)b * H_ * DIM_ * DIM_ + i];
    if (tid < H_ * DIM_) sKs[tid] = Ks[b * H_ * DIM_ + tid];
    __syncthreads();

    const int token = blockIdx.x * 256 + tid;
    if (token >= L_) return;
    const size_t row = (size_t)b * L_ + token;
    const __half* q = Q + row * D_;
    __half* o = Out + row * D_;

    for (int h = 0; h < H_; h++) {
        float qr[DIM_];
        uint4 uu[4];
        #pragma unroll
        for (int t = 0; t < 4; t++)
            uu[t] = *(const uint4*)(q + h * DIM_ + t * 8);
        const __half2* hh = (const __half2*)uu;
        #pragma unroll
        for (int t = 0; t < 16; t++) {
            float2 f = __half22float2(hh[t]);
            qr[2 * t] = f.x; qr[2 * t + 1] = f.y;
        }
        const float4* ks4 = (const float4*)&sKs[h * DIM_];
        float s = 0.f;
        #pragma unroll
        for (int d4 = 0; d4 < 8; d4++) {
            float4 kk = ks4[d4];
            s += kk.x * qr[d4 * 4] + kk.y * qr[d4 * 4 + 1]
               + kk.z * qr[d4 * 4 + 2] + kk.w * qr[d4 * 4 + 3];
        }
        float zz = 1.f / (s + EPS_ATTN);
        const float4* kv4 = (const float4*)&sKV[h * DIM_ * DIM_];
        #pragma unroll 4
        for (int m = 0; m < DIM_; m += 2) {
            float acc0 = 0.f, acc1 = 0.f;
            #pragma unroll
            for (int d4 = 0; d4 < 8; d4++) {
                float4 a = kv4[m * 8 + d4];
                float4 bb = kv4[(m + 1) * 8 + d4];
                acc0 += a.x * qr[d4 * 4] + a.y * qr[d4 * 4 + 1]
                      + a.z * qr[d4 * 4 + 2] + a.w * qr[d4 * 4 + 3];
                acc1 += bb.x * qr[d4 * 4] + bb.y * qr[d4 * 4 + 1]
                      + bb.z * qr[d4 * 4 + 2] + bb.w * qr[d4 * 4 + 3];
            }
            __half2 hv = __float22half2_rn(make_float2(acc0 * zz, acc1 * zz));
            *(uint32_t*)&o[h * DIM_ + m] = *(const uint32_t*)&hv;
        }
    }
}

// ================= host orchestration =================
namespace {

struct Ptrs {
    float *x0, *x1, *KV, *Ks;
    __half *xh0, *xh1, *Q, *KVc, *A, *Msg, *Hid, *WTh, *w1Th, *w2Th;
};

void run_block(int nd,
               float* x[2], __half* xh[2], const __half* src[2],
               const float* mq[2], const float* ms[2],
               const float* bq, const float* bk, const float* bv,
               const float* bm, const __half* w1P, const __half* w2P,
               const float* g1, const float* b1, const float* g2, const float* b2,
               const Ptrs& p)
{
    const int G = M_ / BM;   // 600
    __half* Q0 = p.Q;            __half* Q1 = p.Q + MD;
    __half* KVc0 = p.KVc;        __half* KVc1 = p.KVc + 2 * MD;
    __half* A0 = p.A;            __half* A1 = p.A + MD;
    __half* Ms0 = p.Msg;         __half* Ms1 = p.Msg + MD;
    __half* H0 = p.Hid;          __half* H1 = p.Hid + 2 * MD;
    const __half* WmP = p.WTh + 3 * 65536;

    gemm_qkv<<<dim3(G, 3 * nd), 256, SMEM_K8>>>(
        xh[0], xh[1], src[0], src[1], mq[0], mq[1], ms[0], ms[1],
        p.WTh, bq, bk, bv, Q0, Q1, KVc0, KVc1, p.KV, p.Ks);
    kv_kernel<<<dim3(B_ * H_, KV_SPLITS, nd), 256>>>(KVc0, KVc1, p.KV, p.Ks);
    attn_apply<<<dim3((L_ + 255) / 256, B_, nd), 256>>>(Q0, Q1, p.KV, p.Ks, A0, A1);

    gemm_std<EPI_BIAS_LN, 8, 1><<<dim3(G, nd), 256, SMEM_K8>>>(
        A0, A1, WmP, bm, g1, b1, Ms0, Ms1, nullptr, nullptr, 256);
    gemm_std<EPI_RELU, 8, 2><<<dim3(G, 2 * nd), 256, SMEM_K8>>>(
        Ms0, Ms1, w1P, nullptr, nullptr, nullptr, H0, H1, nullptr, nullptr, 512);
    gemm_std<EPI_LN_RES, 16, 1><<<dim3(G, nd), 256, SMEM_K16>>>(
        H0, H1, w2P, nullptr, g2, b2, x[0], x[1], xh[0], xh[1], 256);
}

} // namespace

extern "C" void kernel_launch(void* const* d_in, const int* in_sizes, int n_in,
                              void* d_out, int out_size)
{
    const float* desc0 = (const float*)d_in[0];
    const float* desc1 = (const float*)d_in[1];
    const float* mask0 = (const float*)d_in[2];
    const float* mask1 = (const float*)d_in[3];
    const float* Wq = (const float*)d_in[4];
    const float* bq = (const float*)d_in[5];
    const float* Wk = (const float*)d_in[6];
    const float* bk = (const float*)d_in[7];
    const float* Wv = (const float*)d_in[8];
    const float* bv = (const float*)d_in[9];
    const float* Wm = (const float*)d_in[10];
    const float* bm = (const float*)d_in[11];
    const float* w1 = (const float*)d_in[12];
    const float* w2 = (const float*)d_in[13];
    const float* g1 = (const float*)d_in[14];
    const float* b1 = (const float*)d_in[15];
    const float* g2 = (const float*)d_in[16];
    const float* b2 = (const float*)d_in[17];

    Ptrs p;
    cudaGetSymbolAddress((void**)&p.x0,  g_x0);
    cudaGetSymbolAddress((void**)&p.x1,  g_x1);
    cudaGetSymbolAddress((void**)&p.xh0, g_xh0);
    cudaGetSymbolAddress((void**)&p.xh1, g_xh1);
    cudaGetSymbolAddress((void**)&p.Q,   g_Q);
    cudaGetSymbolAddress((void**)&p.KVc, g_KVc);
    cudaGetSymbolAddress((void**)&p.A,   g_A);
    cudaGetSymbolAddress((void**)&p.Msg, g_Msg);
    cudaGetSymbolAddress((void**)&p.Hid, g_Hid);
    cudaGetSymbolAddress((void**)&p.KV,  g_KV);
    cudaGetSymbolAddress((void**)&p.Ks,  g_Ks);
    cudaGetSymbolAddress((void**)&p.WTh,  g_WTh);
    cudaGetSymbolAddress((void**)&p.w1Th, g_w1Th);
    cudaGetSymbolAddress((void**)&p.w2Th, g_w2Th);

    cudaFuncSetAttribute((const void*)gemm_qkv,                    cudaFuncAttributeMaxDynamicSharedMemorySize, SMEM_K8);
    cudaFuncSetAttribute((const void*)gemm_std<EPI_BIAS_LN, 8, 1>, cudaFuncAttributeMaxDynamicSharedMemorySize, SMEM_K8);
    cudaFuncSetAttribute((const void*)gemm_std<EPI_RELU, 8, 2>,    cudaFuncAttributeMaxDynamicSharedMemorySize, SMEM_K8);
    cudaFuncSetAttribute((const void*)gemm_std<EPI_LN_RES, 16, 1>, cudaFuncAttributeMaxDynamicSharedMemorySize, SMEM_K16);

    // ---- one-time prep ----
    pack_all<<<(4 * 65536 + 2 * 8 * 131072) / 256, 256>>>(Wq, Wk, Wv, Wm, w1, w2,
                                                          p.WTh, p.w1Th, p.w2Th);

    const size_t tensorBytes = (size_t)MD * sizeof(float);
    cudaMemcpyAsync(p.x0, desc0, tensorBytes, cudaMemcpyDeviceToDevice);
    cudaMemcpyAsync(p.x1, desc1, tensorBytes, cudaMemcpyDeviceToDevice);
    x_to_h<<<dim3((MD / 4 + 255) / 256, 2), 256>>>(p.x0, p.x1, p.xh0, p.xh1);

    const int w1sz = D_ * 2 * D_;
    const int w2sz = 2 * D_ * D_;

    for (int li = 0; li < 8; li++) {
        const __half* lw1 = p.w1Th + (size_t)li * w1sz;
        const __half* lw2 = p.w2Th + (size_t)li * w2sz;
        const float* lg1 = g1 + li * D_;
        const float* lb1 = b1 + li * D_;
        const float* lg2 = g2 + li * D_;
        const float* lb2 = b2 + li * D_;

        if ((li & 1) == 0) {
            float* x[2] = {p.x0, p.x1};
            __half* xh[2] = {p.xh0, p.xh1};
            const __half* src[2] = {p.xh0, p.xh1};
            const float* mq[2] = {mask0, mask1};
            const float* ms[2] = {mask0, mask1};
            run_block(2, x, xh, src, mq, ms, bq, bk, bv, bm,
                      lw1, lw2, lg1, lb1, lg2, lb2, p);
        } else {
            {
                float* x[2] = {p.x0, p.x0};
                __half* xh[2] = {p.xh0, p.xh0};
                const __half* src[2] = {p.xh1, p.xh1};
                const float* mq[2] = {mask0, mask0};
                const float* ms[2] = {mask1, mask1};
                run_block(1, x, xh, src, mq, ms, bq, bk, bv, bm,
                          lw1, lw2, lg1, lb1, lg2, lb2, p);
            }
            {
                float* x[2] = {p.x1, p.x1};
                __half* xh[2] = {p.xh1, p.xh1};
                const __half* src[2] = {p.xh0, p.xh0};
                const float* mq[2] = {mask1, mask1};
                const float* ms[2] = {mask0, mask0};
                run_block(1, x, xh, src, mq, ms, bq, bk, bv, bm,
                          lw1, lw2, lg1, lb1, lg2, lb2, p);
            }
        }
    }

    cudaMemcpyAsync((float*)d_out,                p.x0, tensorBytes, cudaMemcpyDeviceToDevice);
    cudaMemcpyAsync((float*)d_out + (size_t)MD,   p.x1, tensorBytes, cudaMemcpyDeviceToDevice);
}